// round 11
// baseline (speedup 1.0000x reference)
#include <cuda_runtime.h>
#include <cuda_bf16.h>
#include <math.h>
#include <stdint.h>

// Problem constants
#define NBN   65536      // B*N nodes
#define BGR   128        // graphs
#define NN    512        // nodes per graph
#define FD    512        // input features
#define HD    256        // hidden
#define KP1   256        // K1
#define KP2   128        // K2
#define EDGES 1048576    // B*EPG
#define EPG   8192       // edges per graph

typedef unsigned long long ull;

__device__ __forceinline__ void mma_bf16(float* c, const uint32_t* a,
                                         uint32_t b0, uint32_t b1)
{
    asm volatile(
        "mma.sync.aligned.m16n8k16.row.col.f32.bf16.bf16.f32 "
        "{%0,%1,%2,%3}, {%4,%5,%6,%7}, {%8,%9}, {%0,%1,%2,%3};"
        : "+f"(c[0]), "+f"(c[1]), "+f"(c[2]), "+f"(c[3])
        : "r"(a[0]), "r"(a[1]), "r"(a[2]), "r"(a[3]), "r"(b0), "r"(b1));
}

__device__ __forceinline__ void cp16(uint32_t dst, const void* src)
{
    asm volatile("cp.async.cg.shared.global [%0], [%1], 16;"
                 :: "r"(dst), "l"(src));
}

__device__ __forceinline__ void ldsm4(uint32_t* r, uint32_t a)
{
    asm volatile("ldmatrix.sync.aligned.m8n8.x4.shared.b16 {%0,%1,%2,%3}, [%4];"
                 : "=r"(r[0]), "=r"(r[1]), "=r"(r[2]), "=r"(r[3]) : "r"(a));
}

// ---------------------------------------------------------------------------
// Scratch
// ---------------------------------------------------------------------------
struct Scratch {
    alignas(16) float xw[(long long)NBN * HD];        // x @ W1
    alignas(16) int   cnt[NBN];
    alignas(16) int   off[NBN + 4];
    alignas(16) int   csr[EDGES];
    alignas(16) float dinv[NBN];
    alignas(16) float score[NBN];
    alignas(16) int   perm[BGR * KP1];
    alignas(16) int   rank[NBN];
    alignas(16) float h1[(long long)BGR * KP1 * HD];
    alignas(16) uint8_t A1c[(long long)BGR * KP1 * KP1]; // 0/1 A_ind
    alignas(16) float A1[(long long)BGR * KP1 * KP1];    // adj1 (softmax out)
    alignas(16) float ef1[BGR * KP1 * 2];
    alignas(16) float x1[BGR * 2 * HD];
    alignas(16) float c2[HD];
    alignas(16) float xw2[(long long)BGR * KP1 * HD];
    alignas(16) float h2[(long long)BGR * KP1 * HD];
    alignas(16) float prop[(long long)BGR * KP1 * HD];
    alignas(16) float score2[BGR * KP1];
    alignas(16) int   idx2[BGR * KP2];
    alignas(16) float h2sel[(long long)BGR * KP2 * HD];
    alignas(16) float A2[(long long)BGR * KP2 * KP2];
    alignas(16) float A2s[(long long)BGR * KP2 * KP2];   // adj2 (softmax out)
    alignas(16) float ef2[BGR * KP2 * 2];
    alignas(16) float x2[BGR * 2 * HD];
    alignas(16) float xw3[(long long)BGR * KP2 * HD];
    alignas(16) float h3[(long long)BGR * KP2 * HD];
    alignas(16) float x3[BGR * 2 * HD];
    // bf16 split weights (transposed [n][k])
    alignas(16) __nv_bfloat16 w1th[HD * FD];
    alignas(16) __nv_bfloat16 w1tl[HD * FD];
    alignas(16) __nv_bfloat16 w2fth[HD * HD];
    alignas(16) __nv_bfloat16 w2ftl[HD * HD];
    alignas(16) __nv_bfloat16 w3th[HD * HD];
    alignas(16) __nv_bfloat16 w3tl[HD * HD];
    // bf16 split A operands (row-major, emitted by producers)
    alignas(16) __nv_bfloat16 xh[(long long)NBN * FD];
    alignas(16) __nv_bfloat16 xl[(long long)NBN * FD];
    alignas(16) __nv_bfloat16 h1h[(long long)BGR * KP1 * HD];
    alignas(16) __nv_bfloat16 h1l[(long long)BGR * KP1 * HD];
    alignas(16) __nv_bfloat16 A1h[(long long)BGR * KP1 * KP1];
    alignas(16) __nv_bfloat16 A1l[(long long)BGR * KP1 * KP1];
    alignas(16) __nv_bfloat16 h2selh[(long long)BGR * KP2 * HD];
    alignas(16) __nv_bfloat16 h2sell[(long long)BGR * KP2 * HD];
    alignas(16) __nv_bfloat16 A2h[(long long)BGR * KP2 * KP2];
    alignas(16) __nv_bfloat16 A2l[(long long)BGR * KP2 * KP2];
    // bf16 split transposed activations (produced by bmma epilogue)
    alignas(16) __nv_bfloat16 xw2th[(long long)BGR * HD * KP1];
    alignas(16) __nv_bfloat16 xw2tl[(long long)BGR * HD * KP1];
    alignas(16) __nv_bfloat16 h2th[(long long)BGR * HD * KP1];
    alignas(16) __nv_bfloat16 h2tl[(long long)BGR * HD * KP1];
    alignas(16) __nv_bfloat16 xw3th[(long long)BGR * HD * KP2];
    alignas(16) __nv_bfloat16 xw3tl[(long long)BGR * HD * KP2];
};
__device__ Scratch S;

// ---------------------------------------------------------------------------
// bmma: pipelined split-bf16 HMMA GEMM, single __syncthreads per K-chunk.
// ---------------------------------------------------------------------------
#define ST  40
#define SZB (128 * ST)
#define BMMA_SMEM (2 * 4 * SZB * 2)

__global__ __launch_bounds__(256, 2)
void bmma(const __nv_bfloat16* __restrict__ Ah, const __nv_bfloat16* __restrict__ Al,
          const __nv_bfloat16* __restrict__ Bh, const __nv_bfloat16* __restrict__ Bl,
          const float* __restrict__ D, float* __restrict__ C,
          __nv_bfloat16* __restrict__ CTh, __nv_bfloat16* __restrict__ CTl,
          int M, int N, int K,
          long long sA, long long sB, long long sD, long long sC, long long sCT,
          const float* __restrict__ bias, float scale, int doRelu)
{
    extern __shared__ __nv_bfloat16 dyn[];
    uint32_t smem_base = (uint32_t)__cvta_generic_to_shared(dyn);

    long long z = blockIdx.z;
    const __nv_bfloat16* Ahb = Ah + z * sA;
    const __nv_bfloat16* Alb = Al + z * sA;
    const __nv_bfloat16* Bhb = Bh + z * sB;
    const __nv_bfloat16* Blb = Bl + z * sB;
    const float* Db = D ? (D + z * sD) : nullptr;
    float* Cb = C + z * sC;
    __nv_bfloat16* CThb = CTh ? (CTh + z * sCT) : nullptr;
    __nv_bfloat16* CTlb = CTl ? (CTl + z * sCT) : nullptr;

    int tid = threadIdx.x;
    int warp = tid >> 5, lane = tid & 31;
    int gid = lane >> 2, tig = lane & 3;
    int wm = warp >> 1, wn = warp & 1;
    int m0 = wm * 32, n0 = wn * 64;
    int row0 = blockIdx.y * 128, col0 = blockIdx.x * 128;

    uint32_t aoff = (uint32_t)((m0 + (lane & 15)) * ST + (lane >> 4) * 8) * 2;
    uint32_t boff = (uint32_t)((n0 + (lane >> 4) * 8 + (lane & 7)) * ST
                               + ((lane >> 3) & 1) * 8) * 2;

    float acc[2][8][4];
#pragma unroll
    for (int mt = 0; mt < 2; mt++)
#pragma unroll
        for (int nt = 0; nt < 8; nt++)
#pragma unroll
            for (int i = 0; i < 4; i++) acc[mt][nt][i] = 0.f;

    auto copy_chunk = [&](int buf, int kc) {
        uint32_t base = smem_base + (uint32_t)buf * 4 * SZB * 2;
#pragma unroll
        for (int it = 0; it < 2; it++) {
            int idx = it * 256 + tid;
            int row = idx >> 2, c8 = (idx & 3) << 3;
            uint32_t so = (uint32_t)(row * ST + c8) * 2;
            long long ga = (long long)(row0 + row) * K + kc + c8;
            long long gb = (long long)(col0 + row) * K + kc + c8;
            cp16(base + 0 * SZB * 2 + so, Ahb + ga);
            cp16(base + 1 * SZB * 2 + so, Alb + ga);
            cp16(base + 2 * SZB * 2 + so, Bhb + gb);
            cp16(base + 3 * SZB * 2 + so, Blb + gb);
        }
        asm volatile("cp.async.commit_group;" ::: "memory");
    };

    copy_chunk(0, 0);
    int buf = 0;
    for (int kc = 0; kc < K; kc += 32) {
        asm volatile("cp.async.wait_group 0;" ::: "memory");
        __syncthreads();
        if (kc + 32 < K) copy_chunk(buf ^ 1, kc + 32);

        uint32_t bufb = smem_base + (uint32_t)buf * 4 * SZB * 2;
        uint32_t aH = bufb + aoff;
        uint32_t aL = bufb + SZB * 2 + aoff;
        uint32_t bH = bufb + 2 * SZB * 2 + boff;
        uint32_t bL = bufb + 3 * SZB * 2 + boff;

#pragma unroll
        for (int ks = 0; ks < 2; ks++) {
            uint32_t kbb = (uint32_t)ks * 32;
            uint32_t ah[2][4], al[2][4];
            ldsm4(ah[0], aH + kbb);
            ldsm4(ah[1], aH + 16 * ST * 2 + kbb);
            ldsm4(al[0], aL + kbb);
            ldsm4(al[1], aL + 16 * ST * 2 + kbb);
#pragma unroll
            for (int p = 0; p < 4; p++) {
                uint32_t bh[4], bl[4];
                ldsm4(bh, bH + (uint32_t)p * 16 * ST * 2 + kbb);
                ldsm4(bl, bL + (uint32_t)p * 16 * ST * 2 + kbb);
#pragma unroll
                for (int mt = 0; mt < 2; mt++) {
                    mma_bf16(acc[mt][2 * p], ah[mt], bh[0], bh[1]);
                    mma_bf16(acc[mt][2 * p], ah[mt], bl[0], bl[1]);
                    mma_bf16(acc[mt][2 * p], al[mt], bh[0], bh[1]);
                    mma_bf16(acc[mt][2 * p + 1], ah[mt], bh[2], bh[3]);
                    mma_bf16(acc[mt][2 * p + 1], ah[mt], bl[2], bl[3]);
                    mma_bf16(acc[mt][2 * p + 1], al[mt], bh[2], bh[3]);
                }
            }
        }
        buf ^= 1;
    }

    // epilogue
#pragma unroll
    for (int mt = 0; mt < 2; mt++) {
        long long r = row0 + m0 + mt * 16 + gid;
#pragma unroll
        for (int nt = 0; nt < 8; nt++) {
            int c = col0 + n0 + nt * 8 + tig * 2;
            float v0 = acc[mt][nt][0], v1 = acc[mt][nt][1];
            float v2 = acc[mt][nt][2], v3 = acc[mt][nt][3];
            if (Db) {
                float2 d0 = *(const float2*)(Db + r * N + c);
                float2 d1 = *(const float2*)(Db + (r + 8) * N + c);
                v0 += d0.x; v1 += d0.y; v2 += d1.x; v3 += d1.y;
            }
            v0 *= scale; v1 *= scale; v2 *= scale; v3 *= scale;
            if (bias) {
                float2 bb = *(const float2*)(bias + c);
                v0 += bb.x; v1 += bb.y; v2 += bb.x; v3 += bb.y;
            }
            if (doRelu) {
                v0 = fmaxf(v0, 0.f); v1 = fmaxf(v1, 0.f);
                v2 = fmaxf(v2, 0.f); v3 = fmaxf(v3, 0.f);
            }
            *(float2*)(Cb + r * N + c) = make_float2(v0, v1);
            *(float2*)(Cb + (r + 8) * N + c) = make_float2(v2, v3);
            if (CThb) {
                __nv_bfloat16 h0 = __float2bfloat16(v0);
                __nv_bfloat16 h1 = __float2bfloat16(v1);
                __nv_bfloat16 h2_ = __float2bfloat16(v2);
                __nv_bfloat16 h3_ = __float2bfloat16(v3);
                CThb[(long long)c * M + r] = h0;
                CThb[(long long)c * M + r + 8] = h2_;
                CThb[(long long)(c + 1) * M + r] = h1;
                CThb[(long long)(c + 1) * M + r + 8] = h3_;
                CTlb[(long long)c * M + r] = __float2bfloat16(v0 - __bfloat162float(h0));
                CTlb[(long long)c * M + r + 8] = __float2bfloat16(v2 - __bfloat162float(h2_));
                CTlb[(long long)(c + 1) * M + r] = __float2bfloat16(v1 - __bfloat162float(h1));
                CTlb[(long long)(c + 1) * M + r + 8] = __float2bfloat16(v3 - __bfloat162float(h3_));
            }
        }
    }
}

// ---------------------------------------------------------------------------
// split / weight prep kernels
// ---------------------------------------------------------------------------
__global__ void split_x(const float* __restrict__ in, __nv_bfloat16* __restrict__ hi,
                        __nv_bfloat16* __restrict__ lo, long long n4)
{
    long long i = (long long)blockIdx.x * 256 + threadIdx.x;
    if (i >= n4) return;
    float4 v = ((const float4*)in)[i];
    __nv_bfloat16 h0 = __float2bfloat16(v.x), h1 = __float2bfloat16(v.y);
    __nv_bfloat16 h2 = __float2bfloat16(v.z), h3 = __float2bfloat16(v.w);
    __nv_bfloat162 ha, hb, la, lb;
    ha.x = h0; ha.y = h1; hb.x = h2; hb.y = h3;
    la.x = __float2bfloat16(v.x - __bfloat162float(h0));
    la.y = __float2bfloat16(v.y - __bfloat162float(h1));
    lb.x = __float2bfloat16(v.z - __bfloat162float(h2));
    lb.y = __float2bfloat16(v.w - __bfloat162float(h3));
    ((__nv_bfloat162*)hi)[2 * i] = ha; ((__nv_bfloat162*)hi)[2 * i + 1] = hb;
    ((__nv_bfloat162*)lo)[2 * i] = la; ((__nv_bfloat162*)lo)[2 * i + 1] = lb;
}

__global__ void split_w1t(const float* __restrict__ W, __nv_bfloat16* __restrict__ hi,
                          __nv_bfloat16* __restrict__ lo)
{
    int n = blockIdx.x;
    int k = threadIdx.x;
    float v = W[k * HD + n];
    __nv_bfloat16 h = __float2bfloat16(v);
    hi[n * FD + k] = h;
    lo[n * FD + k] = __float2bfloat16(v - __bfloat162float(h));
}

__global__ void foldW2(const float* __restrict__ W2, const float* __restrict__ gam,
                       const float* __restrict__ bet, const float* __restrict__ mean,
                       const float* __restrict__ var,
                       __nv_bfloat16* __restrict__ Wth, __nv_bfloat16* __restrict__ Wtl,
                       float* __restrict__ c2)
{
    int n = blockIdx.x;
    int k = threadIdx.x;
    float sc_ = gam[k] * rsqrtf(var[k] + 1e-5f);
    float sh = bet[k] - mean[k] * sc_;
    float w0 = W2[k * HD + n];
    float w = w0 * sc_;
    __nv_bfloat16 h = __float2bfloat16(w);
    Wth[n * HD + k] = h;
    Wtl[n * HD + k] = __float2bfloat16(w - __bfloat162float(h));
    __shared__ float red[256];
    red[k] = sh * w0;
    __syncthreads();
    for (int s = 128; s > 0; s >>= 1) {
        if (k < s) red[k] += red[k + s];
        __syncthreads();
    }
    if (k == 0) c2[n] = red[0];
}

__global__ void split_w3t(const float* __restrict__ W, __nv_bfloat16* __restrict__ hi,
                          __nv_bfloat16* __restrict__ lo)
{
    int n = blockIdx.x;
    int k = threadIdx.x;
    float v = W[k * HD + n];
    __nv_bfloat16 h = __float2bfloat16(v);
    hi[n * HD + k] = h;
    lo[n * HD + k] = __float2bfloat16(v - __bfloat162float(h));
}

// ---------------------------------------------------------------------------
// csr_build: per-graph deterministic counting sort in smem.
// 1 CTA = 1 graph, 512 threads. Thread t owns local dst bucket t.
// Bucket contents in edge-index order (deterministic). Also emits
// cnt/off/dinv and initializes rank=-1. Dynamic smem: 2*EPG ints = 64KB.
// ---------------------------------------------------------------------------
#define CSR_SMEM (2 * EPG * 4)

__global__ __launch_bounds__(512)
void csr_build(const int* __restrict__ src, const int* __restrict__ dst,
               int* __restrict__ csr, int* __restrict__ off, int* __restrict__ cnt,
               float* __restrict__ dinv, int* __restrict__ rank)
{
    extern __shared__ int sed[];          // [0..EPG) = src, [EPG..2EPG) = dst
    __shared__ int soff[512];
    int g = blockIdx.x;
    int t = threadIdx.x;
    int ebase = g * EPG;
    int nbase = g * NN;

    for (int i = t; i < EPG; i += 512) {
        sed[i] = src[ebase + i] - nbase;
        sed[EPG + i] = dst[ebase + i] - nbase;
    }
    __syncthreads();

    // count (vectorized broadcast walk)
    int c = 0;
    const int4* d4 = (const int4*)(sed + EPG);
    for (int e = 0; e < EPG / 4; e++) {
        int4 v = d4[e];
        c += (v.x == t) + (v.y == t) + (v.z == t) + (v.w == t);
    }
    // inclusive scan over 512 counters
    int v = c;
    soff[t] = c;
    __syncthreads();
    for (int d = 1; d < 512; d <<= 1) {
        int u = (t >= d) ? soff[t - d] : 0;
        __syncthreads();
        soff[t] += u;
        __syncthreads();
    }
    int myoff = soff[t] - v;   // exclusive

    // scatter: edge-index order per bucket
    int p = ebase + myoff;
    for (int e = 0; e < EPG; e++) {
        if (sed[EPG + e] == t) csr[p++] = nbase + sed[e];
    }

    int gn = nbase + t;
    cnt[gn] = c;
    off[gn] = ebase + myoff;
    dinv[gn] = rsqrtf((float)(c + 1));
    rank[gn] = -1;
    if (g == BGR - 1 && t == 511) off[NBN] = EDGES;
}

// ---------------------------------------------------------------------------
// Graph gather kernels (R8/R10 versions)
// ---------------------------------------------------------------------------
__global__ __launch_bounds__(256)
void gcn_agg(const float4* __restrict__ xw4, const int* __restrict__ off,
             const int* __restrict__ csr, const float* __restrict__ dinv,
             const float4* __restrict__ b1_4, float4* __restrict__ h4)
{
    int g = threadIdx.x >> 6;
    int t = threadIdx.x & 63;
    int i = blockIdx.x * 4 + g;
    float di = dinv[i];
    float4 a = xw4[(long long)i * 64 + t];
    float w0 = di * di;
    float4 acc = make_float4(a.x * w0, a.y * w0, a.z * w0, a.w * w0);
    float4 acc2 = make_float4(0.f, 0.f, 0.f, 0.f);
    int e0 = off[i], e1 = off[i + 1];
    int e = e0;
    for (; e + 1 < e1; e += 2) {
        int s0 = csr[e], s1 = csr[e + 1];
        float wa = dinv[s0] * di, wb = dinv[s1] * di;
        float4 v0 = xw4[(long long)s0 * 64 + t];
        float4 v1 = xw4[(long long)s1 * 64 + t];
        acc.x += v0.x * wa; acc.y += v0.y * wa; acc.z += v0.z * wa; acc.w += v0.w * wa;
        acc2.x += v1.x * wb; acc2.y += v1.y * wb; acc2.z += v1.z * wb; acc2.w += v1.w * wb;
    }
    if (e < e1) {
        int s0 = csr[e];
        float wa = dinv[s0] * di;
        float4 v0 = xw4[(long long)s0 * 64 + t];
        acc.x += v0.x * wa; acc.y += v0.y * wa; acc.z += v0.z * wa; acc.w += v0.w * wa;
    }
    acc.x += acc2.x; acc.y += acc2.y; acc.z += acc2.z; acc.w += acc2.w;
    float4 bb = b1_4[t];
    acc.x = fmaxf(acc.x + bb.x, 0.f);
    acc.y = fmaxf(acc.y + bb.y, 0.f);
    acc.z = fmaxf(acc.z + bb.z, 0.f);
    acc.w = fmaxf(acc.w + bb.w, 0.f);
    h4[(long long)i * 64 + t] = acc;
}

__global__ __launch_bounds__(256)
void pool_score(const float4* __restrict__ h4, const int* __restrict__ off,
                const int* __restrict__ csr, const int* __restrict__ cnt,
                float* __restrict__ score)
{
    __shared__ float red[4][2];
    int g = threadIdx.x >> 6;
    int t = threadIdx.x & 63;
    int i = blockIdx.x * 4 + g;
    float4 acc = make_float4(0.f, 0.f, 0.f, 0.f);
    float4 acc2 = make_float4(0.f, 0.f, 0.f, 0.f);
    int e0 = off[i], e1 = off[i + 1];
    int e = e0;
    for (; e + 1 < e1; e += 2) {
        int s0 = csr[e], s1 = csr[e + 1];
        float4 v0 = h4[(long long)s0 * 64 + t];
        float4 v1 = h4[(long long)s1 * 64 + t];
        acc.x += v0.x; acc.y += v0.y; acc.z += v0.z; acc.w += v0.w;
        acc2.x += v1.x; acc2.y += v1.y; acc2.z += v1.z; acc2.w += v1.w;
    }
    if (e < e1) {
        int s0 = csr[e];
        float4 v0 = h4[(long long)s0 * 64 + t];
        acc.x += v0.x; acc.y += v0.y; acc.z += v0.z; acc.w += v0.w;
    }
    acc.x += acc2.x; acc.y += acc2.y; acc.z += acc2.z; acc.w += acc2.w;
    float degp = fmaxf((float)cnt[i], 1.f);
    float4 hh = h4[(long long)i * 64 + t];
    float s = fabsf(hh.x - acc.x / degp) + fabsf(hh.y - acc.y / degp)
            + fabsf(hh.z - acc.z / degp) + fabsf(hh.w - acc.w / degp);
#pragma unroll
    for (int o = 16; o > 0; o >>= 1)
        s += __shfl_down_sync(0xffffffff, s, o);
    if ((t & 31) == 0) red[g][t >> 5] = s;
    __syncthreads();
    if (t == 0) score[i] = red[g][0] + red[g][1];
}

__global__ void topk_kernel(const float* __restrict__ score, int n, int kout,
                            int* outidx, int* rank)
{
    int g = blockIdx.x;
    int t = threadIdx.x;
    __shared__ float s[512];
    __shared__ int id[512];
    s[t] = score[g * n + t];
    id[t] = t;
    __syncthreads();
    for (int k = 2; k <= n; k <<= 1)
        for (int j = k >> 1; j > 0; j >>= 1) {
            int p = t ^ j;
            if (p > t) {
                float s1 = s[t], s2 = s[p];
                int i1 = id[t], i2 = id[p];
                bool lt12 = (s1 > s2) || (s1 == s2 && i1 < i2);
                bool up = ((t & k) == 0);
                if (up ? !lt12 : lt12) { s[t] = s2; s[p] = s1; id[t] = i2; id[p] = i1; }
            }
            __syncthreads();
        }
    if (t < kout) {
        if (rank) {
            int node = g * n + id[t];
            outidx[g * kout + t] = node;
            rank[node] = t;
        } else {
            outidx[g * kout + t] = id[t];
        }
    }
}

__global__ void gather_rows_ef(const float* __restrict__ h, const int* __restrict__ perm,
                               const float* __restrict__ att,
                               float* __restrict__ h1, __nv_bfloat16* __restrict__ h1h,
                               __nv_bfloat16* __restrict__ h1l, float* __restrict__ ef)
{
    long long n = blockIdx.x;
    int c = threadIdx.x;
    float v = h[(long long)perm[n] * HD + c];
    h1[n * HD + c] = v;
    __nv_bfloat16 hh = __float2bfloat16(v);
    h1h[n * HD + c] = hh;
    h1l[n * HD + c] = __float2bfloat16(v - __bfloat162float(hh));
    __shared__ float re[256], rf[256];
    re[c] = v * att[2 * c];
    rf[c] = v * att[2 * c + 1];
    __syncthreads();
    for (int s = 128; s > 0; s >>= 1) {
        if (c < s) { re[c] += re[c + s]; rf[c] += rf[c + s]; }
        __syncthreads();
    }
    if (c == 0) { ef[2 * n] = re[0]; ef[2 * n + 1] = rf[0]; }
}

__global__ void zero_c(uint8_t* p, long long n16)
{
    long long i = (long long)blockIdx.x * 256 + threadIdx.x;
    if (i < n16) ((uint4*)p)[i] = make_uint4(0, 0, 0, 0);
}

__global__ void buildA1(const int* __restrict__ src, const int* __restrict__ dst,
                        const int* __restrict__ rank, uint8_t* __restrict__ A1c, int E)
{
    int e = blockIdx.x * 256 + threadIdx.x;
    if (e >= E) return;
    int s = src[e], d = dst[e];
    int ns = rank[s], nd = rank[d];
    if (ns >= 0 && nd >= 0) {
        int g = s >> 9;
        A1c[(((long long)g * KP1 + ns) * KP1) + nd] = 1;
    }
}

__global__ void struct_softmax(const uint8_t* __restrict__ Ac,
                               const float* __restrict__ Af,
                               const float* __restrict__ ef, int Kd,
                               float* __restrict__ Aout,
                               __nv_bfloat16* __restrict__ Ah,
                               __nv_bfloat16* __restrict__ Al)
{
    int row = blockIdx.x;
    int j = threadIdx.x;
    int b = row / Kd;
    long long base = (long long)row * Kd;
    float aind = Ac ? (float)Ac[base + j] : Af[base + j];
    float logit = ef[2 * row] + ef[2 * (b * Kd + j) + 1] + aind;
    __shared__ float red[256];
    red[j] = logit;
    __syncthreads();
    for (int s = Kd >> 1; s > 0; s >>= 1) {
        if (j < s) red[j] = fmaxf(red[j], red[j + s]);
        __syncthreads();
    }
    float m = red[0];
    __syncthreads();
    float e = expf(logit - m);
    red[j] = e;
    __syncthreads();
    for (int s = Kd >> 1; s > 0; s >>= 1) {
        if (j < s) red[j] += red[j + s];
        __syncthreads();
    }
    float v = e / red[0];
    Aout[base + j] = v;
    __nv_bfloat16 hh = __float2bfloat16(v);
    Ah[base + j] = hh;
    Al[base + j] = __float2bfloat16(v - __bfloat162float(hh));
}

__global__ void readout_k(const float* __restrict__ X, float* __restrict__ out, int Kd)
{
    __shared__ float smx[4][256], ssm[4][256];
    int b = blockIdx.x;
    int part = threadIdx.x >> 8;
    int c = threadIdx.x & 255;
    int kq = Kd >> 2;
    int k0 = part * kq, k1 = k0 + kq;
    float mx = -3.4e38f, sm = 0.f;
    for (int k = k0; k < k1; k++) {
        float v = X[((long long)b * Kd + k) * HD + c];
        mx = fmaxf(mx, v);
        sm += v;
    }
    smx[part][c] = mx;
    ssm[part][c] = sm;
    __syncthreads();
    if (part == 0) {
        float m = fmaxf(fmaxf(smx[0][c], smx[1][c]), fmaxf(smx[2][c], smx[3][c]));
        float s = ssm[0][c] + ssm[1][c] + ssm[2][c] + ssm[3][c];
        out[b * 2 * HD + c] = m;
        out[b * 2 * HD + HD + c] = s / (float)Kd;
    }
}

__global__ void score_dense(const float* __restrict__ X, const float* __restrict__ P,
                            float* __restrict__ sc)
{
    int row = blockIdx.x;
    int c = threadIdx.x;
    __shared__ float red[256];
    long long base = (long long)row * HD;
    red[c] = fabsf(X[base + c] - P[base + c]);
    __syncthreads();
    for (int s = 128; s > 0; s >>= 1) {
        if (c < s) red[c] += red[c + s];
        __syncthreads();
    }
    if (c == 0) sc[row] = red[0];
}

__global__ void gather_h2sel_ef(const float* __restrict__ h2, const int* __restrict__ idx2,
                                const float* __restrict__ att,
                                float* __restrict__ h2sel, __nv_bfloat16* __restrict__ sh,
                                __nv_bfloat16* __restrict__ sl, float* __restrict__ ef)
{
    int n = blockIdx.x;
    int c = threadIdx.x;
    int b = n >> 7;
    int row = idx2[n];
    float v = h2[((long long)b * KP1 + row) * HD + c];
    h2sel[(long long)n * HD + c] = v;
    __nv_bfloat16 hh = __float2bfloat16(v);
    sh[(long long)n * HD + c] = hh;
    sl[(long long)n * HD + c] = __float2bfloat16(v - __bfloat162float(hh));
    __shared__ float re[256], rf[256];
    re[c] = v * att[2 * c];
    rf[c] = v * att[2 * c + 1];
    __syncthreads();
    for (int s = 128; s > 0; s >>= 1) {
        if (c < s) { re[c] += re[c + s]; rf[c] += rf[c + s]; }
        __syncthreads();
    }
    if (c == 0) { ef[2 * n] = re[0]; ef[2 * n + 1] = rf[0]; }
}

__global__ void gatherA2(const float* __restrict__ adj1, const int* __restrict__ idx2,
                         float* __restrict__ A2)
{
    int n = blockIdx.x;
    int j = threadIdx.x;
    int b = n >> 7;
    int ri = idx2[n];
    int rj = idx2[b * KP2 + j];
    A2[(long long)n * KP2 + j] = adj1[((long long)b * KP1 + ri) * KP1 + rj];
}

__global__ void head(const float* __restrict__ x1, const float* __restrict__ x2,
                     const float* __restrict__ x3,
                     const float* __restrict__ l1w, const float* __restrict__ l1b,
                     const float* __restrict__ l2w, const float* __restrict__ l2b,
                     const float* __restrict__ l3w, const float* __restrict__ l3b,
                     float* __restrict__ out_x, float* __restrict__ out_lp)
{
    int b = blockIdx.x;
    int t = threadIdx.x;
    __shared__ float g[512], g1[256], g2[128], lg[10];
    for (int i = t; i < 512; i += 256) {
        g[i] = fmaxf(x1[b * 512 + i], 0.f) + fmaxf(x2[b * 512 + i], 0.f) +
               fmaxf(x3[b * 512 + i], 0.f);
    }
    __syncthreads();
    {
        float a = 0.f;
        for (int c = 0; c < 512; c++) a += g[c] * l1w[c * 256 + t];
        g1[t] = fmaxf(a + l1b[t], 0.f);
    }
    __syncthreads();
    if (t < 128) {
        float a = 0.f;
        for (int c = 0; c < 256; c++) a += g1[c] * l2w[c * 128 + t];
        float v = fmaxf(a + l2b[t], 0.f);
        g2[t] = v;
        out_x[b * 128 + t] = v;
    }
    __syncthreads();
    if (t < 10) {
        float a = 0.f;
        for (int c = 0; c < 128; c++) a += g2[c] * l3w[c * 10 + t];
        lg[t] = a + l3b[t];
    }
    __syncthreads();
    if (t == 0) {
        float m = -3.4e38f;
        for (int i = 0; i < 10; i++) m = fmaxf(m, lg[i]);
        float s = 0.f;
        for (int i = 0; i < 10; i++) s += expf(lg[i] - m);
        float lse = m + logf(s);
        for (int i = 0; i < 10; i++) out_lp[b * 10 + i] = lg[i] - lse;
    }
}

// ---------------------------------------------------------------------------
// Launch
// ---------------------------------------------------------------------------
extern "C" void kernel_launch(void* const* d_in, const int* in_sizes, int n_in,
                              void* d_out, int out_size)
{
    void* sp = nullptr;
    cudaGetSymbolAddress(&sp, S);
    Scratch* sc = (Scratch*)sp;

    const float* x    = (const float*)d_in[0];
    const int*   ei   = (const int*)d_in[1];
    const float* W1   = (const float*)d_in[3];
    const float* b1   = (const float*)d_in[4];
    const float* W2   = (const float*)d_in[5];
    const float* b2   = (const float*)d_in[6];
    const float* W3   = (const float*)d_in[7];
    const float* b3   = (const float*)d_in[8];
    const float* att1 = (const float*)d_in[9];
    const float* att2 = (const float*)d_in[10];
    const float* bng  = (const float*)d_in[11];
    const float* bnb  = (const float*)d_in[12];
    const float* bnm  = (const float*)d_in[13];
    const float* bnv  = (const float*)d_in[14];
    const float* l1w  = (const float*)d_in[15];
    const float* l1b  = (const float*)d_in[16];
    const float* l2w  = (const float*)d_in[17];
    const float* l2b  = (const float*)d_in[18];
    const float* l3w  = (const float*)d_in[19];
    const float* l3b  = (const float*)d_in[20];

    int E = in_sizes[1] / 2;
    const int* src = ei;
    const int* dst = ei + E;

    float* out    = (float*)d_out;
    float* out_x  = out;                        // [128,128]
    float* out_lp = out + BGR * 128;            // [128,10]
    float* h      = out + BGR * 128 + BGR * 10; // x__ = [65536,256]

    cudaFuncSetAttribute(bmma, cudaFuncAttributeMaxDynamicSharedMemorySize,
                         BMMA_SMEM);
    cudaFuncSetAttribute(csr_build, cudaFuncAttributeMaxDynamicSharedMemorySize,
                         CSR_SMEM);

    // --- prep + big GEMM (bmma is 4th launch -> profiled) ---
    split_x<<<32768, 256>>>(x, sc->xh, sc->xl, (long long)NBN * FD / 4);
    split_w1t<<<HD, FD>>>(W1, sc->w1th, sc->w1tl);
    foldW2<<<HD, HD>>>(W2, bng, bnb, bnm, bnv, sc->w2fth, sc->w2ftl, sc->c2);
    bmma<<<dim3(HD / 128, NBN / 128, 1), 256, BMMA_SMEM>>>(
        sc->xh, sc->xl, sc->w1th, sc->w1tl, nullptr, sc->xw, nullptr, nullptr,
        NBN, HD, FD, 0, 0, 0, 0, 0, nullptr, 1.0f, 0);
    split_w3t<<<HD, HD>>>(W3, sc->w3th, sc->w3tl);

    // --- stage 1: sparse GCN ---
    csr_build<<<BGR, 512, CSR_SMEM>>>(src, dst, sc->csr, sc->off, sc->cnt,
                                      sc->dinv, sc->rank);
    gcn_agg<<<NBN / 4, 256>>>((const float4*)sc->xw, sc->off, sc->csr, sc->dinv,
                              (const float4*)b1, (float4*)h);

    // --- stage 1 pool (sparse) ---
    pool_score<<<NBN / 4, 256>>>((const float4*)h, sc->off, sc->csr, sc->cnt,
                                 sc->score);
    topk_kernel<<<BGR, NN>>>(sc->score, NN, KP1, sc->perm, sc->rank);
    gather_rows_ef<<<BGR * KP1, 256>>>(h, sc->perm, att1, sc->h1,
                                       sc->h1h, sc->h1l, sc->ef1);
    zero_c<<<(int)(((long long)BGR * KP1 * KP1 / 16 + 255) / 256), 256>>>(
        sc->A1c, (long long)BGR * KP1 * KP1 / 16);
    buildA1<<<(E + 255) / 256, 256>>>(src, dst, sc->rank, sc->A1c, E);
    struct_softmax<<<BGR * KP1, KP1>>>(sc->A1c, nullptr, sc->ef1, KP1,
                                       sc->A1, sc->A1h, sc->A1l);
    readout_k<<<BGR, 1024>>>(sc->h1, sc->x1, KP1);

    // --- stage 2: BN folded + dense GCN (An = (adj+I)/2 exactly) ---
    bmma<<<dim3(2, 2, BGR), 256, BMMA_SMEM>>>(
        sc->h1h, sc->h1l, sc->w2fth, sc->w2ftl, nullptr, sc->xw2,
        sc->xw2th, sc->xw2tl,
        KP1, HD, HD, (long long)KP1 * HD, 0, 0, (long long)KP1 * HD,
        (long long)KP1 * HD, sc->c2, 1.0f, 0);
    bmma<<<dim3(2, 2, BGR), 256, BMMA_SMEM>>>(
        sc->A1h, sc->A1l, sc->xw2th, sc->xw2tl, sc->xw2, sc->h2,
        sc->h2th, sc->h2tl,
        KP1, HD, KP1, (long long)KP1 * KP1, (long long)KP1 * HD,
        (long long)KP1 * HD, (long long)KP1 * HD, (long long)KP1 * HD,
        b2, 0.5f, 1);
    bmma<<<dim3(2, 2, BGR), 256, BMMA_SMEM>>>(
        sc->A1h, sc->A1l, sc->h2th, sc->h2tl, nullptr, sc->prop, nullptr, nullptr,
        KP1, HD, KP1, (long long)KP1 * KP1, (long long)KP1 * HD, 0,
        (long long)KP1 * HD, 0, nullptr, 1.0f, 0);
    score_dense<<<BGR * KP1, 256>>>(sc->h2, sc->prop, sc->score2);
    topk_kernel<<<BGR, KP1>>>(sc->score2, KP1, KP2, sc->idx2, nullptr);
    gather_h2sel_ef<<<BGR * KP2, 256>>>(sc->h2, sc->idx2, att2, sc->h2sel,
                                        sc->h2selh, sc->h2sell, sc->ef2);
    gatherA2<<<BGR * KP2, KP2>>>(sc->A1, sc->idx2, sc->A2);
    struct_softmax<<<BGR * KP2, KP2>>>(nullptr, sc->A2, sc->ef2, KP2,
                                       sc->A2s, sc->A2h, sc->A2l);
    readout_k<<<BGR, 1024>>>(sc->h2sel, sc->x2, KP2);

    // --- stage 3: dense GCN ---
    bmma<<<dim3(2, 1, BGR), 256, BMMA_SMEM>>>(
        sc->h2selh, sc->h2sell, sc->w3th, sc->w3tl, nullptr, sc->xw3,
        sc->xw3th, sc->xw3tl,
        KP2, HD, HD, (long long)KP2 * HD, 0, 0, (long long)KP2 * HD,
        (long long)KP2 * HD, nullptr, 1.0f, 0);
    bmma<<<dim3(2, 1, BGR), 256, BMMA_SMEM>>>(
        sc->A2h, sc->A2l, sc->xw3th, sc->xw3tl, sc->xw3, sc->h3, nullptr, nullptr,
        KP2, HD, KP2, (long long)KP2 * KP2, (long long)KP2 * HD,
        (long long)KP2 * HD, (long long)KP2 * HD, 0, b3, 0.5f, 1);
    readout_k<<<BGR, 1024>>>(sc->h3, sc->x3, KP2);

    // --- head ---
    head<<<BGR, 256>>>(sc->x1, sc->x2, sc->x3, l1w, l1b, l2w, l2b, l3w, l3b,
                       out_x, out_lp);
}

// round 12
// speedup vs baseline: 1.1632x; 1.1632x over previous
#include <cuda_runtime.h>
#include <cuda_bf16.h>
#include <math.h>
#include <stdint.h>

// Problem constants
#define NBN   65536      // B*N nodes
#define BGR   128        // graphs
#define NN    512        // nodes per graph
#define FD    512        // input features
#define HD    256        // hidden
#define KP1   256        // K1
#define KP2   128        // K2
#define EDGES 1048576    // B*EPG

typedef unsigned long long ull;

__device__ __forceinline__ void mma_bf16(float* c, const uint32_t* a,
                                         uint32_t b0, uint32_t b1)
{
    asm volatile(
        "mma.sync.aligned.m16n8k16.row.col.f32.bf16.bf16.f32 "
        "{%0,%1,%2,%3}, {%4,%5,%6,%7}, {%8,%9}, {%0,%1,%2,%3};"
        : "+f"(c[0]), "+f"(c[1]), "+f"(c[2]), "+f"(c[3])
        : "r"(a[0]), "r"(a[1]), "r"(a[2]), "r"(a[3]), "r"(b0), "r"(b1));
}

__device__ __forceinline__ void cp16(uint32_t dst, const void* src)
{
    asm volatile("cp.async.cg.shared.global [%0], [%1], 16;"
                 :: "r"(dst), "l"(src));
}

__device__ __forceinline__ void ldsm4(uint32_t* r, uint32_t a)
{
    asm volatile("ldmatrix.sync.aligned.m8n8.x4.shared.b16 {%0,%1,%2,%3}, [%4];"
                 : "=r"(r[0]), "=r"(r[1]), "=r"(r[2]), "=r"(r[3]) : "r"(a));
}

// ---------------------------------------------------------------------------
// Scratch
// ---------------------------------------------------------------------------
struct Scratch {
    alignas(16) float xw[(long long)NBN * HD];        // x @ W1
    alignas(16) int   cnt[NBN];
    alignas(16) int   off[NBN + 4];
    alignas(16) int   pos[NBN];
    alignas(16) int   csr[EDGES];
    alignas(16) int   bsum[256];
    alignas(16) float dinv[NBN];
    alignas(16) float score[NBN];
    alignas(16) int   perm[BGR * KP1];
    alignas(16) int   rank[NBN];
    alignas(16) float h1[(long long)BGR * KP1 * HD];
    alignas(16) uint8_t A1c[(long long)BGR * KP1 * KP1]; // 0/1 A_ind
    alignas(16) float A1[(long long)BGR * KP1 * KP1];    // adj1 (softmax out)
    alignas(16) float ef1[BGR * KP1 * 2];
    alignas(16) float x1[BGR * 2 * HD];
    alignas(16) float c2[HD];
    alignas(16) float xw2[(long long)BGR * KP1 * HD];
    alignas(16) float h2[(long long)BGR * KP1 * HD];
    alignas(16) float prop[(long long)BGR * KP1 * HD];
    alignas(16) float score2[BGR * KP1];
    alignas(16) int   idx2[BGR * KP2];
    alignas(16) float h2sel[(long long)BGR * KP2 * HD];
    alignas(16) float ef2[BGR * KP2 * 2];
    alignas(16) float x2[BGR * 2 * HD];
    alignas(16) float xw3[(long long)BGR * KP2 * HD];
    alignas(16) float h3[(long long)BGR * KP2 * HD];
    alignas(16) float x3[BGR * 2 * HD];
    // bf16 split weights (transposed [n][k])
    alignas(16) __nv_bfloat16 w1th[HD * FD];
    alignas(16) __nv_bfloat16 w1tl[HD * FD];
    alignas(16) __nv_bfloat16 w2fth[HD * HD];
    alignas(16) __nv_bfloat16 w2ftl[HD * HD];
    alignas(16) __nv_bfloat16 w3th[HD * HD];
    alignas(16) __nv_bfloat16 w3tl[HD * HD];
    // bf16 split A operands (row-major, emitted by producers)
    alignas(16) __nv_bfloat16 xh[(long long)NBN * FD];
    alignas(16) __nv_bfloat16 xl[(long long)NBN * FD];
    alignas(16) __nv_bfloat16 h1h[(long long)BGR * KP1 * HD];
    alignas(16) __nv_bfloat16 h1l[(long long)BGR * KP1 * HD];
    alignas(16) __nv_bfloat16 A1h[(long long)BGR * KP1 * KP1];
    alignas(16) __nv_bfloat16 A1l[(long long)BGR * KP1 * KP1];
    alignas(16) __nv_bfloat16 h2selh[(long long)BGR * KP2 * HD];
    alignas(16) __nv_bfloat16 h2sell[(long long)BGR * KP2 * HD];
    alignas(16) __nv_bfloat16 A2h[(long long)BGR * KP2 * KP2];
    alignas(16) __nv_bfloat16 A2l[(long long)BGR * KP2 * KP2];
    // bf16 split transposed activations (produced by bmma epilogue)
    alignas(16) __nv_bfloat16 xw2th[(long long)BGR * HD * KP1];
    alignas(16) __nv_bfloat16 xw2tl[(long long)BGR * HD * KP1];
    alignas(16) __nv_bfloat16 h2th[(long long)BGR * HD * KP1];
    alignas(16) __nv_bfloat16 h2tl[(long long)BGR * HD * KP1];
    alignas(16) __nv_bfloat16 xw3th[(long long)BGR * HD * KP2];
    alignas(16) __nv_bfloat16 xw3tl[(long long)BGR * HD * KP2];
};
__device__ Scratch S;

// ---------------------------------------------------------------------------
// bmma: pipelined split-bf16 HMMA GEMM, single __syncthreads per K-chunk.
// ---------------------------------------------------------------------------
#define ST  40
#define SZB (128 * ST)
#define BMMA_SMEM (2 * 4 * SZB * 2)

__global__ __launch_bounds__(256, 2)
void bmma(const __nv_bfloat16* __restrict__ Ah, const __nv_bfloat16* __restrict__ Al,
          const __nv_bfloat16* __restrict__ Bh, const __nv_bfloat16* __restrict__ Bl,
          const float* __restrict__ D, float* __restrict__ C,
          __nv_bfloat16* __restrict__ CTh, __nv_bfloat16* __restrict__ CTl,
          int M, int N, int K,
          long long sA, long long sB, long long sD, long long sC, long long sCT,
          const float* __restrict__ bias, float scale, int doRelu)
{
    extern __shared__ __nv_bfloat16 dyn[];
    uint32_t smem_base = (uint32_t)__cvta_generic_to_shared(dyn);

    long long z = blockIdx.z;
    const __nv_bfloat16* Ahb = Ah + z * sA;
    const __nv_bfloat16* Alb = Al + z * sA;
    const __nv_bfloat16* Bhb = Bh + z * sB;
    const __nv_bfloat16* Blb = Bl + z * sB;
    const float* Db = D ? (D + z * sD) : nullptr;
    float* Cb = C + z * sC;
    __nv_bfloat16* CThb = CTh ? (CTh + z * sCT) : nullptr;
    __nv_bfloat16* CTlb = CTl ? (CTl + z * sCT) : nullptr;

    int tid = threadIdx.x;
    int warp = tid >> 5, lane = tid & 31;
    int gid = lane >> 2, tig = lane & 3;
    int wm = warp >> 1, wn = warp & 1;
    int m0 = wm * 32, n0 = wn * 64;
    int row0 = blockIdx.y * 128, col0 = blockIdx.x * 128;

    uint32_t aoff = (uint32_t)((m0 + (lane & 15)) * ST + (lane >> 4) * 8) * 2;
    uint32_t boff = (uint32_t)((n0 + (lane >> 4) * 8 + (lane & 7)) * ST
                               + ((lane >> 3) & 1) * 8) * 2;

    float acc[2][8][4];
#pragma unroll
    for (int mt = 0; mt < 2; mt++)
#pragma unroll
        for (int nt = 0; nt < 8; nt++)
#pragma unroll
            for (int i = 0; i < 4; i++) acc[mt][nt][i] = 0.f;

    auto copy_chunk = [&](int buf, int kc) {
        uint32_t base = smem_base + (uint32_t)buf * 4 * SZB * 2;
#pragma unroll
        for (int it = 0; it < 2; it++) {
            int idx = it * 256 + tid;
            int row = idx >> 2, c8 = (idx & 3) << 3;
            uint32_t so = (uint32_t)(row * ST + c8) * 2;
            long long ga = (long long)(row0 + row) * K + kc + c8;
            long long gb = (long long)(col0 + row) * K + kc + c8;
            cp16(base + 0 * SZB * 2 + so, Ahb + ga);
            cp16(base + 1 * SZB * 2 + so, Alb + ga);
            cp16(base + 2 * SZB * 2 + so, Bhb + gb);
            cp16(base + 3 * SZB * 2 + so, Blb + gb);
        }
        asm volatile("cp.async.commit_group;" ::: "memory");
    };

    copy_chunk(0, 0);
    int buf = 0;
    for (int kc = 0; kc < K; kc += 32) {
        asm volatile("cp.async.wait_group 0;" ::: "memory");
        __syncthreads();
        if (kc + 32 < K) copy_chunk(buf ^ 1, kc + 32);

        uint32_t bufb = smem_base + (uint32_t)buf * 4 * SZB * 2;
        uint32_t aH = bufb + aoff;
        uint32_t aL = bufb + SZB * 2 + aoff;
        uint32_t bH = bufb + 2 * SZB * 2 + boff;
        uint32_t bL = bufb + 3 * SZB * 2 + boff;

#pragma unroll
        for (int ks = 0; ks < 2; ks++) {
            uint32_t kbb = (uint32_t)ks * 32;
            uint32_t ah[2][4], al[2][4];
            ldsm4(ah[0], aH + kbb);
            ldsm4(ah[1], aH + 16 * ST * 2 + kbb);
            ldsm4(al[0], aL + kbb);
            ldsm4(al[1], aL + 16 * ST * 2 + kbb);
#pragma unroll
            for (int p = 0; p < 4; p++) {
                uint32_t bh[4], bl[4];
                ldsm4(bh, bH + (uint32_t)p * 16 * ST * 2 + kbb);
                ldsm4(bl, bL + (uint32_t)p * 16 * ST * 2 + kbb);
#pragma unroll
                for (int mt = 0; mt < 2; mt++) {
                    mma_bf16(acc[mt][2 * p], ah[mt], bh[0], bh[1]);
                    mma_bf16(acc[mt][2 * p], ah[mt], bl[0], bl[1]);
                    mma_bf16(acc[mt][2 * p], al[mt], bh[0], bh[1]);
                    mma_bf16(acc[mt][2 * p + 1], ah[mt], bh[2], bh[3]);
                    mma_bf16(acc[mt][2 * p + 1], ah[mt], bl[2], bl[3]);
                    mma_bf16(acc[mt][2 * p + 1], al[mt], bh[2], bh[3]);
                }
            }
        }
        buf ^= 1;
    }

    // epilogue
#pragma unroll
    for (int mt = 0; mt < 2; mt++) {
        long long r = row0 + m0 + mt * 16 + gid;
#pragma unroll
        for (int nt = 0; nt < 8; nt++) {
            int c = col0 + n0 + nt * 8 + tig * 2;
            float v0 = acc[mt][nt][0], v1 = acc[mt][nt][1];
            float v2 = acc[mt][nt][2], v3 = acc[mt][nt][3];
            if (Db) {
                float2 d0 = *(const float2*)(Db + r * N + c);
                float2 d1 = *(const float2*)(Db + (r + 8) * N + c);
                v0 += d0.x; v1 += d0.y; v2 += d1.x; v3 += d1.y;
            }
            v0 *= scale; v1 *= scale; v2 *= scale; v3 *= scale;
            if (bias) {
                float2 bb = *(const float2*)(bias + c);
                v0 += bb.x; v1 += bb.y; v2 += bb.x; v3 += bb.y;
            }
            if (doRelu) {
                v0 = fmaxf(v0, 0.f); v1 = fmaxf(v1, 0.f);
                v2 = fmaxf(v2, 0.f); v3 = fmaxf(v3, 0.f);
            }
            *(float2*)(Cb + r * N + c) = make_float2(v0, v1);
            *(float2*)(Cb + (r + 8) * N + c) = make_float2(v2, v3);
            if (CThb) {
                __nv_bfloat16 h0 = __float2bfloat16(v0);
                __nv_bfloat16 h1 = __float2bfloat16(v1);
                __nv_bfloat16 h2_ = __float2bfloat16(v2);
                __nv_bfloat16 h3_ = __float2bfloat16(v3);
                CThb[(long long)c * M + r] = h0;
                CThb[(long long)c * M + r + 8] = h2_;
                CThb[(long long)(c + 1) * M + r] = h1;
                CThb[(long long)(c + 1) * M + r + 8] = h3_;
                CTlb[(long long)c * M + r] = __float2bfloat16(v0 - __bfloat162float(h0));
                CTlb[(long long)c * M + r + 8] = __float2bfloat16(v2 - __bfloat162float(h2_));
                CTlb[(long long)(c + 1) * M + r] = __float2bfloat16(v1 - __bfloat162float(h1));
                CTlb[(long long)(c + 1) * M + r + 8] = __float2bfloat16(v3 - __bfloat162float(h3_));
            }
        }
    }
}

// ---------------------------------------------------------------------------
// split / weight prep kernels
// ---------------------------------------------------------------------------
__global__ void split_x(const float* __restrict__ in, __nv_bfloat16* __restrict__ hi,
                        __nv_bfloat16* __restrict__ lo, long long n4)
{
    long long i = (long long)blockIdx.x * 256 + threadIdx.x;
    if (i >= n4) return;
    float4 v = ((const float4*)in)[i];
    __nv_bfloat16 h0 = __float2bfloat16(v.x), h1 = __float2bfloat16(v.y);
    __nv_bfloat16 h2 = __float2bfloat16(v.z), h3 = __float2bfloat16(v.w);
    __nv_bfloat162 ha, hb, la, lb;
    ha.x = h0; ha.y = h1; hb.x = h2; hb.y = h3;
    la.x = __float2bfloat16(v.x - __bfloat162float(h0));
    la.y = __float2bfloat16(v.y - __bfloat162float(h1));
    lb.x = __float2bfloat16(v.z - __bfloat162float(h2));
    lb.y = __float2bfloat16(v.w - __bfloat162float(h3));
    ((__nv_bfloat162*)hi)[2 * i] = ha; ((__nv_bfloat162*)hi)[2 * i + 1] = hb;
    ((__nv_bfloat162*)lo)[2 * i] = la; ((__nv_bfloat162*)lo)[2 * i + 1] = lb;
}

__global__ void split_w1t(const float* __restrict__ W, __nv_bfloat16* __restrict__ hi,
                          __nv_bfloat16* __restrict__ lo)
{
    int n = blockIdx.x;
    int k = threadIdx.x;
    float v = W[k * HD + n];
    __nv_bfloat16 h = __float2bfloat16(v);
    hi[n * FD + k] = h;
    lo[n * FD + k] = __float2bfloat16(v - __bfloat162float(h));
}

__global__ void foldW2(const float* __restrict__ W2, const float* __restrict__ gam,
                       const float* __restrict__ bet, const float* __restrict__ mean,
                       const float* __restrict__ var,
                       __nv_bfloat16* __restrict__ Wth, __nv_bfloat16* __restrict__ Wtl,
                       float* __restrict__ c2)
{
    int n = blockIdx.x;
    int k = threadIdx.x;
    float sc_ = gam[k] * rsqrtf(var[k] + 1e-5f);
    float sh = bet[k] - mean[k] * sc_;
    float w0 = W2[k * HD + n];
    float w = w0 * sc_;
    __nv_bfloat16 h = __float2bfloat16(w);
    Wth[n * HD + k] = h;
    Wtl[n * HD + k] = __float2bfloat16(w - __bfloat162float(h));
    __shared__ float red[256];
    red[k] = sh * w0;
    __syncthreads();
    for (int s = 128; s > 0; s >>= 1) {
        if (k < s) red[k] += red[k + s];
        __syncthreads();
    }
    if (k == 0) c2[n] = red[0];
}

__global__ void split_w3t(const float* __restrict__ W, __nv_bfloat16* __restrict__ hi,
                          __nv_bfloat16* __restrict__ lo)
{
    int n = blockIdx.x;
    int k = threadIdx.x;
    float v = W[k * HD + n];
    __nv_bfloat16 h = __float2bfloat16(v);
    hi[n * HD + k] = h;
    lo[n * HD + k] = __float2bfloat16(v - __bfloat162float(h));
}

// ---------------------------------------------------------------------------
// Graph-structure kernels (R10 chain)
// ---------------------------------------------------------------------------
__global__ void init_misc(int* cnt, int* rank)
{
    int i = blockIdx.x * 256 + threadIdx.x;
    if (i < NBN) { cnt[i] = 0; rank[i] = -1; }
}

__global__ void count_edges(const int* __restrict__ dst, int* cnt, int E)
{
    int e = blockIdx.x * 256 + threadIdx.x;
    if (e < E) atomicAdd(&cnt[dst[e]], 1);
}

__global__ void scan_a(const int* __restrict__ cnt, int* off, int* bsum)
{
    __shared__ int sh[256];
    int b = blockIdx.x, t = threadIdx.x;
    int v = cnt[b * 256 + t];
    sh[t] = v;
    __syncthreads();
    for (int d = 1; d < 256; d <<= 1) {
        int u = (t >= d) ? sh[t - d] : 0;
        __syncthreads();
        sh[t] += u;
        __syncthreads();
    }
    off[b * 256 + t] = sh[t] - v;
    if (t == 255) bsum[b] = sh[255];
}

// merged scan_b+scan_c: each block locally scans bsum (256 ints), then applies
__global__ void scan_c(int* off, int* pos, const int* __restrict__ bsum,
                       const int* __restrict__ cnt, float* dinv, int E)
{
    __shared__ int sh[256];
    int b = blockIdx.x, t = threadIdx.x;
    int v = bsum[t];
    sh[t] = v;
    __syncthreads();
    for (int d = 1; d < 256; d <<= 1) {
        int u = (t >= d) ? sh[t - d] : 0;
        __syncthreads();
        sh[t] += u;
        __syncthreads();
    }
    // exclusive prefix of bsum for this block
    int bofs = (b == 0) ? 0 : sh[b - 1];
    __syncthreads();
    int i = b * 256 + t;
    int o = off[i] + bofs;
    off[i] = o;
    pos[i] = o;
    dinv[i] = rsqrtf((float)(cnt[i] + 1));
    if (i == NBN - 1) off[NBN] = E;
}

__global__ void scatter_edges(const int* __restrict__ src, const int* __restrict__ dst,
                              int* pos, int* csr, int E)
{
    int e = blockIdx.x * 256 + threadIdx.x;
    if (e < E) {
        int p = atomicAdd(&pos[dst[e]], 1);
        csr[p] = src[e];
    }
}

__global__ void sort_buckets(int* csr, const int* __restrict__ off)
{
    int i = blockIdx.x * 256 + threadIdx.x;
    if (i >= NBN) return;
    int a = off[i], b = off[i + 1];
    for (int p = a + 1; p < b; p++) {
        int v = csr[p];
        int q = p - 1;
        while (q >= a && csr[q] > v) { csr[q + 1] = csr[q]; q--; }
        csr[q + 1] = v;
    }
}

__global__ __launch_bounds__(256)
void gcn_agg(const float4* __restrict__ xw4, const int* __restrict__ off,
             const int* __restrict__ csr, const float* __restrict__ dinv,
             const float4* __restrict__ b1_4, float4* __restrict__ h4)
{
    int g = threadIdx.x >> 6;
    int t = threadIdx.x & 63;
    int i = blockIdx.x * 4 + g;
    float di = dinv[i];
    float4 a = xw4[(long long)i * 64 + t];
    float w0 = di * di;
    float4 acc = make_float4(a.x * w0, a.y * w0, a.z * w0, a.w * w0);
    float4 acc2 = make_float4(0.f, 0.f, 0.f, 0.f);
    int e0 = off[i], e1 = off[i + 1];
    int e = e0;
    for (; e + 1 < e1; e += 2) {
        int s0 = csr[e], s1 = csr[e + 1];
        float wa = dinv[s0] * di, wb = dinv[s1] * di;
        float4 v0 = xw4[(long long)s0 * 64 + t];
        float4 v1 = xw4[(long long)s1 * 64 + t];
        acc.x += v0.x * wa; acc.y += v0.y * wa; acc.z += v0.z * wa; acc.w += v0.w * wa;
        acc2.x += v1.x * wb; acc2.y += v1.y * wb; acc2.z += v1.z * wb; acc2.w += v1.w * wb;
    }
    if (e < e1) {
        int s0 = csr[e];
        float wa = dinv[s0] * di;
        float4 v0 = xw4[(long long)s0 * 64 + t];
        acc.x += v0.x * wa; acc.y += v0.y * wa; acc.z += v0.z * wa; acc.w += v0.w * wa;
    }
    acc.x += acc2.x; acc.y += acc2.y; acc.z += acc2.z; acc.w += acc2.w;
    float4 bb = b1_4[t];
    acc.x = fmaxf(acc.x + bb.x, 0.f);
    acc.y = fmaxf(acc.y + bb.y, 0.f);
    acc.z = fmaxf(acc.z + bb.z, 0.f);
    acc.w = fmaxf(acc.w + bb.w, 0.f);
    h4[(long long)i * 64 + t] = acc;
}

__global__ __launch_bounds__(256)
void pool_score(const float4* __restrict__ h4, const int* __restrict__ off,
                const int* __restrict__ csr, const int* __restrict__ cnt,
                float* __restrict__ score)
{
    __shared__ float red[4][2];
    int g = threadIdx.x >> 6;
    int t = threadIdx.x & 63;
    int i = blockIdx.x * 4 + g;
    float4 acc = make_float4(0.f, 0.f, 0.f, 0.f);
    float4 acc2 = make_float4(0.f, 0.f, 0.f, 0.f);
    int e0 = off[i], e1 = off[i + 1];
    int e = e0;
    for (; e + 1 < e1; e += 2) {
        int s0 = csr[e], s1 = csr[e + 1];
        float4 v0 = h4[(long long)s0 * 64 + t];
        float4 v1 = h4[(long long)s1 * 64 + t];
        acc.x += v0.x; acc.y += v0.y; acc.z += v0.z; acc.w += v0.w;
        acc2.x += v1.x; acc2.y += v1.y; acc2.z += v1.z; acc2.w += v1.w;
    }
    if (e < e1) {
        int s0 = csr[e];
        float4 v0 = h4[(long long)s0 * 64 + t];
        acc.x += v0.x; acc.y += v0.y; acc.z += v0.z; acc.w += v0.w;
    }
    acc.x += acc2.x; acc.y += acc2.y; acc.z += acc2.z; acc.w += acc2.w;
    float degp = fmaxf((float)cnt[i], 1.f);
    float4 hh = h4[(long long)i * 64 + t];
    float s = fabsf(hh.x - acc.x / degp) + fabsf(hh.y - acc.y / degp)
            + fabsf(hh.z - acc.z / degp) + fabsf(hh.w - acc.w / degp);
#pragma unroll
    for (int o = 16; o > 0; o >>= 1)
        s += __shfl_down_sync(0xffffffff, s, o);
    if ((t & 31) == 0) red[g][t >> 5] = s;
    __syncthreads();
    if (t == 0) score[i] = red[g][0] + red[g][1];
}

__global__ void topk_kernel(const float* __restrict__ score, int n, int kout,
                            int* outidx, int* rank)
{
    int g = blockIdx.x;
    int t = threadIdx.x;
    __shared__ float s[512];
    __shared__ int id[512];
    s[t] = score[g * n + t];
    id[t] = t;
    __syncthreads();
    for (int k = 2; k <= n; k <<= 1)
        for (int j = k >> 1; j > 0; j >>= 1) {
            int p = t ^ j;
            if (p > t) {
                float s1 = s[t], s2 = s[p];
                int i1 = id[t], i2 = id[p];
                bool lt12 = (s1 > s2) || (s1 == s2 && i1 < i2);
                bool up = ((t & k) == 0);
                if (up ? !lt12 : lt12) { s[t] = s2; s[p] = s1; id[t] = i2; id[p] = i1; }
            }
            __syncthreads();
        }
    if (t < kout) {
        if (rank) {
            int node = g * n + id[t];
            outidx[g * kout + t] = node;
            rank[node] = t;
        } else {
            outidx[g * kout + t] = id[t];
        }
    }
}

__global__ void gather_rows_ef(const float* __restrict__ h, const int* __restrict__ perm,
                               const float* __restrict__ att,
                               float* __restrict__ h1, __nv_bfloat16* __restrict__ h1h,
                               __nv_bfloat16* __restrict__ h1l, float* __restrict__ ef)
{
    long long n = blockIdx.x;
    int c = threadIdx.x;
    float v = h[(long long)perm[n] * HD + c];
    h1[n * HD + c] = v;
    __nv_bfloat16 hh = __float2bfloat16(v);
    h1h[n * HD + c] = hh;
    h1l[n * HD + c] = __float2bfloat16(v - __bfloat162float(hh));
    __shared__ float re[256], rf[256];
    re[c] = v * att[2 * c];
    rf[c] = v * att[2 * c + 1];
    __syncthreads();
    for (int s = 128; s > 0; s >>= 1) {
        if (c < s) { re[c] += re[c + s]; rf[c] += rf[c + s]; }
        __syncthreads();
    }
    if (c == 0) { ef[2 * n] = re[0]; ef[2 * n + 1] = rf[0]; }
}

__global__ void zero_c(uint8_t* p, long long n16)
{
    long long i = (long long)blockIdx.x * 256 + threadIdx.x;
    if (i < n16) ((uint4*)p)[i] = make_uint4(0, 0, 0, 0);
}

__global__ void buildA1(const int* __restrict__ src, const int* __restrict__ dst,
                        const int* __restrict__ rank, uint8_t* __restrict__ A1c, int E)
{
    int e = blockIdx.x * 256 + threadIdx.x;
    if (e >= E) return;
    int s = src[e], d = dst[e];
    int ns = rank[s], nd = rank[d];
    if (ns >= 0 && nd >= 0) {
        int g = s >> 9;
        A1c[(((long long)g * KP1 + ns) * KP1) + nd] = 1;
    }
}

// stage-1 softmax: A_ind from uint8; writes fp32 adj + bf16 splits
__global__ void struct_softmax1(const uint8_t* __restrict__ Ac,
                                const float* __restrict__ ef,
                                float* __restrict__ Aout,
                                __nv_bfloat16* __restrict__ Ah,
                                __nv_bfloat16* __restrict__ Al)
{
    int row = blockIdx.x;
    int j = threadIdx.x;
    int b = row >> 8;                    // / KP1
    long long base = (long long)row * KP1;
    float logit = ef[2 * row] + ef[2 * ((b << 8) + j) + 1] + (float)Ac[base + j];
    __shared__ float red[256];
    red[j] = logit;
    __syncthreads();
    for (int s = 128; s > 0; s >>= 1) {
        if (j < s) red[j] = fmaxf(red[j], red[j + s]);
        __syncthreads();
    }
    float m = red[0];
    __syncthreads();
    float e = expf(logit - m);
    red[j] = e;
    __syncthreads();
    for (int s = 128; s > 0; s >>= 1) {
        if (j < s) red[j] += red[j + s];
        __syncthreads();
    }
    float v = e / red[0];
    Aout[base + j] = v;
    __nv_bfloat16 hh = __float2bfloat16(v);
    Ah[base + j] = hh;
    Al[base + j] = __float2bfloat16(v - __bfloat162float(hh));
}

// stage-2 softmax fused with A2 gather: A_ind = adj1[b][ri][rj]; only bf16 out
__global__ void struct_softmax2(const float* __restrict__ adj1,
                                const int* __restrict__ idx2,
                                const float* __restrict__ ef,
                                __nv_bfloat16* __restrict__ Ah,
                                __nv_bfloat16* __restrict__ Al)
{
    int row = blockIdx.x;                // b*KP2 + i
    int j = threadIdx.x;                 // 0..KP2-1
    int b = row >> 7;
    int ri = idx2[row];
    int rj = idx2[(b << 7) + j];
    float aind = adj1[((long long)b * KP1 + ri) * KP1 + rj];
    float logit = ef[2 * row] + ef[2 * ((b << 7) + j) + 1] + aind;
    __shared__ float red[128];
    red[j] = logit;
    __syncthreads();
    for (int s = 64; s > 0; s >>= 1) {
        if (j < s) red[j] = fmaxf(red[j], red[j + s]);
        __syncthreads();
    }
    float m = red[0];
    __syncthreads();
    float e = expf(logit - m);
    red[j] = e;
    __syncthreads();
    for (int s = 64; s > 0; s >>= 1) {
        if (j < s) red[j] += red[j + s];
        __syncthreads();
    }
    float v = e / red[0];
    long long base = (long long)row * KP2;
    __nv_bfloat16 hh = __float2bfloat16(v);
    Ah[base + j] = hh;
    Al[base + j] = __float2bfloat16(v - __bfloat162float(hh));
}

__global__ void readout_k(const float* __restrict__ X, float* __restrict__ out, int Kd)
{
    __shared__ float smx[4][256], ssm[4][256];
    int b = blockIdx.x;
    int part = threadIdx.x >> 8;
    int c = threadIdx.x & 255;
    int kq = Kd >> 2;
    int k0 = part * kq, k1 = k0 + kq;
    float mx = -3.4e38f, sm = 0.f;
    for (int k = k0; k < k1; k++) {
        float v = X[((long long)b * Kd + k) * HD + c];
        mx = fmaxf(mx, v);
        sm += v;
    }
    smx[part][c] = mx;
    ssm[part][c] = sm;
    __syncthreads();
    if (part == 0) {
        float m = fmaxf(fmaxf(smx[0][c], smx[1][c]), fmaxf(smx[2][c], smx[3][c]));
        float s = ssm[0][c] + ssm[1][c] + ssm[2][c] + ssm[3][c];
        out[b * 2 * HD + c] = m;
        out[b * 2 * HD + HD + c] = s / (float)Kd;
    }
}

__global__ void score_dense(const float* __restrict__ X, const float* __restrict__ P,
                            float* __restrict__ sc)
{
    int row = blockIdx.x;
    int c = threadIdx.x;
    __shared__ float red[256];
    long long base = (long long)row * HD;
    red[c] = fabsf(X[base + c] - P[base + c]);
    __syncthreads();
    for (int s = 128; s > 0; s >>= 1) {
        if (c < s) red[c] += red[c + s];
        __syncthreads();
    }
    if (c == 0) sc[row] = red[0];
}

__global__ void gather_h2sel_ef(const float* __restrict__ h2, const int* __restrict__ idx2,
                                const float* __restrict__ att,
                                float* __restrict__ h2sel, __nv_bfloat16* __restrict__ sh,
                                __nv_bfloat16* __restrict__ sl, float* __restrict__ ef)
{
    int n = blockIdx.x;
    int c = threadIdx.x;
    int b = n >> 7;
    int row = idx2[n];
    float v = h2[((long long)b * KP1 + row) * HD + c];
    h2sel[(long long)n * HD + c] = v;
    __nv_bfloat16 hh = __float2bfloat16(v);
    sh[(long long)n * HD + c] = hh;
    sl[(long long)n * HD + c] = __float2bfloat16(v - __bfloat162float(hh));
    __shared__ float re[256], rf[256];
    re[c] = v * att[2 * c];
    rf[c] = v * att[2 * c + 1];
    __syncthreads();
    for (int s = 128; s > 0; s >>= 1) {
        if (c < s) { re[c] += re[c + s]; rf[c] += rf[c + s]; }
        __syncthreads();
    }
    if (c == 0) { ef[2 * n] = re[0]; ef[2 * n + 1] = rf[0]; }
}

__global__ void head(const float* __restrict__ x1, const float* __restrict__ x2,
                     const float* __restrict__ x3,
                     const float* __restrict__ l1w, const float* __restrict__ l1b,
                     const float* __restrict__ l2w, const float* __restrict__ l2b,
                     const float* __restrict__ l3w, const float* __restrict__ l3b,
                     float* __restrict__ out_x, float* __restrict__ out_lp)
{
    int b = blockIdx.x;
    int t = threadIdx.x;
    __shared__ float g[512], g1[256], g2[128], lg[10];
    for (int i = t; i < 512; i += 256) {
        g[i] = fmaxf(x1[b * 512 + i], 0.f) + fmaxf(x2[b * 512 + i], 0.f) +
               fmaxf(x3[b * 512 + i], 0.f);
    }
    __syncthreads();
    {
        float a = 0.f;
        for (int c = 0; c < 512; c++) a += g[c] * l1w[c * 256 + t];
        g1[t] = fmaxf(a + l1b[t], 0.f);
    }
    __syncthreads();
    if (t < 128) {
        float a = 0.f;
        for (int c = 0; c < 256; c++) a += g1[c] * l2w[c * 128 + t];
        float v = fmaxf(a + l2b[t], 0.f);
        g2[t] = v;
        out_x[b * 128 + t] = v;
    }
    __syncthreads();
    if (t < 10) {
        float a = 0.f;
        for (int c = 0; c < 128; c++) a += g2[c] * l3w[c * 10 + t];
        lg[t] = a + l3b[t];
    }
    __syncthreads();
    if (t == 0) {
        float m = -3.4e38f;
        for (int i = 0; i < 10; i++) m = fmaxf(m, lg[i]);
        float s = 0.f;
        for (int i = 0; i < 10; i++) s += expf(lg[i] - m);
        float lse = m + logf(s);
        for (int i = 0; i < 10; i++) out_lp[b * 10 + i] = lg[i] - lse;
    }
}

// ---------------------------------------------------------------------------
// Launch
// ---------------------------------------------------------------------------
extern "C" void kernel_launch(void* const* d_in, const int* in_sizes, int n_in,
                              void* d_out, int out_size)
{
    void* sp = nullptr;
    cudaGetSymbolAddress(&sp, S);
    Scratch* sc = (Scratch*)sp;

    const float* x    = (const float*)d_in[0];
    const int*   ei   = (const int*)d_in[1];
    const float* W1   = (const float*)d_in[3];
    const float* b1   = (const float*)d_in[4];
    const float* W2   = (const float*)d_in[5];
    const float* b2   = (const float*)d_in[6];
    const float* W3   = (const float*)d_in[7];
    const float* b3   = (const float*)d_in[8];
    const float* att1 = (const float*)d_in[9];
    const float* att2 = (const float*)d_in[10];
    const float* bng  = (const float*)d_in[11];
    const float* bnb  = (const float*)d_in[12];
    const float* bnm  = (const float*)d_in[13];
    const float* bnv  = (const float*)d_in[14];
    const float* l1w  = (const float*)d_in[15];
    const float* l1b  = (const float*)d_in[16];
    const float* l2w  = (const float*)d_in[17];
    const float* l2b  = (const float*)d_in[18];
    const float* l3w  = (const float*)d_in[19];
    const float* l3b  = (const float*)d_in[20];

    int E = in_sizes[1] / 2;
    const int* src = ei;
    const int* dst = ei + E;

    float* out    = (float*)d_out;
    float* out_x  = out;                        // [128,128]
    float* out_lp = out + BGR * 128;            // [128,10]
    float* h      = out + BGR * 128 + BGR * 10; // x__ = [65536,256]

    cudaFuncSetAttribute(bmma, cudaFuncAttributeMaxDynamicSharedMemorySize,
                         BMMA_SMEM);

    // --- prep + big GEMM (bmma is 4th launch -> profiled) ---
    split_x<<<32768, 256>>>(x, sc->xh, sc->xl, (long long)NBN * FD / 4);
    split_w1t<<<HD, FD>>>(W1, sc->w1th, sc->w1tl);
    foldW2<<<HD, HD>>>(W2, bng, bnb, bnm, bnv, sc->w2fth, sc->w2ftl, sc->c2);
    bmma<<<dim3(HD / 128, NBN / 128, 1), 256, BMMA_SMEM>>>(
        sc->xh, sc->xl, sc->w1th, sc->w1tl, nullptr, sc->xw, nullptr, nullptr,
        NBN, HD, FD, 0, 0, 0, 0, 0, nullptr, 1.0f, 0);
    split_w3t<<<HD, HD>>>(W3, sc->w3th, sc->w3tl);

    // --- stage 1: sparse GCN ---
    init_misc<<<NBN / 256, 256>>>(sc->cnt, sc->rank);
    count_edges<<<(E + 255) / 256, 256>>>(dst, sc->cnt, E);
    scan_a<<<256, 256>>>(sc->cnt, sc->off, sc->bsum);
    scan_c<<<256, 256>>>(sc->off, sc->pos, sc->bsum, sc->cnt, sc->dinv, E);
    scatter_edges<<<(E + 255) / 256, 256>>>(src, dst, sc->pos, sc->csr, E);
    sort_buckets<<<NBN / 256, 256>>>(sc->csr, sc->off);
    gcn_agg<<<NBN / 4, 256>>>((const float4*)sc->xw, sc->off, sc->csr, sc->dinv,
                              (const float4*)b1, (float4*)h);

    // --- stage 1 pool (sparse) ---
    pool_score<<<NBN / 4, 256>>>((const float4*)h, sc->off, sc->csr, sc->cnt,
                                 sc->score);
    topk_kernel<<<BGR, NN>>>(sc->score, NN, KP1, sc->perm, sc->rank);
    gather_rows_ef<<<BGR * KP1, 256>>>(h, sc->perm, att1, sc->h1,
                                       sc->h1h, sc->h1l, sc->ef1);
    zero_c<<<(int)(((long long)BGR * KP1 * KP1 / 16 + 255) / 256), 256>>>(
        sc->A1c, (long long)BGR * KP1 * KP1 / 16);
    buildA1<<<(E + 255) / 256, 256>>>(src, dst, sc->rank, sc->A1c, E);
    struct_softmax1<<<BGR * KP1, KP1>>>(sc->A1c, sc->ef1, sc->A1,
                                        sc->A1h, sc->A1l);
    readout_k<<<BGR, 1024>>>(sc->h1, sc->x1, KP1);

    // --- stage 2: BN folded + dense GCN (An = (adj+I)/2 exactly) ---
    bmma<<<dim3(2, 2, BGR), 256, BMMA_SMEM>>>(
        sc->h1h, sc->h1l, sc->w2fth, sc->w2ftl, nullptr, sc->xw2,
        sc->xw2th, sc->xw2tl,
        KP1, HD, HD, (long long)KP1 * HD, 0, 0, (long long)KP1 * HD,
        (long long)KP1 * HD, sc->c2, 1.0f, 0);
    bmma<<<dim3(2, 2, BGR), 256, BMMA_SMEM>>>(
        sc->A1h, sc->A1l, sc->xw2th, sc->xw2tl, sc->xw2, sc->h2,
        sc->h2th, sc->h2tl,
        KP1, HD, KP1, (long long)KP1 * KP1, (long long)KP1 * HD,
        (long long)KP1 * HD, (long long)KP1 * HD, (long long)KP1 * HD,
        b2, 0.5f, 1);
    bmma<<<dim3(2, 2, BGR), 256, BMMA_SMEM>>>(
        sc->A1h, sc->A1l, sc->h2th, sc->h2tl, nullptr, sc->prop, nullptr, nullptr,
        KP1, HD, KP1, (long long)KP1 * KP1, (long long)KP1 * HD, 0,
        (long long)KP1 * HD, 0, nullptr, 1.0f, 0);
    score_dense<<<BGR * KP1, 256>>>(sc->h2, sc->prop, sc->score2);
    topk_kernel<<<BGR, KP1>>>(sc->score2, KP1, KP2, sc->idx2, nullptr);
    gather_h2sel_ef<<<BGR * KP2, 256>>>(sc->h2, sc->idx2, att2, sc->h2sel,
                                        sc->h2selh, sc->h2sell, sc->ef2);
    struct_softmax2<<<BGR * KP2, KP2>>>(sc->A1, sc->idx2, sc->ef2,
                                        sc->A2h, sc->A2l);
    readout_k<<<BGR, 1024>>>(sc->h2sel, sc->x2, KP2);

    // --- stage 3: dense GCN ---
    bmma<<<dim3(2, 1, BGR), 256, BMMA_SMEM>>>(
        sc->h2selh, sc->h2sell, sc->w3th, sc->w3tl, nullptr, sc->xw3,
        sc->xw3th, sc->xw3tl,
        KP2, HD, HD, (long long)KP2 * HD, 0, 0, (long long)KP2 * HD,
        (long long)KP2 * HD, nullptr, 1.0f, 0);
    bmma<<<dim3(2, 1, BGR), 256, BMMA_SMEM>>>(
        sc->A2h, sc->A2l, sc->xw3th, sc->xw3tl, sc->xw3, sc->h3, nullptr, nullptr,
        KP2, HD, KP2, (long long)KP2 * KP2, (long long)KP2 * HD,
        (long long)KP2 * HD, (long long)KP2 * HD, 0, b3, 0.5f, 1);
    readout_k<<<BGR, 1024>>>(sc->h3, sc->x3, KP2);

    // --- head ---
    head<<<BGR, 256>>>(sc->x1, sc->x2, sc->x3, l1w, l1b, l2w, l2b, l3w, l3b,
                       out_x, out_lp);
}

// round 13
// speedup vs baseline: 1.1952x; 1.0275x over previous
#include <cuda_runtime.h>
#include <cuda_bf16.h>
#include <math.h>
#include <stdint.h>

// Problem constants
#define NBN   65536      // B*N nodes
#define BGR   128        // graphs
#define NN    512        // nodes per graph
#define FD    512        // input features
#define HD    256        // hidden
#define KP1   256        // K1
#define KP2   128        // K2
#define EDGES 1048576    // B*EPG

typedef unsigned long long ull;

__device__ __forceinline__ void mma_bf16(float* c, const uint32_t* a,
                                         uint32_t b0, uint32_t b1)
{
    asm volatile(
        "mma.sync.aligned.m16n8k16.row.col.f32.bf16.bf16.f32 "
        "{%0,%1,%2,%3}, {%4,%5,%6,%7}, {%8,%9}, {%0,%1,%2,%3};"
        : "+f"(c[0]), "+f"(c[1]), "+f"(c[2]), "+f"(c[3])
        : "r"(a[0]), "r"(a[1]), "r"(a[2]), "r"(a[3]), "r"(b0), "r"(b1));
}

__device__ __forceinline__ void cp16(uint32_t dst, const void* src)
{
    asm volatile("cp.async.cg.shared.global [%0], [%1], 16;"
                 :: "r"(dst), "l"(src));
}

__device__ __forceinline__ void ldsm4(uint32_t* r, uint32_t a)
{
    asm volatile("ldmatrix.sync.aligned.m8n8.x4.shared.b16 {%0,%1,%2,%3}, [%4];"
                 : "=r"(r[0]), "=r"(r[1]), "=r"(r[2]), "=r"(r[3]) : "r"(a));
}

// ---------------------------------------------------------------------------
// Scratch
// ---------------------------------------------------------------------------
struct Scratch {
    alignas(16) float xw[(long long)NBN * HD];        // x @ W1
    alignas(16) int   cnt[NBN];
    alignas(16) int   off[NBN + 4];
    alignas(16) int   pos[NBN];
    alignas(16) int   csr[EDGES];
    alignas(16) int   bsum[256];
    alignas(16) float dinv[NBN];
    alignas(16) float score[NBN];
    alignas(16) int   perm[BGR * KP1];
    alignas(16) int   rank[NBN];
    alignas(16) float h1[(long long)BGR * KP1 * HD];
    alignas(16) uint8_t A1c[(long long)BGR * KP1 * KP1]; // 0/1 A_ind
    alignas(16) float A1[(long long)BGR * KP1 * KP1];    // adj1 (softmax out)
    alignas(16) float ef1[BGR * KP1 * 2];
    alignas(16) float x1[BGR * 2 * HD];
    alignas(16) float c2[HD];
    alignas(16) float xw2[(long long)BGR * KP1 * HD];
    alignas(16) float h2[(long long)BGR * KP1 * HD];
    alignas(16) float prop[(long long)BGR * KP1 * HD];
    alignas(16) float score2[BGR * KP1];
    alignas(16) int   idx2[BGR * KP2];
    alignas(16) float h2sel[(long long)BGR * KP2 * HD];
    alignas(16) float ef2[BGR * KP2 * 2];
    alignas(16) float x2[BGR * 2 * HD];
    alignas(16) float xw3[(long long)BGR * KP2 * HD];
    alignas(16) float h3[(long long)BGR * KP2 * HD];
    alignas(16) float x3[BGR * 2 * HD];
    // bf16 split weights (transposed [n][k])
    alignas(16) __nv_bfloat16 w1th[HD * FD];
    alignas(16) __nv_bfloat16 w1tl[HD * FD];
    alignas(16) __nv_bfloat16 w2fth[HD * HD];
    alignas(16) __nv_bfloat16 w2ftl[HD * HD];
    alignas(16) __nv_bfloat16 w3th[HD * HD];
    alignas(16) __nv_bfloat16 w3tl[HD * HD];
    // bf16 split A operands (row-major, emitted by producers)
    alignas(16) __nv_bfloat16 xh[(long long)NBN * FD];
    alignas(16) __nv_bfloat16 xl[(long long)NBN * FD];
    alignas(16) __nv_bfloat16 h1h[(long long)BGR * KP1 * HD];
    alignas(16) __nv_bfloat16 h1l[(long long)BGR * KP1 * HD];
    alignas(16) __nv_bfloat16 A1h[(long long)BGR * KP1 * KP1];
    alignas(16) __nv_bfloat16 A1l[(long long)BGR * KP1 * KP1];
    alignas(16) __nv_bfloat16 h2selh[(long long)BGR * KP2 * HD];
    alignas(16) __nv_bfloat16 h2sell[(long long)BGR * KP2 * HD];
    alignas(16) __nv_bfloat16 A2h[(long long)BGR * KP2 * KP2];
    alignas(16) __nv_bfloat16 A2l[(long long)BGR * KP2 * KP2];
    // bf16 split transposed activations (produced by bmma epilogue)
    alignas(16) __nv_bfloat16 xw2th[(long long)BGR * HD * KP1];
    alignas(16) __nv_bfloat16 xw2tl[(long long)BGR * HD * KP1];
    alignas(16) __nv_bfloat16 h2th[(long long)BGR * HD * KP1];
    alignas(16) __nv_bfloat16 h2tl[(long long)BGR * HD * KP1];
    alignas(16) __nv_bfloat16 xw3th[(long long)BGR * HD * KP2];
    alignas(16) __nv_bfloat16 xw3tl[(long long)BGR * HD * KP2];
};
__device__ Scratch S;

// ---------------------------------------------------------------------------
// bmma: pipelined split-bf16 HMMA GEMM, single __syncthreads per K-chunk.
// CT outputs staged through smem transpose for coalesced stores.
// ---------------------------------------------------------------------------
#define ST  40
#define SZB (128 * ST)
#define BMMA_SMEM (2 * 4 * SZB * 2)
#define TPAD 136   // transpose row stride (bf16)

__global__ __launch_bounds__(256, 2)
void bmma(const __nv_bfloat16* __restrict__ Ah, const __nv_bfloat16* __restrict__ Al,
          const __nv_bfloat16* __restrict__ Bh, const __nv_bfloat16* __restrict__ Bl,
          const float* __restrict__ D, float* __restrict__ C,
          __nv_bfloat16* __restrict__ CTh, __nv_bfloat16* __restrict__ CTl,
          int M, int N, int K,
          long long sA, long long sB, long long sD, long long sC, long long sCT,
          const float* __restrict__ bias, float scale, int doRelu)
{
    extern __shared__ __nv_bfloat16 dyn[];
    uint32_t smem_base = (uint32_t)__cvta_generic_to_shared(dyn);

    long long z = blockIdx.z;
    const __nv_bfloat16* Ahb = Ah + z * sA;
    const __nv_bfloat16* Alb = Al + z * sA;
    const __nv_bfloat16* Bhb = Bh + z * sB;
    const __nv_bfloat16* Blb = Bl + z * sB;
    const float* Db = D ? (D + z * sD) : nullptr;
    float* Cb = C + z * sC;
    __nv_bfloat16* CThb = CTh ? (CTh + z * sCT) : nullptr;
    __nv_bfloat16* CTlb = CTl ? (CTl + z * sCT) : nullptr;

    int tid = threadIdx.x;
    int warp = tid >> 5, lane = tid & 31;
    int gid = lane >> 2, tig = lane & 3;
    int wm = warp >> 1, wn = warp & 1;
    int m0 = wm * 32, n0 = wn * 64;
    int row0 = blockIdx.y * 128, col0 = blockIdx.x * 128;

    uint32_t aoff = (uint32_t)((m0 + (lane & 15)) * ST + (lane >> 4) * 8) * 2;
    uint32_t boff = (uint32_t)((n0 + (lane >> 4) * 8 + (lane & 7)) * ST
                               + ((lane >> 3) & 1) * 8) * 2;

    float acc[2][8][4];
#pragma unroll
    for (int mt = 0; mt < 2; mt++)
#pragma unroll
        for (int nt = 0; nt < 8; nt++)
#pragma unroll
            for (int i = 0; i < 4; i++) acc[mt][nt][i] = 0.f;

    auto copy_chunk = [&](int buf, int kc) {
        uint32_t base = smem_base + (uint32_t)buf * 4 * SZB * 2;
#pragma unroll
        for (int it = 0; it < 2; it++) {
            int idx = it * 256 + tid;
            int row = idx >> 2, c8 = (idx & 3) << 3;
            uint32_t so = (uint32_t)(row * ST + c8) * 2;
            long long ga = (long long)(row0 + row) * K + kc + c8;
            long long gb = (long long)(col0 + row) * K + kc + c8;
            cp16(base + 0 * SZB * 2 + so, Ahb + ga);
            cp16(base + 1 * SZB * 2 + so, Alb + ga);
            cp16(base + 2 * SZB * 2 + so, Bhb + gb);
            cp16(base + 3 * SZB * 2 + so, Blb + gb);
        }
        asm volatile("cp.async.commit_group;" ::: "memory");
    };

    copy_chunk(0, 0);
    int buf = 0;
    for (int kc = 0; kc < K; kc += 32) {
        asm volatile("cp.async.wait_group 0;" ::: "memory");
        __syncthreads();
        if (kc + 32 < K) copy_chunk(buf ^ 1, kc + 32);

        uint32_t bufb = smem_base + (uint32_t)buf * 4 * SZB * 2;
        uint32_t aH = bufb + aoff;
        uint32_t aL = bufb + SZB * 2 + aoff;
        uint32_t bH = bufb + 2 * SZB * 2 + boff;
        uint32_t bL = bufb + 3 * SZB * 2 + boff;

#pragma unroll
        for (int ks = 0; ks < 2; ks++) {
            uint32_t kbb = (uint32_t)ks * 32;
            uint32_t ah[2][4], al[2][4];
            ldsm4(ah[0], aH + kbb);
            ldsm4(ah[1], aH + 16 * ST * 2 + kbb);
            ldsm4(al[0], aL + kbb);
            ldsm4(al[1], aL + 16 * ST * 2 + kbb);
#pragma unroll
            for (int p = 0; p < 4; p++) {
                uint32_t bh[4], bl[4];
                ldsm4(bh, bH + (uint32_t)p * 16 * ST * 2 + kbb);
                ldsm4(bl, bL + (uint32_t)p * 16 * ST * 2 + kbb);
#pragma unroll
                for (int mt = 0; mt < 2; mt++) {
                    mma_bf16(acc[mt][2 * p], ah[mt], bh[0], bh[1]);
                    mma_bf16(acc[mt][2 * p], ah[mt], bl[0], bl[1]);
                    mma_bf16(acc[mt][2 * p], al[mt], bh[0], bh[1]);
                    mma_bf16(acc[mt][2 * p + 1], ah[mt], bh[2], bh[3]);
                    mma_bf16(acc[mt][2 * p + 1], ah[mt], bl[2], bl[3]);
                    mma_bf16(acc[mt][2 * p + 1], al[mt], bh[2], bh[3]);
                }
            }
        }
        buf ^= 1;
    }

    // epilogue (smem buffers are dead after this barrier)
    __syncthreads();
    __nv_bfloat16* sTh = dyn;                 // [128][TPAD]
    __nv_bfloat16* sTl = dyn + 128 * TPAD;

#pragma unroll
    for (int mt = 0; mt < 2; mt++) {
        int rl = m0 + mt * 16 + gid;
        long long r = row0 + rl;
#pragma unroll
        for (int nt = 0; nt < 8; nt++) {
            int cl = n0 + nt * 8 + tig * 2;
            int c = col0 + cl;
            float v0 = acc[mt][nt][0], v1 = acc[mt][nt][1];
            float v2 = acc[mt][nt][2], v3 = acc[mt][nt][3];
            if (Db) {
                float2 d0 = *(const float2*)(Db + r * N + c);
                float2 d1 = *(const float2*)(Db + (r + 8) * N + c);
                v0 += d0.x; v1 += d0.y; v2 += d1.x; v3 += d1.y;
            }
            v0 *= scale; v1 *= scale; v2 *= scale; v3 *= scale;
            if (bias) {
                float2 bb = *(const float2*)(bias + c);
                v0 += bb.x; v1 += bb.y; v2 += bb.x; v3 += bb.y;
            }
            if (doRelu) {
                v0 = fmaxf(v0, 0.f); v1 = fmaxf(v1, 0.f);
                v2 = fmaxf(v2, 0.f); v3 = fmaxf(v3, 0.f);
            }
            *(float2*)(Cb + r * N + c) = make_float2(v0, v1);
            *(float2*)(Cb + (r + 8) * N + c) = make_float2(v2, v3);
            if (CThb) {
                __nv_bfloat16 h0 = __float2bfloat16(v0);
                __nv_bfloat16 h1 = __float2bfloat16(v1);
                __nv_bfloat16 h2_ = __float2bfloat16(v2);
                __nv_bfloat16 h3_ = __float2bfloat16(v3);
                sTh[cl * TPAD + rl] = h0;
                sTh[cl * TPAD + rl + 8] = h2_;
                sTh[(cl + 1) * TPAD + rl] = h1;
                sTh[(cl + 1) * TPAD + rl + 8] = h3_;
                sTl[cl * TPAD + rl] = __float2bfloat16(v0 - __bfloat162float(h0));
                sTl[cl * TPAD + rl + 8] = __float2bfloat16(v2 - __bfloat162float(h2_));
                sTl[(cl + 1) * TPAD + rl] = __float2bfloat16(v1 - __bfloat162float(h1));
                sTl[(cl + 1) * TPAD + rl + 8] = __float2bfloat16(v3 - __bfloat162float(h3_));
            }
        }
    }
    if (CThb) {
        __syncthreads();
        // coalesced bulk copy: 128 c-rows x 128 r (16B vectors)
#pragma unroll
        for (int it = 0; it < 8; it++) {
            int i = it * 256 + tid;            // 0..2047
            int cl = i >> 4, v8 = (i & 15) << 3;
            uint4 vh = *(const uint4*)&sTh[cl * TPAD + v8];
            uint4 vl = *(const uint4*)&sTl[cl * TPAD + v8];
            long long go = (long long)(col0 + cl) * M + row0 + v8;
            *(uint4*)(CThb + go) = vh;
            *(uint4*)(CTlb + go) = vl;
        }
    }
}

// ---------------------------------------------------------------------------
// split / weight prep kernels
// ---------------------------------------------------------------------------
__global__ void split_x(const float* __restrict__ in, __nv_bfloat16* __restrict__ hi,
                        __nv_bfloat16* __restrict__ lo, long long n4)
{
    long long i = (long long)blockIdx.x * 256 + threadIdx.x;
    if (i >= n4) return;
    float4 v = ((const float4*)in)[i];
    __nv_bfloat16 h0 = __float2bfloat16(v.x), h1 = __float2bfloat16(v.y);
    __nv_bfloat16 h2 = __float2bfloat16(v.z), h3 = __float2bfloat16(v.w);
    __nv_bfloat162 ha, hb, la, lb;
    ha.x = h0; ha.y = h1; hb.x = h2; hb.y = h3;
    la.x = __float2bfloat16(v.x - __bfloat162float(h0));
    la.y = __float2bfloat16(v.y - __bfloat162float(h1));
    lb.x = __float2bfloat16(v.z - __bfloat162float(h2));
    lb.y = __float2bfloat16(v.w - __bfloat162float(h3));
    ((__nv_bfloat162*)hi)[2 * i] = ha; ((__nv_bfloat162*)hi)[2 * i + 1] = hb;
    ((__nv_bfloat162*)lo)[2 * i] = la; ((__nv_bfloat162*)lo)[2 * i + 1] = lb;
}

__global__ void split_w1t(const float* __restrict__ W, __nv_bfloat16* __restrict__ hi,
                          __nv_bfloat16* __restrict__ lo)
{
    int n = blockIdx.x;
    int k = threadIdx.x;
    float v = W[k * HD + n];
    __nv_bfloat16 h = __float2bfloat16(v);
    hi[n * FD + k] = h;
    lo[n * FD + k] = __float2bfloat16(v - __bfloat162float(h));
}

__global__ void foldW2(const float* __restrict__ W2, const float* __restrict__ gam,
                       const float* __restrict__ bet, const float* __restrict__ mean,
                       const float* __restrict__ var,
                       __nv_bfloat16* __restrict__ Wth, __nv_bfloat16* __restrict__ Wtl,
                       float* __restrict__ c2)
{
    int n = blockIdx.x;
    int k = threadIdx.x;
    float sc_ = gam[k] * rsqrtf(var[k] + 1e-5f);
    float sh = bet[k] - mean[k] * sc_;
    float w0 = W2[k * HD + n];
    float w = w0 * sc_;
    __nv_bfloat16 h = __float2bfloat16(w);
    Wth[n * HD + k] = h;
    Wtl[n * HD + k] = __float2bfloat16(w - __bfloat162float(h));
    __shared__ float red[256];
    red[k] = sh * w0;
    __syncthreads();
    for (int s = 128; s > 0; s >>= 1) {
        if (k < s) red[k] += red[k + s];
        __syncthreads();
    }
    if (k == 0) c2[n] = red[0];
}

__global__ void split_w3t(const float* __restrict__ W, __nv_bfloat16* __restrict__ hi,
                          __nv_bfloat16* __restrict__ lo)
{
    int n = blockIdx.x;
    int k = threadIdx.x;
    float v = W[k * HD + n];
    __nv_bfloat16 h = __float2bfloat16(v);
    hi[n * HD + k] = h;
    lo[n * HD + k] = __float2bfloat16(v - __bfloat162float(h));
}

// ---------------------------------------------------------------------------
// Graph-structure kernels
// ---------------------------------------------------------------------------
__global__ void init_misc(int* cnt, int* rank)
{
    int i = blockIdx.x * 256 + threadIdx.x;
    if (i < NBN) { cnt[i] = 0; rank[i] = -1; }
}

__global__ void count_edges(const int* __restrict__ dst, int* cnt, int E)
{
    int e = blockIdx.x * 256 + threadIdx.x;
    if (e < E) atomicAdd(&cnt[dst[e]], 1);
}

__global__ void scan_a(const int* __restrict__ cnt, int* off, int* bsum)
{
    __shared__ int sh[256];
    int b = blockIdx.x, t = threadIdx.x;
    int v = cnt[b * 256 + t];
    sh[t] = v;
    __syncthreads();
    for (int d = 1; d < 256; d <<= 1) {
        int u = (t >= d) ? sh[t - d] : 0;
        __syncthreads();
        sh[t] += u;
        __syncthreads();
    }
    off[b * 256 + t] = sh[t] - v;
    if (t == 255) bsum[b] = sh[255];
}

__global__ void scan_c(int* off, int* pos, const int* __restrict__ bsum,
                       const int* __restrict__ cnt, float* dinv, int E)
{
    __shared__ int sh[256];
    int b = blockIdx.x, t = threadIdx.x;
    int v = bsum[t];
    sh[t] = v;
    __syncthreads();
    for (int d = 1; d < 256; d <<= 1) {
        int u = (t >= d) ? sh[t - d] : 0;
        __syncthreads();
        sh[t] += u;
        __syncthreads();
    }
    int bofs = (b == 0) ? 0 : sh[b - 1];
    __syncthreads();
    int i = b * 256 + t;
    int o = off[i] + bofs;
    off[i] = o;
    pos[i] = o;
    dinv[i] = rsqrtf((float)(cnt[i] + 1));
    if (i == NBN - 1) off[NBN] = E;
}

__global__ void scatter_edges(const int* __restrict__ src, const int* __restrict__ dst,
                              int* pos, int* csr, int E)
{
    int e = blockIdx.x * 256 + threadIdx.x;
    if (e < E) {
        int p = atomicAdd(&pos[dst[e]], 1);
        csr[p] = src[e];
    }
}

__global__ void sort_buckets(int* csr, const int* __restrict__ off)
{
    int i = blockIdx.x * 256 + threadIdx.x;
    if (i >= NBN) return;
    int a = off[i], b = off[i + 1];
    for (int p = a + 1; p < b; p++) {
        int v = csr[p];
        int q = p - 1;
        while (q >= a && csr[q] > v) { csr[q + 1] = csr[q]; q--; }
        csr[q + 1] = v;
    }
}

__global__ __launch_bounds__(256)
void gcn_agg(const float4* __restrict__ xw4, const int* __restrict__ off,
             const int* __restrict__ csr, const float* __restrict__ dinv,
             const float4* __restrict__ b1_4, float4* __restrict__ h4)
{
    int g = threadIdx.x >> 6;
    int t = threadIdx.x & 63;
    int i = blockIdx.x * 4 + g;
    float di = dinv[i];
    float4 a = xw4[(long long)i * 64 + t];
    float w0 = di * di;
    float4 acc = make_float4(a.x * w0, a.y * w0, a.z * w0, a.w * w0);
    float4 acc2 = make_float4(0.f, 0.f, 0.f, 0.f);
    int e0 = off[i], e1 = off[i + 1];
    int e = e0;
    for (; e + 1 < e1; e += 2) {
        int s0 = csr[e], s1 = csr[e + 1];
        float wa = dinv[s0] * di, wb = dinv[s1] * di;
        float4 v0 = xw4[(long long)s0 * 64 + t];
        float4 v1 = xw4[(long long)s1 * 64 + t];
        acc.x += v0.x * wa; acc.y += v0.y * wa; acc.z += v0.z * wa; acc.w += v0.w * wa;
        acc2.x += v1.x * wb; acc2.y += v1.y * wb; acc2.z += v1.z * wb; acc2.w += v1.w * wb;
    }
    if (e < e1) {
        int s0 = csr[e];
        float wa = dinv[s0] * di;
        float4 v0 = xw4[(long long)s0 * 64 + t];
        acc.x += v0.x * wa; acc.y += v0.y * wa; acc.z += v0.z * wa; acc.w += v0.w * wa;
    }
    acc.x += acc2.x; acc.y += acc2.y; acc.z += acc2.z; acc.w += acc2.w;
    float4 bb = b1_4[t];
    acc.x = fmaxf(acc.x + bb.x, 0.f);
    acc.y = fmaxf(acc.y + bb.y, 0.f);
    acc.z = fmaxf(acc.z + bb.z, 0.f);
    acc.w = fmaxf(acc.w + bb.w, 0.f);
    h4[(long long)i * 64 + t] = acc;
}

__global__ __launch_bounds__(256)
void pool_score(const float4* __restrict__ h4, const int* __restrict__ off,
                const int* __restrict__ csr, const int* __restrict__ cnt,
                float* __restrict__ score)
{
    __shared__ float red[4][2];
    int g = threadIdx.x >> 6;
    int t = threadIdx.x & 63;
    int i = blockIdx.x * 4 + g;
    float4 acc = make_float4(0.f, 0.f, 0.f, 0.f);
    float4 acc2 = make_float4(0.f, 0.f, 0.f, 0.f);
    int e0 = off[i], e1 = off[i + 1];
    int e = e0;
    for (; e + 1 < e1; e += 2) {
        int s0 = csr[e], s1 = csr[e + 1];
        float4 v0 = h4[(long long)s0 * 64 + t];
        float4 v1 = h4[(long long)s1 * 64 + t];
        acc.x += v0.x; acc.y += v0.y; acc.z += v0.z; acc.w += v0.w;
        acc2.x += v1.x; acc2.y += v1.y; acc2.z += v1.z; acc2.w += v1.w;
    }
    if (e < e1) {
        int s0 = csr[e];
        float4 v0 = h4[(long long)s0 * 64 + t];
        acc.x += v0.x; acc.y += v0.y; acc.z += v0.z; acc.w += v0.w;
    }
    acc.x += acc2.x; acc.y += acc2.y; acc.z += acc2.z; acc.w += acc2.w;
    float degp = fmaxf((float)cnt[i], 1.f);
    float4 hh = h4[(long long)i * 64 + t];
    float s = fabsf(hh.x - acc.x / degp) + fabsf(hh.y - acc.y / degp)
            + fabsf(hh.z - acc.z / degp) + fabsf(hh.w - acc.w / degp);
#pragma unroll
    for (int o = 16; o > 0; o >>= 1)
        s += __shfl_down_sync(0xffffffff, s, o);
    if ((t & 31) == 0) red[g][t >> 5] = s;
    __syncthreads();
    if (t == 0) score[i] = red[g][0] + red[g][1];
}

__global__ void topk_kernel(const float* __restrict__ score, int n, int kout,
                            int* outidx, int* rank)
{
    int g = blockIdx.x;
    int t = threadIdx.x;
    __shared__ float s[512];
    __shared__ int id[512];
    s[t] = score[g * n + t];
    id[t] = t;
    __syncthreads();
    for (int k = 2; k <= n; k <<= 1)
        for (int j = k >> 1; j > 0; j >>= 1) {
            int p = t ^ j;
            if (p > t) {
                float s1 = s[t], s2 = s[p];
                int i1 = id[t], i2 = id[p];
                bool lt12 = (s1 > s2) || (s1 == s2 && i1 < i2);
                bool up = ((t & k) == 0);
                if (up ? !lt12 : lt12) { s[t] = s2; s[p] = s1; id[t] = i2; id[p] = i1; }
            }
            __syncthreads();
        }
    if (t < kout) {
        if (rank) {
            int node = g * n + id[t];
            outidx[g * kout + t] = node;
            rank[node] = t;
        } else {
            outidx[g * kout + t] = id[t];
        }
    }
}

__global__ void gather_rows_ef(const float* __restrict__ h, const int* __restrict__ perm,
                               const float* __restrict__ att,
                               float* __restrict__ h1, __nv_bfloat16* __restrict__ h1h,
                               __nv_bfloat16* __restrict__ h1l, float* __restrict__ ef)
{
    long long n = blockIdx.x;
    int c = threadIdx.x;
    float v = h[(long long)perm[n] * HD + c];
    h1[n * HD + c] = v;
    __nv_bfloat16 hh = __float2bfloat16(v);
    h1h[n * HD + c] = hh;
    h1l[n * HD + c] = __float2bfloat16(v - __bfloat162float(hh));
    __shared__ float re[256], rf[256];
    re[c] = v * att[2 * c];
    rf[c] = v * att[2 * c + 1];
    __syncthreads();
    for (int s = 128; s > 0; s >>= 1) {
        if (c < s) { re[c] += re[c + s]; rf[c] += rf[c + s]; }
        __syncthreads();
    }
    if (c == 0) { ef[2 * n] = re[0]; ef[2 * n + 1] = rf[0]; }
}

__global__ void zero_c(uint8_t* p, long long n16)
{
    long long i = (long long)blockIdx.x * 256 + threadIdx.x;
    if (i < n16) ((uint4*)p)[i] = make_uint4(0, 0, 0, 0);
}

__global__ void buildA1(const int* __restrict__ src, const int* __restrict__ dst,
                        const int* __restrict__ rank, uint8_t* __restrict__ A1c, int E)
{
    int e = blockIdx.x * 256 + threadIdx.x;
    if (e >= E) return;
    int s = src[e], d = dst[e];
    int ns = rank[s], nd = rank[d];
    if (ns >= 0 && nd >= 0) {
        int g = s >> 9;
        A1c[(((long long)g * KP1 + ns) * KP1) + nd] = 1;
    }
}

__global__ void struct_softmax1(const uint8_t* __restrict__ Ac,
                                const float* __restrict__ ef,
                                float* __restrict__ Aout,
                                __nv_bfloat16* __restrict__ Ah,
                                __nv_bfloat16* __restrict__ Al)
{
    int row = blockIdx.x;
    int j = threadIdx.x;
    int b = row >> 8;
    long long base = (long long)row * KP1;
    float logit = ef[2 * row] + ef[2 * ((b << 8) + j) + 1] + (float)Ac[base + j];
    __shared__ float red[256];
    red[j] = logit;
    __syncthreads();
    for (int s = 128; s > 0; s >>= 1) {
        if (j < s) red[j] = fmaxf(red[j], red[j + s]);
        __syncthreads();
    }
    float m = red[0];
    __syncthreads();
    float e = expf(logit - m);
    red[j] = e;
    __syncthreads();
    for (int s = 128; s > 0; s >>= 1) {
        if (j < s) red[j] += red[j + s];
        __syncthreads();
    }
    float v = e / red[0];
    Aout[base + j] = v;
    __nv_bfloat16 hh = __float2bfloat16(v);
    Ah[base + j] = hh;
    Al[base + j] = __float2bfloat16(v - __bfloat162float(hh));
}

__global__ void struct_softmax2(const float* __restrict__ adj1,
                                const int* __restrict__ idx2,
                                const float* __restrict__ ef,
                                __nv_bfloat16* __restrict__ Ah,
                                __nv_bfloat16* __restrict__ Al)
{
    int row = blockIdx.x;
    int j = threadIdx.x;
    int b = row >> 7;
    int ri = idx2[row];
    int rj = idx2[(b << 7) + j];
    float aind = adj1[((long long)b * KP1 + ri) * KP1 + rj];
    float logit = ef[2 * row] + ef[2 * ((b << 7) + j) + 1] + aind;
    __shared__ float red[128];
    red[j] = logit;
    __syncthreads();
    for (int s = 64; s > 0; s >>= 1) {
        if (j < s) red[j] = fmaxf(red[j], red[j + s]);
        __syncthreads();
    }
    float m = red[0];
    __syncthreads();
    float e = expf(logit - m);
    red[j] = e;
    __syncthreads();
    for (int s = 64; s > 0; s >>= 1) {
        if (j < s) red[j] += red[j + s];
        __syncthreads();
    }
    float v = e / red[0];
    long long base = (long long)row * KP2;
    __nv_bfloat16 hh = __float2bfloat16(v);
    Ah[base + j] = hh;
    Al[base + j] = __float2bfloat16(v - __bfloat162float(hh));
}

__global__ void readout_k(const float* __restrict__ X, float* __restrict__ out, int Kd)
{
    __shared__ float smx[4][256], ssm[4][256];
    int b = blockIdx.x;
    int part = threadIdx.x >> 8;
    int c = threadIdx.x & 255;
    int kq = Kd >> 2;
    int k0 = part * kq, k1 = k0 + kq;
    float mx = -3.4e38f, sm = 0.f;
    for (int k = k0; k < k1; k++) {
        float v = X[((long long)b * Kd + k) * HD + c];
        mx = fmaxf(mx, v);
        sm += v;
    }
    smx[part][c] = mx;
    ssm[part][c] = sm;
    __syncthreads();
    if (part == 0) {
        float m = fmaxf(fmaxf(smx[0][c], smx[1][c]), fmaxf(smx[2][c], smx[3][c]));
        float s = ssm[0][c] + ssm[1][c] + ssm[2][c] + ssm[3][c];
        out[b * 2 * HD + c] = m;
        out[b * 2 * HD + HD + c] = s / (float)Kd;
    }
}

__global__ void score_dense(const float* __restrict__ X, const float* __restrict__ P,
                            float* __restrict__ sc)
{
    int row = blockIdx.x;
    int c = threadIdx.x;
    __shared__ float red[256];
    long long base = (long long)row * HD;
    red[c] = fabsf(X[base + c] - P[base + c]);
    __syncthreads();
    for (int s = 128; s > 0; s >>= 1) {
        if (c < s) red[c] += red[c + s];
        __syncthreads();
    }
    if (c == 0) sc[row] = red[0];
}

__global__ void gather_h2sel_ef(const float* __restrict__ h2, const int* __restrict__ idx2,
                                const float* __restrict__ att,
                                float* __restrict__ h2sel, __nv_bfloat16* __restrict__ sh,
                                __nv_bfloat16* __restrict__ sl, float* __restrict__ ef)
{
    int n = blockIdx.x;
    int c = threadIdx.x;
    int b = n >> 7;
    int row = idx2[n];
    float v = h2[((long long)b * KP1 + row) * HD + c];
    h2sel[(long long)n * HD + c] = v;
    __nv_bfloat16 hh = __float2bfloat16(v);
    sh[(long long)n * HD + c] = hh;
    sl[(long long)n * HD + c] = __float2bfloat16(v - __bfloat162float(hh));
    __shared__ float re[256], rf[256];
    re[c] = v * att[2 * c];
    rf[c] = v * att[2 * c + 1];
    __syncthreads();
    for (int s = 128; s > 0; s >>= 1) {
        if (c < s) { re[c] += re[c + s]; rf[c] += rf[c + s]; }
        __syncthreads();
    }
    if (c == 0) { ef[2 * n] = re[0]; ef[2 * n + 1] = rf[0]; }
}

__global__ void head(const float* __restrict__ x1, const float* __restrict__ x2,
                     const float* __restrict__ x3,
                     const float* __restrict__ l1w, const float* __restrict__ l1b,
                     const float* __restrict__ l2w, const float* __restrict__ l2b,
                     const float* __restrict__ l3w, const float* __restrict__ l3b,
                     float* __restrict__ out_x, float* __restrict__ out_lp)
{
    int b = blockIdx.x;
    int t = threadIdx.x;
    __shared__ float g[512], g1[256], g2[128], lg[10];
    for (int i = t; i < 512; i += 256) {
        g[i] = fmaxf(x1[b * 512 + i], 0.f) + fmaxf(x2[b * 512 + i], 0.f) +
               fmaxf(x3[b * 512 + i], 0.f);
    }
    __syncthreads();
    {
        float a = 0.f;
        for (int c = 0; c < 512; c++) a += g[c] * l1w[c * 256 + t];
        g1[t] = fmaxf(a + l1b[t], 0.f);
    }
    __syncthreads();
    if (t < 128) {
        float a = 0.f;
        for (int c = 0; c < 256; c++) a += g1[c] * l2w[c * 128 + t];
        float v = fmaxf(a + l2b[t], 0.f);
        g2[t] = v;
        out_x[b * 128 + t] = v;
    }
    __syncthreads();
    if (t < 10) {
        float a = 0.f;
        for (int c = 0; c < 128; c++) a += g2[c] * l3w[c * 10 + t];
        lg[t] = a + l3b[t];
    }
    __syncthreads();
    if (t == 0) {
        float m = -3.4e38f;
        for (int i = 0; i < 10; i++) m = fmaxf(m, lg[i]);
        float s = 0.f;
        for (int i = 0; i < 10; i++) s += expf(lg[i] - m);
        float lse = m + logf(s);
        for (int i = 0; i < 10; i++) out_lp[b * 10 + i] = lg[i] - lse;
    }
}

// ---------------------------------------------------------------------------
// Launch
// ---------------------------------------------------------------------------
extern "C" void kernel_launch(void* const* d_in, const int* in_sizes, int n_in,
                              void* d_out, int out_size)
{
    void* sp = nullptr;
    cudaGetSymbolAddress(&sp, S);
    Scratch* sc = (Scratch*)sp;

    const float* x    = (const float*)d_in[0];
    const int*   ei   = (const int*)d_in[1];
    const float* W1   = (const float*)d_in[3];
    const float* b1   = (const float*)d_in[4];
    const float* W2   = (const float*)d_in[5];
    const float* b2   = (const float*)d_in[6];
    const float* W3   = (const float*)d_in[7];
    const float* b3   = (const float*)d_in[8];
    const float* att1 = (const float*)d_in[9];
    const float* att2 = (const float*)d_in[10];
    const float* bng  = (const float*)d_in[11];
    const float* bnb  = (const float*)d_in[12];
    const float* bnm  = (const float*)d_in[13];
    const float* bnv  = (const float*)d_in[14];
    const float* l1w  = (const float*)d_in[15];
    const float* l1b  = (const float*)d_in[16];
    const float* l2w  = (const float*)d_in[17];
    const float* l2b  = (const float*)d_in[18];
    const float* l3w  = (const float*)d_in[19];
    const float* l3b  = (const float*)d_in[20];

    int E = in_sizes[1] / 2;
    const int* src = ei;
    const int* dst = ei + E;

    float* out    = (float*)d_out;
    float* out_x  = out;                        // [128,128]
    float* out_lp = out + BGR * 128;            // [128,10]
    float* h      = out + BGR * 128 + BGR * 10; // x__ = [65536,256]

    cudaFuncSetAttribute(bmma, cudaFuncAttributeMaxDynamicSharedMemorySize,
                         BMMA_SMEM);

    // --- prep + big GEMM (bmma is 4th launch -> profiled) ---
    split_x<<<32768, 256>>>(x, sc->xh, sc->xl, (long long)NBN * FD / 4);
    split_w1t<<<HD, FD>>>(W1, sc->w1th, sc->w1tl);
    foldW2<<<HD, HD>>>(W2, bng, bnb, bnm, bnv, sc->w2fth, sc->w2ftl, sc->c2);
    bmma<<<dim3(HD / 128, NBN / 128, 1), 256, BMMA_SMEM>>>(
        sc->xh, sc->xl, sc->w1th, sc->w1tl, nullptr, sc->xw, nullptr, nullptr,
        NBN, HD, FD, 0, 0, 0, 0, 0, nullptr, 1.0f, 0);
    split_w3t<<<HD, HD>>>(W3, sc->w3th, sc->w3tl);

    // --- stage 1: sparse GCN ---
    init_misc<<<NBN / 256, 256>>>(sc->cnt, sc->rank);
    count_edges<<<(E + 255) / 256, 256>>>(dst, sc->cnt, E);
    scan_a<<<256, 256>>>(sc->cnt, sc->off, sc->bsum);
    scan_c<<<256, 256>>>(sc->off, sc->pos, sc->bsum, sc->cnt, sc->dinv, E);
    scatter_edges<<<(E + 255) / 256, 256>>>(src, dst, sc->pos, sc->csr, E);
    sort_buckets<<<NBN / 256, 256>>>(sc->csr, sc->off);
    gcn_agg<<<NBN / 4, 256>>>((const float4*)sc->xw, sc->off, sc->csr, sc->dinv,
                              (const float4*)b1, (float4*)h);

    // --- stage 1 pool (sparse) ---
    pool_score<<<NBN / 4, 256>>>((const float4*)h, sc->off, sc->csr, sc->cnt,
                                 sc->score);
    topk_kernel<<<BGR, NN>>>(sc->score, NN, KP1, sc->perm, sc->rank);
    gather_rows_ef<<<BGR * KP1, 256>>>(h, sc->perm, att1, sc->h1,
                                       sc->h1h, sc->h1l, sc->ef1);
    zero_c<<<(int)(((long long)BGR * KP1 * KP1 / 16 + 255) / 256), 256>>>(
        sc->A1c, (long long)BGR * KP1 * KP1 / 16);
    buildA1<<<(E + 255) / 256, 256>>>(src, dst, sc->rank, sc->A1c, E);
    struct_softmax1<<<BGR * KP1, KP1>>>(sc->A1c, sc->ef1, sc->A1,
                                        sc->A1h, sc->A1l);
    readout_k<<<BGR, 1024>>>(sc->h1, sc->x1, KP1);

    // --- stage 2: BN folded + dense GCN (An = (adj+I)/2 exactly) ---
    bmma<<<dim3(2, 2, BGR), 256, BMMA_SMEM>>>(
        sc->h1h, sc->h1l, sc->w2fth, sc->w2ftl, nullptr, sc->xw2,
        sc->xw2th, sc->xw2tl,
        KP1, HD, HD, (long long)KP1 * HD, 0, 0, (long long)KP1 * HD,
        (long long)KP1 * HD, sc->c2, 1.0f, 0);
    bmma<<<dim3(2, 2, BGR), 256, BMMA_SMEM>>>(
        sc->A1h, sc->A1l, sc->xw2th, sc->xw2tl, sc->xw2, sc->h2,
        sc->h2th, sc->h2tl,
        KP1, HD, KP1, (long long)KP1 * KP1, (long long)KP1 * HD,
        (long long)KP1 * HD, (long long)KP1 * HD, (long long)KP1 * HD,
        b2, 0.5f, 1);
    bmma<<<dim3(2, 2, BGR), 256, BMMA_SMEM>>>(
        sc->A1h, sc->A1l, sc->h2th, sc->h2tl, nullptr, sc->prop, nullptr, nullptr,
        KP1, HD, KP1, (long long)KP1 * KP1, (long long)KP1 * HD, 0,
        (long long)KP1 * HD, 0, nullptr, 1.0f, 0);
    score_dense<<<BGR * KP1, 256>>>(sc->h2, sc->prop, sc->score2);
    topk_kernel<<<BGR, KP1>>>(sc->score2, KP1, KP2, sc->idx2, nullptr);
    gather_h2sel_ef<<<BGR * KP2, 256>>>(sc->h2, sc->idx2, att2, sc->h2sel,
                                        sc->h2selh, sc->h2sell, sc->ef2);
    struct_softmax2<<<BGR * KP2, KP2>>>(sc->A1, sc->idx2, sc->ef2,
                                        sc->A2h, sc->A2l);
    readout_k<<<BGR, 1024>>>(sc->h2sel, sc->x2, KP2);

    // --- stage 3: dense GCN ---
    bmma<<<dim3(2, 1, BGR), 256, BMMA_SMEM>>>(
        sc->h2selh, sc->h2sell, sc->w3th, sc->w3tl, nullptr, sc->xw3,
        sc->xw3th, sc->xw3tl,
        KP2, HD, HD, (long long)KP2 * HD, 0, 0, (long long)KP2 * HD,
        (long long)KP2 * HD, nullptr, 1.0f, 0);
    bmma<<<dim3(2, 1, BGR), 256, BMMA_SMEM>>>(
        sc->A2h, sc->A2l, sc->xw3th, sc->xw3tl, sc->xw3, sc->h3, nullptr, nullptr,
        KP2, HD, KP2, (long long)KP2 * KP2, (long long)KP2 * HD,
        (long long)KP2 * HD, (long long)KP2 * HD, 0, b3, 0.5f, 1);
    readout_k<<<BGR, 1024>>>(sc->h3, sc->x3, KP2);

    // --- head ---
    head<<<BGR, 256>>>(sc->x1, sc->x2, sc->x3, l1w, l1b, l2w, l2b, l3w, l3b,
                       out_x, out_lp);
}

// round 14
// speedup vs baseline: 1.2425x; 1.0396x over previous
#include <cuda_runtime.h>
#include <cuda_bf16.h>
#include <math.h>
#include <stdint.h>

// Problem constants
#define NBN   65536      // B*N nodes
#define BGR   128        // graphs
#define NN    512        // nodes per graph
#define FD    512        // input features
#define HD    256        // hidden
#define KP1   256        // K1
#define KP2   128        // K2
#define EDGES 1048576    // B*EPG

typedef unsigned long long ull;

__device__ __forceinline__ void mma_bf16(float* c, const uint32_t* a,
                                         uint32_t b0, uint32_t b1)
{
    asm volatile(
        "mma.sync.aligned.m16n8k16.row.col.f32.bf16.bf16.f32 "
        "{%0,%1,%2,%3}, {%4,%5,%6,%7}, {%8,%9}, {%0,%1,%2,%3};"
        : "+f"(c[0]), "+f"(c[1]), "+f"(c[2]), "+f"(c[3])
        : "r"(a[0]), "r"(a[1]), "r"(a[2]), "r"(a[3]), "r"(b0), "r"(b1));
}

__device__ __forceinline__ void cp16(uint32_t dst, const void* src)
{
    asm volatile("cp.async.cg.shared.global [%0], [%1], 16;"
                 :: "r"(dst), "l"(src));
}

__device__ __forceinline__ void ldsm4(uint32_t* r, uint32_t a)
{
    asm volatile("ldmatrix.sync.aligned.m8n8.x4.shared.b16 {%0,%1,%2,%3}, [%4];"
                 : "=r"(r[0]), "=r"(r[1]), "=r"(r[2]), "=r"(r[3]) : "r"(a));
}

// ---------------------------------------------------------------------------
// Scratch
// ---------------------------------------------------------------------------
struct Scratch {
    alignas(16) float xw[(long long)NBN * HD];        // x @ W1
    alignas(16) int   cnt[NBN];
    alignas(16) int   off[NBN + 4];
    alignas(16) int   pos[NBN];
    alignas(16) int   csr[EDGES];
    alignas(16) int   bsum[256];
    alignas(16) float dinv[NBN];
    alignas(16) float score[NBN];
    alignas(16) int   perm[BGR * KP1];
    alignas(16) int   rank[NBN];
    alignas(16) float h1[(long long)BGR * KP1 * HD];
    alignas(16) uint8_t A1c[(long long)BGR * KP1 * KP1]; // 0/1 A_ind
    alignas(16) float A1[(long long)BGR * KP1 * KP1];    // adj1 (softmax out)
    alignas(16) float ef1[BGR * KP1 * 2];
    alignas(16) float x1[BGR * 2 * HD];
    alignas(16) float c2[HD];
    alignas(16) float xw2[(long long)BGR * KP1 * HD];
    alignas(16) float h2[(long long)BGR * KP1 * HD];
    alignas(16) float prop[(long long)BGR * KP1 * HD];
    alignas(16) float score2[BGR * KP1];
    alignas(16) int   idx2[BGR * KP2];
    alignas(16) float h2sel[(long long)BGR * KP2 * HD];
    alignas(16) float ef2[BGR * KP2 * 2];
    alignas(16) float x2[BGR * 2 * HD];
    alignas(16) float xw3[(long long)BGR * KP2 * HD];
    alignas(16) float h3[(long long)BGR * KP2 * HD];
    alignas(16) float x3[BGR * 2 * HD];
    // bf16 split weights (transposed [n][k])
    alignas(16) __nv_bfloat16 w1th[HD * FD];
    alignas(16) __nv_bfloat16 w1tl[HD * FD];
    alignas(16) __nv_bfloat16 w2fth[HD * HD];
    alignas(16) __nv_bfloat16 w2ftl[HD * HD];
    alignas(16) __nv_bfloat16 w3th[HD * HD];
    alignas(16) __nv_bfloat16 w3tl[HD * HD];
    // bf16 split A operands (row-major, emitted by producers)
    alignas(16) __nv_bfloat16 xh[(long long)NBN * FD];
    alignas(16) __nv_bfloat16 xl[(long long)NBN * FD];
    alignas(16) __nv_bfloat16 h1h[(long long)BGR * KP1 * HD];
    alignas(16) __nv_bfloat16 h1l[(long long)BGR * KP1 * HD];
    alignas(16) __nv_bfloat16 A1h[(long long)BGR * KP1 * KP1];
    alignas(16) __nv_bfloat16 A1l[(long long)BGR * KP1 * KP1];
    alignas(16) __nv_bfloat16 h2selh[(long long)BGR * KP2 * HD];
    alignas(16) __nv_bfloat16 h2sell[(long long)BGR * KP2 * HD];
    alignas(16) __nv_bfloat16 A2h[(long long)BGR * KP2 * KP2];
    alignas(16) __nv_bfloat16 A2l[(long long)BGR * KP2 * KP2];
    // bf16 split transposed activations (produced by bmma epilogue)
    alignas(16) __nv_bfloat16 xw2th[(long long)BGR * HD * KP1];
    alignas(16) __nv_bfloat16 xw2tl[(long long)BGR * HD * KP1];
    alignas(16) __nv_bfloat16 h2th[(long long)BGR * HD * KP1];
    alignas(16) __nv_bfloat16 h2tl[(long long)BGR * HD * KP1];
    alignas(16) __nv_bfloat16 xw3th[(long long)BGR * HD * KP2];
    alignas(16) __nv_bfloat16 xw3tl[(long long)BGR * HD * KP2];
};
__device__ Scratch S;

// ---------------------------------------------------------------------------
// bmma: pipelined split-bf16 HMMA GEMM, single __syncthreads per K-chunk.
// CT outputs staged through smem transpose for coalesced stores.
// ---------------------------------------------------------------------------
#define ST  40
#define SZB (128 * ST)
#define BMMA_SMEM (2 * 4 * SZB * 2)
#define TPAD 136   // transpose row stride (bf16)

__global__ __launch_bounds__(256, 2)
void bmma(const __nv_bfloat16* __restrict__ Ah, const __nv_bfloat16* __restrict__ Al,
          const __nv_bfloat16* __restrict__ Bh, const __nv_bfloat16* __restrict__ Bl,
          const float* __restrict__ D, float* __restrict__ C,
          __nv_bfloat16* __restrict__ CTh, __nv_bfloat16* __restrict__ CTl,
          int M, int N, int K,
          long long sA, long long sB, long long sD, long long sC, long long sCT,
          const float* __restrict__ bias, float scale, int doRelu)
{
    extern __shared__ __nv_bfloat16 dyn[];
    uint32_t smem_base = (uint32_t)__cvta_generic_to_shared(dyn);

    long long z = blockIdx.z;
    const __nv_bfloat16* Ahb = Ah + z * sA;
    const __nv_bfloat16* Alb = Al + z * sA;
    const __nv_bfloat16* Bhb = Bh + z * sB;
    const __nv_bfloat16* Blb = Bl + z * sB;
    const float* Db = D ? (D + z * sD) : nullptr;
    float* Cb = C + z * sC;
    __nv_bfloat16* CThb = CTh ? (CTh + z * sCT) : nullptr;
    __nv_bfloat16* CTlb = CTl ? (CTl + z * sCT) : nullptr;

    int tid = threadIdx.x;
    int warp = tid >> 5, lane = tid & 31;
    int gid = lane >> 2, tig = lane & 3;
    int wm = warp >> 1, wn = warp & 1;
    int m0 = wm * 32, n0 = wn * 64;
    int row0 = blockIdx.y * 128, col0 = blockIdx.x * 128;

    uint32_t aoff = (uint32_t)((m0 + (lane & 15)) * ST + (lane >> 4) * 8) * 2;
    uint32_t boff = (uint32_t)((n0 + (lane >> 4) * 8 + (lane & 7)) * ST
                               + ((lane >> 3) & 1) * 8) * 2;

    float acc[2][8][4];
#pragma unroll
    for (int mt = 0; mt < 2; mt++)
#pragma unroll
        for (int nt = 0; nt < 8; nt++)
#pragma unroll
            for (int i = 0; i < 4; i++) acc[mt][nt][i] = 0.f;

    auto copy_chunk = [&](int buf, int kc) {
        uint32_t base = smem_base + (uint32_t)buf * 4 * SZB * 2;
#pragma unroll
        for (int it = 0; it < 2; it++) {
            int idx = it * 256 + tid;
            int row = idx >> 2, c8 = (idx & 3) << 3;
            uint32_t so = (uint32_t)(row * ST + c8) * 2;
            long long ga = (long long)(row0 + row) * K + kc + c8;
            long long gb = (long long)(col0 + row) * K + kc + c8;
            cp16(base + 0 * SZB * 2 + so, Ahb + ga);
            cp16(base + 1 * SZB * 2 + so, Alb + ga);
            cp16(base + 2 * SZB * 2 + so, Bhb + gb);
            cp16(base + 3 * SZB * 2 + so, Blb + gb);
        }
        asm volatile("cp.async.commit_group;" ::: "memory");
    };

    copy_chunk(0, 0);
    int buf = 0;
    for (int kc = 0; kc < K; kc += 32) {
        asm volatile("cp.async.wait_group 0;" ::: "memory");
        __syncthreads();
        if (kc + 32 < K) copy_chunk(buf ^ 1, kc + 32);

        uint32_t bufb = smem_base + (uint32_t)buf * 4 * SZB * 2;
        uint32_t aH = bufb + aoff;
        uint32_t aL = bufb + SZB * 2 + aoff;
        uint32_t bH = bufb + 2 * SZB * 2 + boff;
        uint32_t bL = bufb + 3 * SZB * 2 + boff;

#pragma unroll
        for (int ks = 0; ks < 2; ks++) {
            uint32_t kbb = (uint32_t)ks * 32;
            uint32_t ah[2][4], al[2][4];
            ldsm4(ah[0], aH + kbb);
            ldsm4(ah[1], aH + 16 * ST * 2 + kbb);
            ldsm4(al[0], aL + kbb);
            ldsm4(al[1], aL + 16 * ST * 2 + kbb);
#pragma unroll
            for (int p = 0; p < 4; p++) {
                uint32_t bh[4], bl[4];
                ldsm4(bh, bH + (uint32_t)p * 16 * ST * 2 + kbb);
                ldsm4(bl, bL + (uint32_t)p * 16 * ST * 2 + kbb);
#pragma unroll
                for (int mt = 0; mt < 2; mt++) {
                    mma_bf16(acc[mt][2 * p], ah[mt], bh[0], bh[1]);
                    mma_bf16(acc[mt][2 * p], ah[mt], bl[0], bl[1]);
                    mma_bf16(acc[mt][2 * p], al[mt], bh[0], bh[1]);
                    mma_bf16(acc[mt][2 * p + 1], ah[mt], bh[2], bh[3]);
                    mma_bf16(acc[mt][2 * p + 1], ah[mt], bl[2], bl[3]);
                    mma_bf16(acc[mt][2 * p + 1], al[mt], bh[2], bh[3]);
                }
            }
        }
        buf ^= 1;
    }

    // epilogue (smem buffers are dead after this barrier)
    __syncthreads();
    __nv_bfloat16* sTh = dyn;                 // [128][TPAD]
    __nv_bfloat16* sTl = dyn + 128 * TPAD;

#pragma unroll
    for (int mt = 0; mt < 2; mt++) {
        int rl = m0 + mt * 16 + gid;
        long long r = row0 + rl;
#pragma unroll
        for (int nt = 0; nt < 8; nt++) {
            int cl = n0 + nt * 8 + tig * 2;
            int c = col0 + cl;
            float v0 = acc[mt][nt][0], v1 = acc[mt][nt][1];
            float v2 = acc[mt][nt][2], v3 = acc[mt][nt][3];
            if (Db) {
                float2 d0 = *(const float2*)(Db + r * N + c);
                float2 d1 = *(const float2*)(Db + (r + 8) * N + c);
                v0 += d0.x; v1 += d0.y; v2 += d1.x; v3 += d1.y;
            }
            v0 *= scale; v1 *= scale; v2 *= scale; v3 *= scale;
            if (bias) {
                float2 bb = *(const float2*)(bias + c);
                v0 += bb.x; v1 += bb.y; v2 += bb.x; v3 += bb.y;
            }
            if (doRelu) {
                v0 = fmaxf(v0, 0.f); v1 = fmaxf(v1, 0.f);
                v2 = fmaxf(v2, 0.f); v3 = fmaxf(v3, 0.f);
            }
            *(float2*)(Cb + r * N + c) = make_float2(v0, v1);
            *(float2*)(Cb + (r + 8) * N + c) = make_float2(v2, v3);
            if (CThb) {
                __nv_bfloat16 h0 = __float2bfloat16(v0);
                __nv_bfloat16 h1 = __float2bfloat16(v1);
                __nv_bfloat16 h2_ = __float2bfloat16(v2);
                __nv_bfloat16 h3_ = __float2bfloat16(v3);
                sTh[cl * TPAD + rl] = h0;
                sTh[cl * TPAD + rl + 8] = h2_;
                sTh[(cl + 1) * TPAD + rl] = h1;
                sTh[(cl + 1) * TPAD + rl + 8] = h3_;
                sTl[cl * TPAD + rl] = __float2bfloat16(v0 - __bfloat162float(h0));
                sTl[cl * TPAD + rl + 8] = __float2bfloat16(v2 - __bfloat162float(h2_));
                sTl[(cl + 1) * TPAD + rl] = __float2bfloat16(v1 - __bfloat162float(h1));
                sTl[(cl + 1) * TPAD + rl + 8] = __float2bfloat16(v3 - __bfloat162float(h3_));
            }
        }
    }
    if (CThb) {
        __syncthreads();
#pragma unroll
        for (int it = 0; it < 8; it++) {
            int i = it * 256 + tid;
            int cl = i >> 4, v8 = (i & 15) << 3;
            uint4 vh = *(const uint4*)&sTh[cl * TPAD + v8];
            uint4 vl = *(const uint4*)&sTl[cl * TPAD + v8];
            long long go = (long long)(col0 + cl) * M + row0 + v8;
            *(uint4*)(CThb + go) = vh;
            *(uint4*)(CTlb + go) = vl;
        }
    }
}

// ---------------------------------------------------------------------------
// split / weight prep kernels
// ---------------------------------------------------------------------------
__global__ void split_x(const float* __restrict__ in, __nv_bfloat16* __restrict__ hi,
                        __nv_bfloat16* __restrict__ lo, long long n4)
{
    long long i = (long long)blockIdx.x * 256 + threadIdx.x;
    if (i >= n4) return;
    float4 v = ((const float4*)in)[i];
    __nv_bfloat16 h0 = __float2bfloat16(v.x), h1 = __float2bfloat16(v.y);
    __nv_bfloat16 h2 = __float2bfloat16(v.z), h3 = __float2bfloat16(v.w);
    __nv_bfloat162 ha, hb, la, lb;
    ha.x = h0; ha.y = h1; hb.x = h2; hb.y = h3;
    la.x = __float2bfloat16(v.x - __bfloat162float(h0));
    la.y = __float2bfloat16(v.y - __bfloat162float(h1));
    lb.x = __float2bfloat16(v.z - __bfloat162float(h2));
    lb.y = __float2bfloat16(v.w - __bfloat162float(h3));
    ((__nv_bfloat162*)hi)[2 * i] = ha; ((__nv_bfloat162*)hi)[2 * i + 1] = hb;
    ((__nv_bfloat162*)lo)[2 * i] = la; ((__nv_bfloat162*)lo)[2 * i + 1] = lb;
}

__global__ void split_w1t(const float* __restrict__ W, __nv_bfloat16* __restrict__ hi,
                          __nv_bfloat16* __restrict__ lo)
{
    int n = blockIdx.x;
    int k = threadIdx.x;
    float v = W[k * HD + n];
    __nv_bfloat16 h = __float2bfloat16(v);
    hi[n * FD + k] = h;
    lo[n * FD + k] = __float2bfloat16(v - __bfloat162float(h));
}

__global__ void foldW2(const float* __restrict__ W2, const float* __restrict__ gam,
                       const float* __restrict__ bet, const float* __restrict__ mean,
                       const float* __restrict__ var,
                       __nv_bfloat16* __restrict__ Wth, __nv_bfloat16* __restrict__ Wtl,
                       float* __restrict__ c2)
{
    int n = blockIdx.x;
    int k = threadIdx.x;
    float sc_ = gam[k] * rsqrtf(var[k] + 1e-5f);
    float sh = bet[k] - mean[k] * sc_;
    float w0 = W2[k * HD + n];
    float w = w0 * sc_;
    __nv_bfloat16 h = __float2bfloat16(w);
    Wth[n * HD + k] = h;
    Wtl[n * HD + k] = __float2bfloat16(w - __bfloat162float(h));
    __shared__ float red[256];
    red[k] = sh * w0;
    __syncthreads();
    for (int s = 128; s > 0; s >>= 1) {
        if (k < s) red[k] += red[k + s];
        __syncthreads();
    }
    if (k == 0) c2[n] = red[0];
}

__global__ void split_w3t(const float* __restrict__ W, __nv_bfloat16* __restrict__ hi,
                          __nv_bfloat16* __restrict__ lo)
{
    int n = blockIdx.x;
    int k = threadIdx.x;
    float v = W[k * HD + n];
    __nv_bfloat16 h = __float2bfloat16(v);
    hi[n * HD + k] = h;
    lo[n * HD + k] = __float2bfloat16(v - __bfloat162float(h));
}

// ---------------------------------------------------------------------------
// Graph-structure kernels
// ---------------------------------------------------------------------------
__global__ void init_misc(int* cnt, int* rank)
{
    int i = blockIdx.x * 256 + threadIdx.x;
    if (i < NBN) { cnt[i] = 0; rank[i] = -1; }
}

__global__ void count_edges(const int* __restrict__ dst, int* cnt, int E)
{
    int e = blockIdx.x * 256 + threadIdx.x;
    if (e < E) atomicAdd(&cnt[dst[e]], 1);
}

__global__ void scan_a(const int* __restrict__ cnt, int* off, int* bsum)
{
    __shared__ int sh[256];
    int b = blockIdx.x, t = threadIdx.x;
    int v = cnt[b * 256 + t];
    sh[t] = v;
    __syncthreads();
    for (int d = 1; d < 256; d <<= 1) {
        int u = (t >= d) ? sh[t - d] : 0;
        __syncthreads();
        sh[t] += u;
        __syncthreads();
    }
    off[b * 256 + t] = sh[t] - v;
    if (t == 255) bsum[b] = sh[255];
}

__global__ void scan_c(int* off, int* pos, const int* __restrict__ bsum,
                       const int* __restrict__ cnt, float* dinv, int E)
{
    __shared__ int sh[256];
    int b = blockIdx.x, t = threadIdx.x;
    int v = bsum[t];
    sh[t] = v;
    __syncthreads();
    for (int d = 1; d < 256; d <<= 1) {
        int u = (t >= d) ? sh[t - d] : 0;
        __syncthreads();
        sh[t] += u;
        __syncthreads();
    }
    int bofs = (b == 0) ? 0 : sh[b - 1];
    __syncthreads();
    int i = b * 256 + t;
    int o = off[i] + bofs;
    off[i] = o;
    pos[i] = o;
    dinv[i] = rsqrtf((float)(cnt[i] + 1));
    if (i == NBN - 1) off[NBN] = E;
}

__global__ void scatter_edges(const int* __restrict__ src, const int* __restrict__ dst,
                              int* pos, int* csr, int E)
{
    int e = blockIdx.x * 256 + threadIdx.x;
    if (e < E) {
        int p = atomicAdd(&pos[dst[e]], 1);
        csr[p] = src[e];
    }
}

__global__ void sort_buckets(int* csr, const int* __restrict__ off)
{
    int i = blockIdx.x * 256 + threadIdx.x;
    if (i >= NBN) return;
    int a = off[i], b = off[i + 1];
    for (int p = a + 1; p < b; p++) {
        int v = csr[p];
        int q = p - 1;
        while (q >= a && csr[q] > v) { csr[q + 1] = csr[q]; q--; }
        csr[q + 1] = v;
    }
}

__global__ __launch_bounds__(256)
void gcn_agg(const float4* __restrict__ xw4, const int* __restrict__ off,
             const int* __restrict__ csr, const float* __restrict__ dinv,
             const float4* __restrict__ b1_4, float4* __restrict__ h4)
{
    int g = threadIdx.x >> 6;
    int t = threadIdx.x & 63;
    int i = blockIdx.x * 4 + g;
    float di = dinv[i];
    float4 a = xw4[(long long)i * 64 + t];
    float w0 = di * di;
    float4 acc = make_float4(a.x * w0, a.y * w0, a.z * w0, a.w * w0);
    float4 acc2 = make_float4(0.f, 0.f, 0.f, 0.f);
    int e0 = off[i], e1 = off[i + 1];
    int e = e0;
    for (; e + 1 < e1; e += 2) {
        int s0 = csr[e], s1 = csr[e + 1];
        float wa = dinv[s0] * di, wb = dinv[s1] * di;
        float4 v0 = xw4[(long long)s0 * 64 + t];
        float4 v1 = xw4[(long long)s1 * 64 + t];
        acc.x += v0.x * wa; acc.y += v0.y * wa; acc.z += v0.z * wa; acc.w += v0.w * wa;
        acc2.x += v1.x * wb; acc2.y += v1.y * wb; acc2.z += v1.z * wb; acc2.w += v1.w * wb;
    }
    if (e < e1) {
        int s0 = csr[e];
        float wa = dinv[s0] * di;
        float4 v0 = xw4[(long long)s0 * 64 + t];
        acc.x += v0.x * wa; acc.y += v0.y * wa; acc.z += v0.z * wa; acc.w += v0.w * wa;
    }
    acc.x += acc2.x; acc.y += acc2.y; acc.z += acc2.z; acc.w += acc2.w;
    float4 bb = b1_4[t];
    acc.x = fmaxf(acc.x + bb.x, 0.f);
    acc.y = fmaxf(acc.y + bb.y, 0.f);
    acc.z = fmaxf(acc.z + bb.z, 0.f);
    acc.w = fmaxf(acc.w + bb.w, 0.f);
    h4[(long long)i * 64 + t] = acc;
}

__global__ __launch_bounds__(256)
void pool_score(const float4* __restrict__ h4, const int* __restrict__ off,
                const int* __restrict__ csr, const int* __restrict__ cnt,
                float* __restrict__ score)
{
    __shared__ float red[4][2];
    int g = threadIdx.x >> 6;
    int t = threadIdx.x & 63;
    int i = blockIdx.x * 4 + g;
    float4 acc = make_float4(0.f, 0.f, 0.f, 0.f);
    float4 acc2 = make_float4(0.f, 0.f, 0.f, 0.f);
    int e0 = off[i], e1 = off[i + 1];
    int e = e0;
    for (; e + 1 < e1; e += 2) {
        int s0 = csr[e], s1 = csr[e + 1];
        float4 v0 = h4[(long long)s0 * 64 + t];
        float4 v1 = h4[(long long)s1 * 64 + t];
        acc.x += v0.x; acc.y += v0.y; acc.z += v0.z; acc.w += v0.w;
        acc2.x += v1.x; acc2.y += v1.y; acc2.z += v1.z; acc2.w += v1.w;
    }
    if (e < e1) {
        int s0 = csr[e];
        float4 v0 = h4[(long long)s0 * 64 + t];
        acc.x += v0.x; acc.y += v0.y; acc.z += v0.z; acc.w += v0.w;
    }
    acc.x += acc2.x; acc.y += acc2.y; acc.z += acc2.z; acc.w += acc2.w;
    float degp = fmaxf((float)cnt[i], 1.f);
    float4 hh = h4[(long long)i * 64 + t];
    float s = fabsf(hh.x - acc.x / degp) + fabsf(hh.y - acc.y / degp)
            + fabsf(hh.z - acc.z / degp) + fabsf(hh.w - acc.w / degp);
#pragma unroll
    for (int o = 16; o > 0; o >>= 1)
        s += __shfl_down_sync(0xffffffff, s, o);
    if ((t & 31) == 0) red[g][t >> 5] = s;
    __syncthreads();
    if (t == 0) score[i] = red[g][0] + red[g][1];
}

__global__ void topk_kernel(const float* __restrict__ score, int n, int kout,
                            int* outidx, int* rank)
{
    int g = blockIdx.x;
    int t = threadIdx.x;
    __shared__ float s[512];
    __shared__ int id[512];
    s[t] = score[g * n + t];
    id[t] = t;
    __syncthreads();
    for (int k = 2; k <= n; k <<= 1)
        for (int j = k >> 1; j > 0; j >>= 1) {
            int p = t ^ j;
            if (p > t) {
                float s1 = s[t], s2 = s[p];
                int i1 = id[t], i2 = id[p];
                bool lt12 = (s1 > s2) || (s1 == s2 && i1 < i2);
                bool up = ((t & k) == 0);
                if (up ? !lt12 : lt12) { s[t] = s2; s[p] = s1; id[t] = i2; id[p] = i1; }
            }
            __syncthreads();
        }
    if (t < kout) {
        if (rank) {
            int node = g * n + id[t];
            outidx[g * kout + t] = node;
            rank[node] = t;
        } else {
            outidx[g * kout + t] = id[t];
        }
    }
}

__global__ void gather_rows_ef(const float* __restrict__ h, const int* __restrict__ perm,
                               const float* __restrict__ att,
                               float* __restrict__ h1, __nv_bfloat16* __restrict__ h1h,
                               __nv_bfloat16* __restrict__ h1l, float* __restrict__ ef)
{
    long long n = blockIdx.x;
    int c = threadIdx.x;
    float v = h[(long long)perm[n] * HD + c];
    h1[n * HD + c] = v;
    __nv_bfloat16 hh = __float2bfloat16(v);
    h1h[n * HD + c] = hh;
    h1l[n * HD + c] = __float2bfloat16(v - __bfloat162float(hh));
    __shared__ float re[256], rf[256];
    re[c] = v * att[2 * c];
    rf[c] = v * att[2 * c + 1];
    __syncthreads();
    for (int s = 128; s > 0; s >>= 1) {
        if (c < s) { re[c] += re[c + s]; rf[c] += rf[c + s]; }
        __syncthreads();
    }
    if (c == 0) { ef[2 * n] = re[0]; ef[2 * n + 1] = rf[0]; }
}

__global__ void zero_c(uint8_t* p, long long n16)
{
    long long i = (long long)blockIdx.x * 256 + threadIdx.x;
    if (i < n16) ((uint4*)p)[i] = make_uint4(0, 0, 0, 0);
}

__global__ void buildA1(const int* __restrict__ src, const int* __restrict__ dst,
                        const int* __restrict__ rank, uint8_t* __restrict__ A1c, int E)
{
    int e = blockIdx.x * 256 + threadIdx.x;
    if (e >= E) return;
    int s = src[e], d = dst[e];
    int ns = rank[s], nd = rank[d];
    if (ns >= 0 && nd >= 0) {
        int g = s >> 9;
        A1c[(((long long)g * KP1 + ns) * KP1) + nd] = 1;
    }
}

__global__ void struct_softmax1(const uint8_t* __restrict__ Ac,
                                const float* __restrict__ ef,
                                float* __restrict__ Aout,
                                __nv_bfloat16* __restrict__ Ah,
                                __nv_bfloat16* __restrict__ Al)
{
    int row = blockIdx.x;
    int j = threadIdx.x;
    int b = row >> 8;
    long long base = (long long)row * KP1;
    float logit = ef[2 * row] + ef[2 * ((b << 8) + j) + 1] + (float)Ac[base + j];
    __shared__ float red[256];
    red[j] = logit;
    __syncthreads();
    for (int s = 128; s > 0; s >>= 1) {
        if (j < s) red[j] = fmaxf(red[j], red[j + s]);
        __syncthreads();
    }
    float m = red[0];
    __syncthreads();
    float e = expf(logit - m);
    red[j] = e;
    __syncthreads();
    for (int s = 128; s > 0; s >>= 1) {
        if (j < s) red[j] += red[j + s];
        __syncthreads();
    }
    float v = e / red[0];
    Aout[base + j] = v;
    __nv_bfloat16 hh = __float2bfloat16(v);
    Ah[base + j] = hh;
    Al[base + j] = __float2bfloat16(v - __bfloat162float(hh));
}

__global__ void struct_softmax2(const float* __restrict__ adj1,
                                const int* __restrict__ idx2,
                                const float* __restrict__ ef,
                                __nv_bfloat16* __restrict__ Ah,
                                __nv_bfloat16* __restrict__ Al)
{
    int row = blockIdx.x;
    int j = threadIdx.x;
    int b = row >> 7;
    int ri = idx2[row];
    int rj = idx2[(b << 7) + j];
    float aind = adj1[((long long)b * KP1 + ri) * KP1 + rj];
    float logit = ef[2 * row] + ef[2 * ((b << 7) + j) + 1] + aind;
    __shared__ float red[128];
    red[j] = logit;
    __syncthreads();
    for (int s = 64; s > 0; s >>= 1) {
        if (j < s) red[j] = fmaxf(red[j], red[j + s]);
        __syncthreads();
    }
    float m = red[0];
    __syncthreads();
    float e = expf(logit - m);
    red[j] = e;
    __syncthreads();
    for (int s = 64; s > 0; s >>= 1) {
        if (j < s) red[j] += red[j + s];
        __syncthreads();
    }
    float v = e / red[0];
    long long base = (long long)row * KP2;
    __nv_bfloat16 hh = __float2bfloat16(v);
    Ah[base + j] = hh;
    Al[base + j] = __float2bfloat16(v - __bfloat162float(hh));
}

__global__ void readout_k(const float* __restrict__ X, float* __restrict__ out, int Kd)
{
    __shared__ float smx[4][256], ssm[4][256];
    int b = blockIdx.x;
    int part = threadIdx.x >> 8;
    int c = threadIdx.x & 255;
    int kq = Kd >> 2;
    int k0 = part * kq, k1 = k0 + kq;
    float mx = -3.4e38f, sm = 0.f;
    for (int k = k0; k < k1; k++) {
        float v = X[((long long)b * Kd + k) * HD + c];
        mx = fmaxf(mx, v);
        sm += v;
    }
    smx[part][c] = mx;
    ssm[part][c] = sm;
    __syncthreads();
    if (part == 0) {
        float m = fmaxf(fmaxf(smx[0][c], smx[1][c]), fmaxf(smx[2][c], smx[3][c]));
        float s = ssm[0][c] + ssm[1][c] + ssm[2][c] + ssm[3][c];
        out[b * 2 * HD + c] = m;
        out[b * 2 * HD + HD + c] = s / (float)Kd;
    }
}

__global__ void score_dense(const float* __restrict__ X, const float* __restrict__ P,
                            float* __restrict__ sc)
{
    int row = blockIdx.x;
    int c = threadIdx.x;
    __shared__ float red[256];
    long long base = (long long)row * HD;
    red[c] = fabsf(X[base + c] - P[base + c]);
    __syncthreads();
    for (int s = 128; s > 0; s >>= 1) {
        if (c < s) red[c] += red[c + s];
        __syncthreads();
    }
    if (c == 0) sc[row] = red[0];
}

__global__ void gather_h2sel_ef(const float* __restrict__ h2, const int* __restrict__ idx2,
                                const float* __restrict__ att,
                                float* __restrict__ h2sel, __nv_bfloat16* __restrict__ sh,
                                __nv_bfloat16* __restrict__ sl, float* __restrict__ ef)
{
    int n = blockIdx.x;
    int c = threadIdx.x;
    int b = n >> 7;
    int row = idx2[n];
    float v = h2[((long long)b * KP1 + row) * HD + c];
    h2sel[(long long)n * HD + c] = v;
    __nv_bfloat16 hh = __float2bfloat16(v);
    sh[(long long)n * HD + c] = hh;
    sl[(long long)n * HD + c] = __float2bfloat16(v - __bfloat162float(hh));
    __shared__ float re[256], rf[256];
    re[c] = v * att[2 * c];
    rf[c] = v * att[2 * c + 1];
    __syncthreads();
    for (int s = 128; s > 0; s >>= 1) {
        if (c < s) { re[c] += re[c + s]; rf[c] += rf[c + s]; }
        __syncthreads();
    }
    if (c == 0) { ef[2 * n] = re[0]; ef[2 * n + 1] = rf[0]; }
}

__global__ void head(const float* __restrict__ x1, const float* __restrict__ x2,
                     const float* __restrict__ x3,
                     const float* __restrict__ l1w, const float* __restrict__ l1b,
                     const float* __restrict__ l2w, const float* __restrict__ l2b,
                     const float* __restrict__ l3w, const float* __restrict__ l3b,
                     float* __restrict__ out_x, float* __restrict__ out_lp)
{
    int b = blockIdx.x;
    int t = threadIdx.x;
    __shared__ float g[512], g1[256], g2[128], lg[10];
    for (int i = t; i < 512; i += 256) {
        g[i] = fmaxf(x1[b * 512 + i], 0.f) + fmaxf(x2[b * 512 + i], 0.f) +
               fmaxf(x3[b * 512 + i], 0.f);
    }
    __syncthreads();
    {
        float a = 0.f;
        for (int c = 0; c < 512; c++) a += g[c] * l1w[c * 256 + t];
        g1[t] = fmaxf(a + l1b[t], 0.f);
    }
    __syncthreads();
    if (t < 128) {
        float a = 0.f;
        for (int c = 0; c < 256; c++) a += g1[c] * l2w[c * 128 + t];
        float v = fmaxf(a + l2b[t], 0.f);
        g2[t] = v;
        out_x[b * 128 + t] = v;
    }
    __syncthreads();
    if (t < 10) {
        float a = 0.f;
        for (int c = 0; c < 128; c++) a += g2[c] * l3w[c * 10 + t];
        lg[t] = a + l3b[t];
    }
    __syncthreads();
    if (t == 0) {
        float m = -3.4e38f;
        for (int i = 0; i < 10; i++) m = fmaxf(m, lg[i]);
        float s = 0.f;
        for (int i = 0; i < 10; i++) s += expf(lg[i] - m);
        float lse = m + logf(s);
        for (int i = 0; i < 10; i++) out_lp[b * 10 + i] = lg[i] - lse;
    }
}

// ---------------------------------------------------------------------------
// Launch (two-stream fork/join; resources created once, work identical per call)
// ---------------------------------------------------------------------------
extern "C" void kernel_launch(void* const* d_in, const int* in_sizes, int n_in,
                              void* d_out, int out_size)
{
    static cudaStream_t s2 = nullptr;
    static cudaEvent_t evF, evCSR, evG1, evA1, evG2, evA2;
    if (!s2) {
        cudaStreamCreateWithFlags(&s2, cudaStreamNonBlocking);
        cudaEventCreateWithFlags(&evF, cudaEventDisableTiming);
        cudaEventCreateWithFlags(&evCSR, cudaEventDisableTiming);
        cudaEventCreateWithFlags(&evG1, cudaEventDisableTiming);
        cudaEventCreateWithFlags(&evA1, cudaEventDisableTiming);
        cudaEventCreateWithFlags(&evG2, cudaEventDisableTiming);
        cudaEventCreateWithFlags(&evA2, cudaEventDisableTiming);
    }

    void* sp = nullptr;
    cudaGetSymbolAddress(&sp, S);
    Scratch* sc = (Scratch*)sp;

    const float* x    = (const float*)d_in[0];
    const int*   ei   = (const int*)d_in[1];
    const float* W1   = (const float*)d_in[3];
    const float* b1   = (const float*)d_in[4];
    const float* W2   = (const float*)d_in[5];
    const float* b2   = (const float*)d_in[6];
    const float* W3   = (const float*)d_in[7];
    const float* b3   = (const float*)d_in[8];
    const float* att1 = (const float*)d_in[9];
    const float* att2 = (const float*)d_in[10];
    const float* bng  = (const float*)d_in[11];
    const float* bnb  = (const float*)d_in[12];
    const float* bnm  = (const float*)d_in[13];
    const float* bnv  = (const float*)d_in[14];
    const float* l1w  = (const float*)d_in[15];
    const float* l1b  = (const float*)d_in[16];
    const float* l2w  = (const float*)d_in[17];
    const float* l2b  = (const float*)d_in[18];
    const float* l3w  = (const float*)d_in[19];
    const float* l3b  = (const float*)d_in[20];

    int E = in_sizes[1] / 2;
    const int* src = ei;
    const int* dst = ei + E;

    float* out    = (float*)d_out;
    float* out_x  = out;                        // [128,128]
    float* out_lp = out + BGR * 128;            // [128,10]
    float* h      = out + BGR * 128 + BGR * 10; // x__ = [65536,256]

    cudaFuncSetAttribute(bmma, cudaFuncAttributeMaxDynamicSharedMemorySize,
                         BMMA_SMEM);

    // ---- fork: CSR build + A1c zero on s2, GEMM prep on s0 ----
    cudaEventRecord(evF, 0);
    cudaStreamWaitEvent(s2, evF, 0);

    zero_c<<<(int)(((long long)BGR * KP1 * KP1 / 16 + 255) / 256), 256, 0, s2>>>(
        sc->A1c, (long long)BGR * KP1 * KP1 / 16);
    init_misc<<<NBN / 256, 256, 0, s2>>>(sc->cnt, sc->rank);
    count_edges<<<(E + 255) / 256, 256, 0, s2>>>(dst, sc->cnt, E);
    scan_a<<<256, 256, 0, s2>>>(sc->cnt, sc->off, sc->bsum);
    scan_c<<<256, 256, 0, s2>>>(sc->off, sc->pos, sc->bsum, sc->cnt, sc->dinv, E);
    scatter_edges<<<(E + 255) / 256, 256, 0, s2>>>(src, dst, sc->pos, sc->csr, E);
    sort_buckets<<<NBN / 256, 256, 0, s2>>>(sc->csr, sc->off);
    cudaEventRecord(evCSR, s2);

    split_x<<<32768, 256>>>(x, sc->xh, sc->xl, (long long)NBN * FD / 4);
    split_w1t<<<HD, FD>>>(W1, sc->w1th, sc->w1tl);
    foldW2<<<HD, HD>>>(W2, bng, bnb, bnm, bnv, sc->w2fth, sc->w2ftl, sc->c2);
    bmma<<<dim3(HD / 128, NBN / 128, 1), 256, BMMA_SMEM>>>(
        sc->xh, sc->xl, sc->w1th, sc->w1tl, nullptr, sc->xw, nullptr, nullptr,
        NBN, HD, FD, 0, 0, 0, 0, 0, nullptr, 1.0f, 0);
    split_w3t<<<HD, HD>>>(W3, sc->w3th, sc->w3tl);

    // ---- join: need csr/off/dinv + xw ----
    cudaStreamWaitEvent(0, evCSR, 0);
    gcn_agg<<<NBN / 4, 256>>>((const float4*)sc->xw, sc->off, sc->csr, sc->dinv,
                              (const float4*)b1, (float4*)h);
    pool_score<<<NBN / 4, 256>>>((const float4*)h, sc->off, sc->csr, sc->cnt,
                                 sc->score);
    topk_kernel<<<BGR, NN>>>(sc->score, NN, KP1, sc->perm, sc->rank);
    gather_rows_ef<<<BGR * KP1, 256>>>(h, sc->perm, att1, sc->h1,
                                       sc->h1h, sc->h1l, sc->ef1);

    // ---- fork: A1 build+softmax on s2, xw2 GEMM + readout on s0 ----
    cudaEventRecord(evG1, 0);
    cudaStreamWaitEvent(s2, evG1, 0);
    buildA1<<<(E + 255) / 256, 256, 0, s2>>>(src, dst, sc->rank, sc->A1c, E);
    struct_softmax1<<<BGR * KP1, KP1, 0, s2>>>(sc->A1c, sc->ef1, sc->A1,
                                               sc->A1h, sc->A1l);
    cudaEventRecord(evA1, s2);

    bmma<<<dim3(2, 2, BGR), 256, BMMA_SMEM>>>(
        sc->h1h, sc->h1l, sc->w2fth, sc->w2ftl, nullptr, sc->xw2,
        sc->xw2th, sc->xw2tl,
        KP1, HD, HD, (long long)KP1 * HD, 0, 0, (long long)KP1 * HD,
        (long long)KP1 * HD, sc->c2, 1.0f, 0);
    readout_k<<<BGR, 1024>>>(sc->h1, sc->x1, KP1);

    // ---- join: need adj1 splits ----
    cudaStreamWaitEvent(0, evA1, 0);
    bmma<<<dim3(2, 2, BGR), 256, BMMA_SMEM>>>(
        sc->A1h, sc->A1l, sc->xw2th, sc->xw2tl, sc->xw2, sc->h2,
        sc->h2th, sc->h2tl,
        KP1, HD, KP1, (long long)KP1 * KP1, (long long)KP1 * HD,
        (long long)KP1 * HD, (long long)KP1 * HD, (long long)KP1 * HD,
        b2, 0.5f, 1);
    bmma<<<dim3(2, 2, BGR), 256, BMMA_SMEM>>>(
        sc->A1h, sc->A1l, sc->h2th, sc->h2tl, nullptr, sc->prop, nullptr, nullptr,
        KP1, HD, KP1, (long long)KP1 * KP1, (long long)KP1 * HD, 0,
        (long long)KP1 * HD, 0, nullptr, 1.0f, 0);
    score_dense<<<BGR * KP1, 256>>>(sc->h2, sc->prop, sc->score2);
    topk_kernel<<<BGR, KP1>>>(sc->score2, KP1, KP2, sc->idx2, nullptr);
    gather_h2sel_ef<<<BGR * KP2, 256>>>(sc->h2, sc->idx2, att2, sc->h2sel,
                                        sc->h2selh, sc->h2sell, sc->ef2);

    // ---- fork: softmax2 on s2, xw3 GEMM + readout on s0 ----
    cudaEventRecord(evG2, 0);
    cudaStreamWaitEvent(s2, evG2, 0);
    struct_softmax2<<<BGR * KP2, KP2, 0, s2>>>(sc->A1, sc->idx2, sc->ef2,
                                               sc->A2h, sc->A2l);
    cudaEventRecord(evA2, s2);

    bmma<<<dim3(2, 1, BGR), 256, BMMA_SMEM>>>(
        sc->h2selh, sc->h2sell, sc->w3th, sc->w3tl, nullptr, sc->xw3,
        sc->xw3th, sc->xw3tl,
        KP2, HD, HD, (long long)KP2 * HD, 0, 0, (long long)KP2 * HD,
        (long long)KP2 * HD, nullptr, 1.0f, 0);
    readout_k<<<BGR, 1024>>>(sc->h2sel, sc->x2, KP2);

    // ---- join: need adj2 splits ----
    cudaStreamWaitEvent(0, evA2, 0);
    bmma<<<dim3(2, 1, BGR), 256, BMMA_SMEM>>>(
        sc->A2h, sc->A2l, sc->xw3th, sc->xw3tl, sc->xw3, sc->h3, nullptr, nullptr,
        KP2, HD, KP2, (long long)KP2 * KP2, (long long)KP2 * HD,
        (long long)KP2 * HD, (long long)KP2 * HD, 0, b3, 0.5f, 1);
    readout_k<<<BGR, 1024>>>(sc->h3, sc->x3, KP2);

    // ---- head ----
    head<<<BGR, 256>>>(sc->x1, sc->x2, sc->x3, l1w, l1b, l2w, l2b, l3w, l3b,
                       out_x, out_lp);
}

// round 15
// speedup vs baseline: 1.2999x; 1.0461x over previous
#include <cuda_runtime.h>
#include <cuda_bf16.h>
#include <math.h>
#include <stdint.h>

// Problem constants
#define NBN   65536      // B*N nodes
#define BGR   128        // graphs
#define NN    512        // nodes per graph
#define FD    512        // input features
#define HD    256        // hidden
#define KP1   256        // K1
#define KP2   128        // K2
#define EDGES 1048576    // B*EPG

typedef unsigned long long ull;

__device__ __forceinline__ void mma_bf16(float* c, const uint32_t* a,
                                         uint32_t b0, uint32_t b1)
{
    asm volatile(
        "mma.sync.aligned.m16n8k16.row.col.f32.bf16.bf16.f32 "
        "{%0,%1,%2,%3}, {%4,%5,%6,%7}, {%8,%9}, {%0,%1,%2,%3};"
        : "+f"(c[0]), "+f"(c[1]), "+f"(c[2]), "+f"(c[3])
        : "r"(a[0]), "r"(a[1]), "r"(a[2]), "r"(a[3]), "r"(b0), "r"(b1));
}

__device__ __forceinline__ void cp16(uint32_t dst, const void* src)
{
    asm volatile("cp.async.cg.shared.global [%0], [%1], 16;"
                 :: "r"(dst), "l"(src));
}

__device__ __forceinline__ void ldsm4(uint32_t* r, uint32_t a)
{
    asm volatile("ldmatrix.sync.aligned.m8n8.x4.shared.b16 {%0,%1,%2,%3}, [%4];"
                 : "=r"(r[0]), "=r"(r[1]), "=r"(r[2]), "=r"(r[3]) : "r"(a));
}

// ---------------------------------------------------------------------------
// Scratch
// ---------------------------------------------------------------------------
struct Scratch {
    alignas(16) float xw[(long long)NBN * HD];        // x @ W1
    alignas(16) int   cnt[NBN];
    alignas(16) int   off[NBN + 4];
    alignas(16) int   pos[NBN];
    alignas(16) int   csr[EDGES];
    alignas(16) int   bsum[256];
    alignas(16) float dinv[NBN];
    alignas(16) float score[NBN];
    alignas(16) float spart[2LL * BGR * KP1];
    alignas(16) int   perm[BGR * KP1];
    alignas(16) int   rank[NBN];
    alignas(16) float h1[(long long)BGR * KP1 * HD];
    alignas(16) uint8_t A1c[(long long)BGR * KP1 * KP1]; // 0/1 A_ind
    alignas(16) float A1[(long long)BGR * KP1 * KP1];    // adj1 (softmax out)
    alignas(16) float ef1[BGR * KP1 * 2];
    alignas(16) float x1[BGR * 2 * HD];
    alignas(16) float c2[HD];
    alignas(16) float xw2[(long long)BGR * KP1 * HD];
    alignas(16) float h2[(long long)BGR * KP1 * HD];
    alignas(16) int   idx2[BGR * KP2];
    alignas(16) float h2sel[(long long)BGR * KP2 * HD];
    alignas(16) float ef2[BGR * KP2 * 2];
    alignas(16) float x2[BGR * 2 * HD];
    alignas(16) float xw3[(long long)BGR * KP2 * HD];
    alignas(16) float h3[(long long)BGR * KP2 * HD];
    alignas(16) float x3[BGR * 2 * HD];
    // bf16 split weights (transposed [n][k])
    alignas(16) __nv_bfloat16 w1th[HD * FD];
    alignas(16) __nv_bfloat16 w1tl[HD * FD];
    alignas(16) __nv_bfloat16 w2fth[HD * HD];
    alignas(16) __nv_bfloat16 w2ftl[HD * HD];
    alignas(16) __nv_bfloat16 w3th[HD * HD];
    alignas(16) __nv_bfloat16 w3tl[HD * HD];
    // bf16 split A operands (row-major, emitted by producers)
    alignas(16) __nv_bfloat16 xh[(long long)NBN * FD];
    alignas(16) __nv_bfloat16 xl[(long long)NBN * FD];
    alignas(16) __nv_bfloat16 h1h[(long long)BGR * KP1 * HD];
    alignas(16) __nv_bfloat16 h1l[(long long)BGR * KP1 * HD];
    alignas(16) __nv_bfloat16 A1h[(long long)BGR * KP1 * KP1];
    alignas(16) __nv_bfloat16 A1l[(long long)BGR * KP1 * KP1];
    alignas(16) __nv_bfloat16 h2selh[(long long)BGR * KP2 * HD];
    alignas(16) __nv_bfloat16 h2sell[(long long)BGR * KP2 * HD];
    alignas(16) __nv_bfloat16 A2h[(long long)BGR * KP2 * KP2];
    alignas(16) __nv_bfloat16 A2l[(long long)BGR * KP2 * KP2];
    // bf16 split transposed activations (produced by bmma epilogue)
    alignas(16) __nv_bfloat16 xw2th[(long long)BGR * HD * KP1];
    alignas(16) __nv_bfloat16 xw2tl[(long long)BGR * HD * KP1];
    alignas(16) __nv_bfloat16 h2th[(long long)BGR * HD * KP1];
    alignas(16) __nv_bfloat16 h2tl[(long long)BGR * HD * KP1];
    alignas(16) __nv_bfloat16 xw3th[(long long)BGR * HD * KP2];
    alignas(16) __nv_bfloat16 xw3tl[(long long)BGR * HD * KP2];
};
__device__ Scratch S;

// ---------------------------------------------------------------------------
// bmma: pipelined split-bf16 HMMA GEMM.
// Modes: normal (C [+CT splits]); score (SP != null): no stores, emits
// per-row partial sums of |D - acc*scale| into SP[bx][z][row] (deterministic).
// ---------------------------------------------------------------------------
#define ST  40
#define SZB (128 * ST)
#define BMMA_SMEM (2 * 4 * SZB * 2)
#define TPAD 136   // transpose row stride (bf16)

__global__ __launch_bounds__(256, 2)
void bmma(const __nv_bfloat16* __restrict__ Ah, const __nv_bfloat16* __restrict__ Al,
          const __nv_bfloat16* __restrict__ Bh, const __nv_bfloat16* __restrict__ Bl,
          const float* __restrict__ D, float* __restrict__ C,
          __nv_bfloat16* __restrict__ CTh, __nv_bfloat16* __restrict__ CTl,
          int M, int N, int K,
          long long sA, long long sB, long long sD, long long sC, long long sCT,
          const float* __restrict__ bias, float scale, int doRelu,
          float* __restrict__ SP)
{
    extern __shared__ __nv_bfloat16 dyn[];
    uint32_t smem_base = (uint32_t)__cvta_generic_to_shared(dyn);

    long long z = blockIdx.z;
    const __nv_bfloat16* Ahb = Ah + z * sA;
    const __nv_bfloat16* Alb = Al + z * sA;
    const __nv_bfloat16* Bhb = Bh + z * sB;
    const __nv_bfloat16* Blb = Bl + z * sB;
    const float* Db = D ? (D + z * sD) : nullptr;
    float* Cb = C ? (C + z * sC) : nullptr;
    __nv_bfloat16* CThb = CTh ? (CTh + z * sCT) : nullptr;
    __nv_bfloat16* CTlb = CTl ? (CTl + z * sCT) : nullptr;
    bool scoreMode = (SP != nullptr);

    int tid = threadIdx.x;
    int warp = tid >> 5, lane = tid & 31;
    int gid = lane >> 2, tig = lane & 3;
    int wm = warp >> 1, wn = warp & 1;
    int m0 = wm * 32, n0 = wn * 64;
    int row0 = blockIdx.y * 128, col0 = blockIdx.x * 128;

    uint32_t aoff = (uint32_t)((m0 + (lane & 15)) * ST + (lane >> 4) * 8) * 2;
    uint32_t boff = (uint32_t)((n0 + (lane >> 4) * 8 + (lane & 7)) * ST
                               + ((lane >> 3) & 1) * 8) * 2;

    float acc[2][8][4];
#pragma unroll
    for (int mt = 0; mt < 2; mt++)
#pragma unroll
        for (int nt = 0; nt < 8; nt++)
#pragma unroll
            for (int i = 0; i < 4; i++) acc[mt][nt][i] = 0.f;

    auto copy_chunk = [&](int buf, int kc) {
        uint32_t base = smem_base + (uint32_t)buf * 4 * SZB * 2;
#pragma unroll
        for (int it = 0; it < 2; it++) {
            int idx = it * 256 + tid;
            int row = idx >> 2, c8 = (idx & 3) << 3;
            uint32_t so = (uint32_t)(row * ST + c8) * 2;
            long long ga = (long long)(row0 + row) * K + kc + c8;
            long long gb = (long long)(col0 + row) * K + kc + c8;
            cp16(base + 0 * SZB * 2 + so, Ahb + ga);
            cp16(base + 1 * SZB * 2 + so, Alb + ga);
            cp16(base + 2 * SZB * 2 + so, Bhb + gb);
            cp16(base + 3 * SZB * 2 + so, Blb + gb);
        }
        asm volatile("cp.async.commit_group;" ::: "memory");
    };

    copy_chunk(0, 0);
    int buf = 0;
    for (int kc = 0; kc < K; kc += 32) {
        asm volatile("cp.async.wait_group 0;" ::: "memory");
        __syncthreads();
        if (kc + 32 < K) copy_chunk(buf ^ 1, kc + 32);

        uint32_t bufb = smem_base + (uint32_t)buf * 4 * SZB * 2;
        uint32_t aH = bufb + aoff;
        uint32_t aL = bufb + SZB * 2 + aoff;
        uint32_t bH = bufb + 2 * SZB * 2 + boff;
        uint32_t bL = bufb + 3 * SZB * 2 + boff;

#pragma unroll
        for (int ks = 0; ks < 2; ks++) {
            uint32_t kbb = (uint32_t)ks * 32;
            uint32_t ah[2][4], al[2][4];
            ldsm4(ah[0], aH + kbb);
            ldsm4(ah[1], aH + 16 * ST * 2 + kbb);
            ldsm4(al[0], aL + kbb);
            ldsm4(al[1], aL + 16 * ST * 2 + kbb);
#pragma unroll
            for (int p = 0; p < 4; p++) {
                uint32_t bh[4], bl[4];
                ldsm4(bh, bH + (uint32_t)p * 16 * ST * 2 + kbb);
                ldsm4(bl, bL + (uint32_t)p * 16 * ST * 2 + kbb);
#pragma unroll
                for (int mt = 0; mt < 2; mt++) {
                    mma_bf16(acc[mt][2 * p], ah[mt], bh[0], bh[1]);
                    mma_bf16(acc[mt][2 * p], ah[mt], bl[0], bl[1]);
                    mma_bf16(acc[mt][2 * p], al[mt], bh[0], bh[1]);
                    mma_bf16(acc[mt][2 * p + 1], ah[mt], bh[2], bh[3]);
                    mma_bf16(acc[mt][2 * p + 1], ah[mt], bl[2], bl[3]);
                    mma_bf16(acc[mt][2 * p + 1], al[mt], bh[2], bh[3]);
                }
            }
        }
        buf ^= 1;
    }

    // epilogue (smem buffers are dead after this barrier)
    __syncthreads();
    __nv_bfloat16* sTh = dyn;                 // [128][TPAD] (normal mode)
    __nv_bfloat16* sTl = dyn + 128 * TPAD;
    float* srow = (float*)dyn;                // [128][9] (score mode)

    float rs[2][2] = {{0.f, 0.f}, {0.f, 0.f}};

#pragma unroll
    for (int mt = 0; mt < 2; mt++) {
        int rl = m0 + mt * 16 + gid;
        long long r = row0 + rl;
#pragma unroll
        for (int nt = 0; nt < 8; nt++) {
            int cl = n0 + nt * 8 + tig * 2;
            int c = col0 + cl;
            float v0 = acc[mt][nt][0], v1 = acc[mt][nt][1];
            float v2 = acc[mt][nt][2], v3 = acc[mt][nt][3];
            if (scoreMode) {
                float2 d0 = *(const float2*)(Db + r * N + c);
                float2 d1 = *(const float2*)(Db + (r + 8) * N + c);
                v0 *= scale; v1 *= scale; v2 *= scale; v3 *= scale;
                rs[mt][0] += fabsf(d0.x - v0) + fabsf(d0.y - v1);
                rs[mt][1] += fabsf(d1.x - v2) + fabsf(d1.y - v3);
                continue;
            }
            if (Db) {
                float2 d0 = *(const float2*)(Db + r * N + c);
                float2 d1 = *(const float2*)(Db + (r + 8) * N + c);
                v0 += d0.x; v1 += d0.y; v2 += d1.x; v3 += d1.y;
            }
            v0 *= scale; v1 *= scale; v2 *= scale; v3 *= scale;
            if (bias) {
                float2 bb = *(const float2*)(bias + c);
                v0 += bb.x; v1 += bb.y; v2 += bb.x; v3 += bb.y;
            }
            if (doRelu) {
                v0 = fmaxf(v0, 0.f); v1 = fmaxf(v1, 0.f);
                v2 = fmaxf(v2, 0.f); v3 = fmaxf(v3, 0.f);
            }
            *(float2*)(Cb + r * N + c) = make_float2(v0, v1);
            *(float2*)(Cb + (r + 8) * N + c) = make_float2(v2, v3);
            if (CThb) {
                __nv_bfloat16 h0 = __float2bfloat16(v0);
                __nv_bfloat16 h1 = __float2bfloat16(v1);
                __nv_bfloat16 h2_ = __float2bfloat16(v2);
                __nv_bfloat16 h3_ = __float2bfloat16(v3);
                sTh[cl * TPAD + rl] = h0;
                sTh[cl * TPAD + rl + 8] = h2_;
                sTh[(cl + 1) * TPAD + rl] = h1;
                sTh[(cl + 1) * TPAD + rl + 8] = h3_;
                sTl[cl * TPAD + rl] = __float2bfloat16(v0 - __bfloat162float(h0));
                sTl[cl * TPAD + rl + 8] = __float2bfloat16(v2 - __bfloat162float(h2_));
                sTl[(cl + 1) * TPAD + rl] = __float2bfloat16(v1 - __bfloat162float(h1));
                sTl[(cl + 1) * TPAD + rl + 8] = __float2bfloat16(v3 - __bfloat162float(h3_));
            }
        }
    }
    if (scoreMode) {
        int slot = wn * 4 + tig;
#pragma unroll
        for (int mt = 0; mt < 2; mt++) {
            int rl = m0 + mt * 16 + gid;
            srow[rl * 9 + slot] = rs[mt][0];
            srow[(rl + 8) * 9 + slot] = rs[mt][1];
        }
        __syncthreads();
        if (tid < 128) {
            float s = 0.f;
#pragma unroll
            for (int k = 0; k < 8; k++) s += srow[tid * 9 + k];
            SP[((long long)blockIdx.x * BGR + z) * (long long)M + row0 + tid] = s;
        }
        return;
    }
    if (CThb) {
        __syncthreads();
#pragma unroll
        for (int it = 0; it < 8; it++) {
            int i = it * 256 + tid;
            int cl = i >> 4, v8 = (i & 15) << 3;
            uint4 vh = *(const uint4*)&sTh[cl * TPAD + v8];
            uint4 vl = *(const uint4*)&sTl[cl * TPAD + v8];
            long long go = (long long)(col0 + cl) * M + row0 + v8;
            *(uint4*)(CThb + go) = vh;
            *(uint4*)(CTlb + go) = vl;
        }
    }
}

// ---------------------------------------------------------------------------
// split / weight prep kernels
// ---------------------------------------------------------------------------
__global__ void split_x(const float* __restrict__ in, __nv_bfloat16* __restrict__ hi,
                        __nv_bfloat16* __restrict__ lo, long long n4)
{
    long long i = (long long)blockIdx.x * 256 + threadIdx.x;
    if (i >= n4) return;
    float4 v = ((const float4*)in)[i];
    __nv_bfloat16 h0 = __float2bfloat16(v.x), h1 = __float2bfloat16(v.y);
    __nv_bfloat16 h2 = __float2bfloat16(v.z), h3 = __float2bfloat16(v.w);
    __nv_bfloat162 ha, hb, la, lb;
    ha.x = h0; ha.y = h1; hb.x = h2; hb.y = h3;
    la.x = __float2bfloat16(v.x - __bfloat162float(h0));
    la.y = __float2bfloat16(v.y - __bfloat162float(h1));
    lb.x = __float2bfloat16(v.z - __bfloat162float(h2));
    lb.y = __float2bfloat16(v.w - __bfloat162float(h3));
    ((__nv_bfloat162*)hi)[2 * i] = ha; ((__nv_bfloat162*)hi)[2 * i + 1] = hb;
    ((__nv_bfloat162*)lo)[2 * i] = la; ((__nv_bfloat162*)lo)[2 * i + 1] = lb;
}

__global__ void split_w1t(const float* __restrict__ W, __nv_bfloat16* __restrict__ hi,
                          __nv_bfloat16* __restrict__ lo)
{
    int n = blockIdx.x;
    int k = threadIdx.x;
    float v = W[k * HD + n];
    __nv_bfloat16 h = __float2bfloat16(v);
    hi[n * FD + k] = h;
    lo[n * FD + k] = __float2bfloat16(v - __bfloat162float(h));
}

__global__ void foldW2(const float* __restrict__ W2, const float* __restrict__ gam,
                       const float* __restrict__ bet, const float* __restrict__ mean,
                       const float* __restrict__ var,
                       __nv_bfloat16* __restrict__ Wth, __nv_bfloat16* __restrict__ Wtl,
                       float* __restrict__ c2)
{
    int n = blockIdx.x;
    int k = threadIdx.x;
    float sc_ = gam[k] * rsqrtf(var[k] + 1e-5f);
    float sh = bet[k] - mean[k] * sc_;
    float w0 = W2[k * HD + n];
    float w = w0 * sc_;
    __nv_bfloat16 h = __float2bfloat16(w);
    Wth[n * HD + k] = h;
    Wtl[n * HD + k] = __float2bfloat16(w - __bfloat162float(h));
    __shared__ float red[256];
    red[k] = sh * w0;
    __syncthreads();
    for (int s = 128; s > 0; s >>= 1) {
        if (k < s) red[k] += red[k + s];
        __syncthreads();
    }
    if (k == 0) c2[n] = red[0];
}

__global__ void split_w3t(const float* __restrict__ W, __nv_bfloat16* __restrict__ hi,
                          __nv_bfloat16* __restrict__ lo)
{
    int n = blockIdx.x;
    int k = threadIdx.x;
    float v = W[k * HD + n];
    __nv_bfloat16 h = __float2bfloat16(v);
    hi[n * HD + k] = h;
    lo[n * HD + k] = __float2bfloat16(v - __bfloat162float(h));
}

// ---------------------------------------------------------------------------
// Graph-structure kernels
// ---------------------------------------------------------------------------
__global__ void init_misc(int* cnt, int* rank)
{
    int i = blockIdx.x * 256 + threadIdx.x;
    if (i < NBN) { cnt[i] = 0; rank[i] = -1; }
}

__global__ void count_edges(const int* __restrict__ dst, int* cnt, int E)
{
    int e = blockIdx.x * 256 + threadIdx.x;
    if (e < E) atomicAdd(&cnt[dst[e]], 1);
}

__global__ void scan_a(const int* __restrict__ cnt, int* off, int* bsum)
{
    __shared__ int sh[256];
    int b = blockIdx.x, t = threadIdx.x;
    int v = cnt[b * 256 + t];
    sh[t] = v;
    __syncthreads();
    for (int d = 1; d < 256; d <<= 1) {
        int u = (t >= d) ? sh[t - d] : 0;
        __syncthreads();
        sh[t] += u;
        __syncthreads();
    }
    off[b * 256 + t] = sh[t] - v;
    if (t == 255) bsum[b] = sh[255];
}

__global__ void scan_c(int* off, int* pos, const int* __restrict__ bsum,
                       const int* __restrict__ cnt, float* dinv, int E)
{
    __shared__ int sh[256];
    int b = blockIdx.x, t = threadIdx.x;
    int v = bsum[t];
    sh[t] = v;
    __syncthreads();
    for (int d = 1; d < 256; d <<= 1) {
        int u = (t >= d) ? sh[t - d] : 0;
        __syncthreads();
        sh[t] += u;
        __syncthreads();
    }
    int bofs = (b == 0) ? 0 : sh[b - 1];
    __syncthreads();
    int i = b * 256 + t;
    int o = off[i] + bofs;
    off[i] = o;
    pos[i] = o;
    dinv[i] = rsqrtf((float)(cnt[i] + 1));
    if (i == NBN - 1) off[NBN] = E;
}

__global__ void scatter_edges(const int* __restrict__ src, const int* __restrict__ dst,
                              int* pos, int* csr, int E)
{
    int e = blockIdx.x * 256 + threadIdx.x;
    if (e < E) {
        int p = atomicAdd(&pos[dst[e]], 1);
        csr[p] = src[e];
    }
}

__global__ void sort_buckets(int* csr, const int* __restrict__ off)
{
    int i = blockIdx.x * 256 + threadIdx.x;
    if (i >= NBN) return;
    int a = off[i], b = off[i + 1];
    for (int p = a + 1; p < b; p++) {
        int v = csr[p];
        int q = p - 1;
        while (q >= a && csr[q] > v) { csr[q + 1] = csr[q]; q--; }
        csr[q + 1] = v;
    }
}

__global__ __launch_bounds__(256)
void gcn_agg(const float4* __restrict__ xw4, const int* __restrict__ off,
             const int* __restrict__ csr, const float* __restrict__ dinv,
             const float4* __restrict__ b1_4, float4* __restrict__ h4)
{
    int g = threadIdx.x >> 6;
    int t = threadIdx.x & 63;
    int i = blockIdx.x * 4 + g;
    float di = dinv[i];
    float4 a = xw4[(long long)i * 64 + t];
    float w0 = di * di;
    float4 acc = make_float4(a.x * w0, a.y * w0, a.z * w0, a.w * w0);
    float4 acc2 = make_float4(0.f, 0.f, 0.f, 0.f);
    int e0 = off[i], e1 = off[i + 1];
    int e = e0;
    for (; e + 1 < e1; e += 2) {
        int s0 = csr[e], s1 = csr[e + 1];
        float wa = dinv[s0] * di, wb = dinv[s1] * di;
        float4 v0 = xw4[(long long)s0 * 64 + t];
        float4 v1 = xw4[(long long)s1 * 64 + t];
        acc.x += v0.x * wa; acc.y += v0.y * wa; acc.z += v0.z * wa; acc.w += v0.w * wa;
        acc2.x += v1.x * wb; acc2.y += v1.y * wb; acc2.z += v1.z * wb; acc2.w += v1.w * wb;
    }
    if (e < e1) {
        int s0 = csr[e];
        float wa = dinv[s0] * di;
        float4 v0 = xw4[(long long)s0 * 64 + t];
        acc.x += v0.x * wa; acc.y += v0.y * wa; acc.z += v0.z * wa; acc.w += v0.w * wa;
    }
    acc.x += acc2.x; acc.y += acc2.y; acc.z += acc2.z; acc.w += acc2.w;
    float4 bb = b1_4[t];
    acc.x = fmaxf(acc.x + bb.x, 0.f);
    acc.y = fmaxf(acc.y + bb.y, 0.f);
    acc.z = fmaxf(acc.z + bb.z, 0.f);
    acc.w = fmaxf(acc.w + bb.w, 0.f);
    h4[(long long)i * 64 + t] = acc;
}

__global__ __launch_bounds__(256)
void pool_score(const float4* __restrict__ h4, const int* __restrict__ off,
                const int* __restrict__ csr, const int* __restrict__ cnt,
                float* __restrict__ score)
{
    __shared__ float red[4][2];
    int g = threadIdx.x >> 6;
    int t = threadIdx.x & 63;
    int i = blockIdx.x * 4 + g;
    float4 acc = make_float4(0.f, 0.f, 0.f, 0.f);
    float4 acc2 = make_float4(0.f, 0.f, 0.f, 0.f);
    int e0 = off[i], e1 = off[i + 1];
    int e = e0;
    for (; e + 1 < e1; e += 2) {
        int s0 = csr[e], s1 = csr[e + 1];
        float4 v0 = h4[(long long)s0 * 64 + t];
        float4 v1 = h4[(long long)s1 * 64 + t];
        acc.x += v0.x; acc.y += v0.y; acc.z += v0.z; acc.w += v0.w;
        acc2.x += v1.x; acc2.y += v1.y; acc2.z += v1.z; acc2.w += v1.w;
    }
    if (e < e1) {
        int s0 = csr[e];
        float4 v0 = h4[(long long)s0 * 64 + t];
        acc.x += v0.x; acc.y += v0.y; acc.z += v0.z; acc.w += v0.w;
    }
    acc.x += acc2.x; acc.y += acc2.y; acc.z += acc2.z; acc.w += acc2.w;
    float degp = fmaxf((float)cnt[i], 1.f);
    float4 hh = h4[(long long)i * 64 + t];
    float s = fabsf(hh.x - acc.x / degp) + fabsf(hh.y - acc.y / degp)
            + fabsf(hh.z - acc.z / degp) + fabsf(hh.w - acc.w / degp);
#pragma unroll
    for (int o = 16; o > 0; o >>= 1)
        s += __shfl_down_sync(0xffffffff, s, o);
    if ((t & 31) == 0) red[g][t >> 5] = s;
    __syncthreads();
    if (t == 0) score[i] = red[g][0] + red[g][1];
}

// top-k; scoreB optional second partial array summed at load
__global__ void topk_kernel(const float* __restrict__ score,
                            const float* __restrict__ scoreB, int n, int kout,
                            int* outidx, int* rank)
{
    int g = blockIdx.x;
    int t = threadIdx.x;
    __shared__ float s[512];
    __shared__ int id[512];
    float v = score[g * n + t];
    if (scoreB) v += scoreB[g * n + t];
    s[t] = v;
    id[t] = t;
    __syncthreads();
    for (int k = 2; k <= n; k <<= 1)
        for (int j = k >> 1; j > 0; j >>= 1) {
            int p = t ^ j;
            if (p > t) {
                float s1 = s[t], s2 = s[p];
                int i1 = id[t], i2 = id[p];
                bool lt12 = (s1 > s2) || (s1 == s2 && i1 < i2);
                bool up = ((t & k) == 0);
                if (up ? !lt12 : lt12) { s[t] = s2; s[p] = s1; id[t] = i2; id[p] = i1; }
            }
            __syncthreads();
        }
    if (t < kout) {
        if (rank) {
            int node = g * n + id[t];
            outidx[g * kout + t] = node;
            rank[node] = t;
        } else {
            outidx[g * kout + t] = id[t];
        }
    }
}

__global__ void gather_rows_ef(const float* __restrict__ h, const int* __restrict__ perm,
                               const float* __restrict__ att,
                               float* __restrict__ h1, __nv_bfloat16* __restrict__ h1h,
                               __nv_bfloat16* __restrict__ h1l, float* __restrict__ ef)
{
    long long n = blockIdx.x;
    int c = threadIdx.x;
    float v = h[(long long)perm[n] * HD + c];
    h1[n * HD + c] = v;
    __nv_bfloat16 hh = __float2bfloat16(v);
    h1h[n * HD + c] = hh;
    h1l[n * HD + c] = __float2bfloat16(v - __bfloat162float(hh));
    __shared__ float re[256], rf[256];
    re[c] = v * att[2 * c];
    rf[c] = v * att[2 * c + 1];
    __syncthreads();
    for (int s = 128; s > 0; s >>= 1) {
        if (c < s) { re[c] += re[c + s]; rf[c] += rf[c + s]; }
        __syncthreads();
    }
    if (c == 0) { ef[2 * n] = re[0]; ef[2 * n + 1] = rf[0]; }
}

__global__ void zero_c(uint8_t* p, long long n16)
{
    long long i = (long long)blockIdx.x * 256 + threadIdx.x;
    if (i < n16) ((uint4*)p)[i] = make_uint4(0, 0, 0, 0);
}

__global__ void buildA1(const int* __restrict__ src, const int* __restrict__ dst,
                        const int* __restrict__ rank, uint8_t* __restrict__ A1c, int E)
{
    int e = blockIdx.x * 256 + threadIdx.x;
    if (e >= E) return;
    int s = src[e], d = dst[e];
    int ns = rank[s], nd = rank[d];
    if (ns >= 0 && nd >= 0) {
        int g = s >> 9;
        A1c[(((long long)g * KP1 + ns) * KP1) + nd] = 1;
    }
}

__global__ void struct_softmax1(const uint8_t* __restrict__ Ac,
                                const float* __restrict__ ef,
                                float* __restrict__ Aout,
                                __nv_bfloat16* __restrict__ Ah,
                                __nv_bfloat16* __restrict__ Al)
{
    int row = blockIdx.x;
    int j = threadIdx.x;
    int b = row >> 8;
    long long base = (long long)row * KP1;
    float logit = ef[2 * row] + ef[2 * ((b << 8) + j) + 1] + (float)Ac[base + j];
    __shared__ float red[256];
    red[j] = logit;
    __syncthreads();
    for (int s = 128; s > 0; s >>= 1) {
        if (j < s) red[j] = fmaxf(red[j], red[j + s]);
        __syncthreads();
    }
    float m = red[0];
    __syncthreads();
    float e = expf(logit - m);
    red[j] = e;
    __syncthreads();
    for (int s = 128; s > 0; s >>= 1) {
        if (j < s) red[j] += red[j + s];
        __syncthreads();
    }
    float v = e / red[0];
    Aout[base + j] = v;
    __nv_bfloat16 hh = __float2bfloat16(v);
    Ah[base + j] = hh;
    Al[base + j] = __float2bfloat16(v - __bfloat162float(hh));
}

__global__ void struct_softmax2(const float* __restrict__ adj1,
                                const int* __restrict__ idx2,
                                const float* __restrict__ ef,
                                __nv_bfloat16* __restrict__ Ah,
                                __nv_bfloat16* __restrict__ Al)
{
    int row = blockIdx.x;
    int j = threadIdx.x;
    int b = row >> 7;
    int ri = idx2[row];
    int rj = idx2[(b << 7) + j];
    float aind = adj1[((long long)b * KP1 + ri) * KP1 + rj];
    float logit = ef[2 * row] + ef[2 * ((b << 7) + j) + 1] + aind;
    __shared__ float red[128];
    red[j] = logit;
    __syncthreads();
    for (int s = 64; s > 0; s >>= 1) {
        if (j < s) red[j] = fmaxf(red[j], red[j + s]);
        __syncthreads();
    }
    float m = red[0];
    __syncthreads();
    float e = expf(logit - m);
    red[j] = e;
    __syncthreads();
    for (int s = 64; s > 0; s >>= 1) {
        if (j < s) red[j] += red[j + s];
        __syncthreads();
    }
    float v = e / red[0];
    long long base = (long long)row * KP2;
    __nv_bfloat16 hh = __float2bfloat16(v);
    Ah[base + j] = hh;
    Al[base + j] = __float2bfloat16(v - __bfloat162float(hh));
}

__global__ void readout_k(const float* __restrict__ X, float* __restrict__ out, int Kd)
{
    __shared__ float smx[4][256], ssm[4][256];
    int b = blockIdx.x;
    int part = threadIdx.x >> 8;
    int c = threadIdx.x & 255;
    int kq = Kd >> 2;
    int k0 = part * kq, k1 = k0 + kq;
    float mx = -3.4e38f, sm = 0.f;
    for (int k = k0; k < k1; k++) {
        float v = X[((long long)b * Kd + k) * HD + c];
        mx = fmaxf(mx, v);
        sm += v;
    }
    smx[part][c] = mx;
    ssm[part][c] = sm;
    __syncthreads();
    if (part == 0) {
        float m = fmaxf(fmaxf(smx[0][c], smx[1][c]), fmaxf(smx[2][c], smx[3][c]));
        float s = ssm[0][c] + ssm[1][c] + ssm[2][c] + ssm[3][c];
        out[b * 2 * HD + c] = m;
        out[b * 2 * HD + HD + c] = s / (float)Kd;
    }
}

__global__ void gather_h2sel_ef(const float* __restrict__ h2, const int* __restrict__ idx2,
                                const float* __restrict__ att,
                                float* __restrict__ h2sel, __nv_bfloat16* __restrict__ sh,
                                __nv_bfloat16* __restrict__ sl, float* __restrict__ ef)
{
    int n = blockIdx.x;
    int c = threadIdx.x;
    int b = n >> 7;
    int row = idx2[n];
    float v = h2[((long long)b * KP1 + row) * HD + c];
    h2sel[(long long)n * HD + c] = v;
    __nv_bfloat16 hh = __float2bfloat16(v);
    sh[(long long)n * HD + c] = hh;
    sl[(long long)n * HD + c] = __float2bfloat16(v - __bfloat162float(hh));
    __shared__ float re[256], rf[256];
    re[c] = v * att[2 * c];
    rf[c] = v * att[2 * c + 1];
    __syncthreads();
    for (int s = 128; s > 0; s >>= 1) {
        if (c < s) { re[c] += re[c + s]; rf[c] += rf[c + s]; }
        __syncthreads();
    }
    if (c == 0) { ef[2 * n] = re[0]; ef[2 * n + 1] = rf[0]; }
}

__global__ void head(const float* __restrict__ x1, const float* __restrict__ x2,
                     const float* __restrict__ x3,
                     const float* __restrict__ l1w, const float* __restrict__ l1b,
                     const float* __restrict__ l2w, const float* __restrict__ l2b,
                     const float* __restrict__ l3w, const float* __restrict__ l3b,
                     float* __restrict__ out_x, float* __restrict__ out_lp)
{
    int b = blockIdx.x;
    int t = threadIdx.x;
    __shared__ float g[512], g1[256], g2[128], lg[10];
    for (int i = t; i < 512; i += 256) {
        g[i] = fmaxf(x1[b * 512 + i], 0.f) + fmaxf(x2[b * 512 + i], 0.f) +
               fmaxf(x3[b * 512 + i], 0.f);
    }
    __syncthreads();
    {
        float a = 0.f;
        for (int c = 0; c < 512; c++) a += g[c] * l1w[c * 256 + t];
        g1[t] = fmaxf(a + l1b[t], 0.f);
    }
    __syncthreads();
    if (t < 128) {
        float a = 0.f;
        for (int c = 0; c < 256; c++) a += g1[c] * l2w[c * 128 + t];
        float v = fmaxf(a + l2b[t], 0.f);
        g2[t] = v;
        out_x[b * 128 + t] = v;
    }
    __syncthreads();
    if (t < 10) {
        float a = 0.f;
        for (int c = 0; c < 128; c++) a += g2[c] * l3w[c * 10 + t];
        lg[t] = a + l3b[t];
    }
    __syncthreads();
    if (t == 0) {
        float m = -3.4e38f;
        for (int i = 0; i < 10; i++) m = fmaxf(m, lg[i]);
        float s = 0.f;
        for (int i = 0; i < 10; i++) s += expf(lg[i] - m);
        float lse = m + logf(s);
        for (int i = 0; i < 10; i++) out_lp[b * 10 + i] = lg[i] - lse;
    }
}

// ---------------------------------------------------------------------------
// Launch (two-stream fork/join)
// ---------------------------------------------------------------------------
extern "C" void kernel_launch(void* const* d_in, const int* in_sizes, int n_in,
                              void* d_out, int out_size)
{
    static cudaStream_t s2 = nullptr;
    static cudaEvent_t evF, evCSR, evW, evG1, evA1, evG2, evA2;
    if (!s2) {
        cudaStreamCreateWithFlags(&s2, cudaStreamNonBlocking);
        cudaEventCreateWithFlags(&evF, cudaEventDisableTiming);
        cudaEventCreateWithFlags(&evCSR, cudaEventDisableTiming);
        cudaEventCreateWithFlags(&evW, cudaEventDisableTiming);
        cudaEventCreateWithFlags(&evG1, cudaEventDisableTiming);
        cudaEventCreateWithFlags(&evA1, cudaEventDisableTiming);
        cudaEventCreateWithFlags(&evG2, cudaEventDisableTiming);
        cudaEventCreateWithFlags(&evA2, cudaEventDisableTiming);
    }

    void* sp = nullptr;
    cudaGetSymbolAddress(&sp, S);
    Scratch* sc = (Scratch*)sp;

    const float* x    = (const float*)d_in[0];
    const int*   ei   = (const int*)d_in[1];
    const float* W1   = (const float*)d_in[3];
    const float* b1   = (const float*)d_in[4];
    const float* W2   = (const float*)d_in[5];
    const float* b2   = (const float*)d_in[6];
    const float* W3   = (const float*)d_in[7];
    const float* b3   = (const float*)d_in[8];
    const float* att1 = (const float*)d_in[9];
    const float* att2 = (const float*)d_in[10];
    const float* bng  = (const float*)d_in[11];
    const float* bnb  = (const float*)d_in[12];
    const float* bnm  = (const float*)d_in[13];
    const float* bnv  = (const float*)d_in[14];
    const float* l1w  = (const float*)d_in[15];
    const float* l1b  = (const float*)d_in[16];
    const float* l2w  = (const float*)d_in[17];
    const float* l2b  = (const float*)d_in[18];
    const float* l3w  = (const float*)d_in[19];
    const float* l3b  = (const float*)d_in[20];

    int E = in_sizes[1] / 2;
    const int* src = ei;
    const int* dst = ei + E;

    float* out    = (float*)d_out;
    float* out_x  = out;                        // [128,128]
    float* out_lp = out + BGR * 128;            // [128,10]
    float* h      = out + BGR * 128 + BGR * 10; // x__ = [65536,256]

    cudaFuncSetAttribute(bmma, cudaFuncAttributeMaxDynamicSharedMemorySize,
                         BMMA_SMEM);

    // ---- fork: CSR build + A1c zero + weight prep on s2, big GEMM on s0 ----
    cudaEventRecord(evF, 0);
    cudaStreamWaitEvent(s2, evF, 0);

    zero_c<<<(int)(((long long)BGR * KP1 * KP1 / 16 + 255) / 256), 256, 0, s2>>>(
        sc->A1c, (long long)BGR * KP1 * KP1 / 16);
    init_misc<<<NBN / 256, 256, 0, s2>>>(sc->cnt, sc->rank);
    count_edges<<<(E + 255) / 256, 256, 0, s2>>>(dst, sc->cnt, E);
    scan_a<<<256, 256, 0, s2>>>(sc->cnt, sc->off, sc->bsum);
    scan_c<<<256, 256, 0, s2>>>(sc->off, sc->pos, sc->bsum, sc->cnt, sc->dinv, E);
    scatter_edges<<<(E + 255) / 256, 256, 0, s2>>>(src, dst, sc->pos, sc->csr, E);
    sort_buckets<<<NBN / 256, 256, 0, s2>>>(sc->csr, sc->off);
    cudaEventRecord(evCSR, s2);
    foldW2<<<HD, HD, 0, s2>>>(W2, bng, bnb, bnm, bnv, sc->w2fth, sc->w2ftl, sc->c2);
    split_w3t<<<HD, HD, 0, s2>>>(W3, sc->w3th, sc->w3tl);
    cudaEventRecord(evW, s2);

    split_x<<<32768, 256>>>(x, sc->xh, sc->xl, (long long)NBN * FD / 4);
    split_w1t<<<HD, FD>>>(W1, sc->w1th, sc->w1tl);
    bmma<<<dim3(HD / 128, NBN / 128, 1), 256, BMMA_SMEM>>>(
        sc->xh, sc->xl, sc->w1th, sc->w1tl, nullptr, sc->xw, nullptr, nullptr,
        NBN, HD, FD, 0, 0, 0, 0, 0, nullptr, 1.0f, 0, nullptr);

    // ---- join: need csr/off/dinv + xw ----
    cudaStreamWaitEvent(0, evCSR, 0);
    gcn_agg<<<NBN / 4, 256>>>((const float4*)sc->xw, sc->off, sc->csr, sc->dinv,
                              (const float4*)b1, (float4*)h);
    pool_score<<<NBN / 4, 256>>>((const float4*)h, sc->off, sc->csr, sc->cnt,
                                 sc->score);
    topk_kernel<<<BGR, NN>>>(sc->score, nullptr, NN, KP1, sc->perm, sc->rank);
    gather_rows_ef<<<BGR * KP1, 256>>>(h, sc->perm, att1, sc->h1,
                                       sc->h1h, sc->h1l, sc->ef1);

    // ---- fork: A1 build+softmax on s2, xw2 GEMM + readout on s0 ----
    cudaEventRecord(evG1, 0);
    cudaStreamWaitEvent(s2, evG1, 0);
    buildA1<<<(E + 255) / 256, 256, 0, s2>>>(src, dst, sc->rank, sc->A1c, E);
    struct_softmax1<<<BGR * KP1, KP1, 0, s2>>>(sc->A1c, sc->ef1, sc->A1,
                                               sc->A1h, sc->A1l);
    cudaEventRecord(evA1, s2);

    cudaStreamWaitEvent(0, evW, 0);
    bmma<<<dim3(2, 2, BGR), 256, BMMA_SMEM>>>(
        sc->h1h, sc->h1l, sc->w2fth, sc->w2ftl, nullptr, sc->xw2,
        sc->xw2th, sc->xw2tl,
        KP1, HD, HD, (long long)KP1 * HD, 0, 0, (long long)KP1 * HD,
        (long long)KP1 * HD, sc->c2, 1.0f, 0, nullptr);
    readout_k<<<BGR, 1024>>>(sc->h1, sc->x1, KP1);

    // ---- join: need adj1 splits ----
    cudaStreamWaitEvent(0, evA1, 0);
    bmma<<<dim3(2, 2, BGR), 256, BMMA_SMEM>>>(
        sc->A1h, sc->A1l, sc->xw2th, sc->xw2tl, sc->xw2, sc->h2,
        sc->h2th, sc->h2tl,
        KP1, HD, KP1, (long long)KP1 * KP1, (long long)KP1 * HD,
        (long long)KP1 * HD, (long long)KP1 * HD, (long long)KP1 * HD,
        b2, 0.5f, 1, nullptr);
    // prop+score fused: no stores, |h2 - adj1@h2| row partials -> spart
    bmma<<<dim3(2, 2, BGR), 256, BMMA_SMEM>>>(
        sc->A1h, sc->A1l, sc->h2th, sc->h2tl, sc->h2, nullptr, nullptr, nullptr,
        KP1, HD, KP1, (long long)KP1 * KP1, (long long)KP1 * HD,
        (long long)KP1 * HD, 0, 0, nullptr, 1.0f, 0, sc->spart);
    topk_kernel<<<BGR, KP1>>>(sc->spart, sc->spart + (long long)BGR * KP1,
                              KP1, KP2, sc->idx2, nullptr);
    gather_h2sel_ef<<<BGR * KP2, 256>>>(sc->h2, sc->idx2, att2, sc->h2sel,
                                        sc->h2selh, sc->h2sell, sc->ef2);

    // ---- fork: softmax2 on s2, xw3 GEMM + readout on s0 ----
    cudaEventRecord(evG2, 0);
    cudaStreamWaitEvent(s2, evG2, 0);
    struct_softmax2<<<BGR * KP2, KP2, 0, s2>>>(sc->A1, sc->idx2, sc->ef2,
                                               sc->A2h, sc->A2l);
    cudaEventRecord(evA2, s2);

    bmma<<<dim3(2, 1, BGR), 256, BMMA_SMEM>>>(
        sc->h2selh, sc->h2sell, sc->w3th, sc->w3tl, nullptr, sc->xw3,
        sc->xw3th, sc->xw3tl,
        KP2, HD, HD, (long long)KP2 * HD, 0, 0, (long long)KP2 * HD,
        (long long)KP2 * HD, nullptr, 1.0f, 0, nullptr);
    readout_k<<<BGR, 1024>>>(sc->h2sel, sc->x2, KP2);

    // ---- join: need adj2 splits ----
    cudaStreamWaitEvent(0, evA2, 0);
    bmma<<<dim3(2, 1, BGR), 256, BMMA_SMEM>>>(
        sc->A2h, sc->A2l, sc->xw3th, sc->xw3tl, sc->xw3, sc->h3, nullptr, nullptr,
        KP2, HD, KP2, (long long)KP2 * KP2, (long long)KP2 * HD,
        (long long)KP2 * HD, (long long)KP2 * HD, 0, b3, 0.5f, 1, nullptr);
    readout_k<<<BGR, 1024>>>(sc->h3, sc->x3, KP2);

    // ---- head ----
    head<<<BGR, 256>>>(sc->x1, sc->x2, sc->x3, l1w, l1b, l2w, l2b, l3w, l3b,
                       out_x, out_lp);
}

// round 16
// speedup vs baseline: 1.3088x; 1.0069x over previous
#include <cuda_runtime.h>
#include <cuda_bf16.h>
#include <math.h>
#include <stdint.h>

// Problem constants
#define NBN   65536      // B*N nodes
#define BGR   128        // graphs
#define NN    512        // nodes per graph
#define FD    512        // input features
#define HD    256        // hidden
#define KP1   256        // K1
#define KP2   128        // K2
#define EDGES 1048576    // B*EPG

typedef unsigned long long ull;

__device__ __forceinline__ void mma_bf16(float* c, const uint32_t* a,
                                         uint32_t b0, uint32_t b1)
{
    asm volatile(
        "mma.sync.aligned.m16n8k16.row.col.f32.bf16.bf16.f32 "
        "{%0,%1,%2,%3}, {%4,%5,%6,%7}, {%8,%9}, {%0,%1,%2,%3};"
        : "+f"(c[0]), "+f"(c[1]), "+f"(c[2]), "+f"(c[3])
        : "r"(a[0]), "r"(a[1]), "r"(a[2]), "r"(a[3]), "r"(b0), "r"(b1));
}

__device__ __forceinline__ void cp16(uint32_t dst, const void* src)
{
    asm volatile("cp.async.cg.shared.global [%0], [%1], 16;"
                 :: "r"(dst), "l"(src));
}

__device__ __forceinline__ void ldsm4(uint32_t* r, uint32_t a)
{
    asm volatile("ldmatrix.sync.aligned.m8n8.x4.shared.b16 {%0,%1,%2,%3}, [%4];"
                 : "=r"(r[0]), "=r"(r[1]), "=r"(r[2]), "=r"(r[3]) : "r"(a));
}

// ---------------------------------------------------------------------------
// Scratch
// ---------------------------------------------------------------------------
struct Scratch {
    alignas(16) float xw[(long long)NBN * HD];        // x @ W1
    alignas(16) int   cnt[NBN];
    alignas(16) int   off[NBN + 4];
    alignas(16) int   pos[NBN];
    alignas(16) int   csr[EDGES];
    alignas(16) int   bsum[256];
    alignas(16) float dinv[NBN];
    alignas(16) float score[NBN];
    alignas(16) float spart[2LL * BGR * KP1];
    alignas(16) int   perm[BGR * KP1];
    alignas(16) int   rank[NBN];
    alignas(16) float h1[(long long)BGR * KP1 * HD];
    alignas(16) uint8_t A1c[(long long)BGR * KP1 * KP1]; // 0/1 A_ind
    alignas(16) float A1[(long long)BGR * KP1 * KP1];    // adj1 (softmax out)
    alignas(16) float A2[(long long)BGR * KP2 * KP2];    // adj2 (softmax out)
    alignas(16) float ef1[BGR * KP1 * 2];
    alignas(16) float x1[BGR * 2 * HD];
    alignas(16) float c2[HD];
    alignas(16) float xw2[(long long)BGR * KP1 * HD];
    alignas(16) float h2[(long long)BGR * KP1 * HD];
    alignas(16) int   idx2[BGR * KP2];
    alignas(16) float h2sel[(long long)BGR * KP2 * HD];
    alignas(16) float ef2[BGR * KP2 * 2];
    alignas(16) float x2[BGR * 2 * HD];
    alignas(16) float xw3[(long long)BGR * KP2 * HD];
    alignas(16) float h3[(long long)BGR * KP2 * HD];
    alignas(16) float x3[BGR * 2 * HD];
    // bf16 split weights (transposed [n][k])
    alignas(16) __nv_bfloat16 w1th[HD * FD];
    alignas(16) __nv_bfloat16 w1tl[HD * FD];
    alignas(16) __nv_bfloat16 w2fth[HD * HD];
    alignas(16) __nv_bfloat16 w2ftl[HD * HD];
    alignas(16) __nv_bfloat16 w3th[HD * HD];
    alignas(16) __nv_bfloat16 w3tl[HD * HD];
    // bf16 split transposed activations (produced by bmma epilogue)
    alignas(16) __nv_bfloat16 xw2th[(long long)BGR * HD * KP1];
    alignas(16) __nv_bfloat16 xw2tl[(long long)BGR * HD * KP1];
    alignas(16) __nv_bfloat16 h2th[(long long)BGR * HD * KP1];
    alignas(16) __nv_bfloat16 h2tl[(long long)BGR * HD * KP1];
    alignas(16) __nv_bfloat16 xw3th[(long long)BGR * HD * KP2];
    alignas(16) __nv_bfloat16 xw3tl[(long long)BGR * HD * KP2];
};
__device__ Scratch S;

// ---------------------------------------------------------------------------
// bmma: pipelined HMMA GEMM; A fp32 (split to bf16 hi/lo in-kernel),
// B pre-split bf16 transposed [N][K].
//   C[z][M,N] = maybeRelu( ((Ahi+Alo)[z] @ (Bh+Bl)[z]^T + D[z]) * scale + bias )
// Modes: normal (C [+CT splits]); score (SP != null): no stores, emits
// per-row partial sums of |D - acc*scale| into SP[bx][z][row].
// Dyn smem: 2 x (4 tile arrays) + 2 x 16KB fp32 A staging = 114688 B.
// ---------------------------------------------------------------------------
#define ST  40
#define SZB (128 * ST)
#define BMMA_SMEM (2 * 4 * SZB * 2 + 2 * 16384)
#define TPAD 136   // transpose row stride (bf16)

__global__ __launch_bounds__(256, 2)
void bmma(const float* __restrict__ A,
          const __nv_bfloat16* __restrict__ Bh, const __nv_bfloat16* __restrict__ Bl,
          const float* __restrict__ D, float* __restrict__ C,
          __nv_bfloat16* __restrict__ CTh, __nv_bfloat16* __restrict__ CTl,
          int M, int N, int K,
          long long sA, long long sB, long long sD, long long sC, long long sCT,
          const float* __restrict__ bias, float scale, int doRelu,
          float* __restrict__ SP)
{
    extern __shared__ __nv_bfloat16 dyn[];
    uint32_t smem_base = (uint32_t)__cvta_generic_to_shared(dyn);

    long long z = blockIdx.z;
    const float* Ab = A + z * sA;
    const __nv_bfloat16* Bhb = Bh + z * sB;
    const __nv_bfloat16* Blb = Bl + z * sB;
    const float* Db = D ? (D + z * sD) : nullptr;
    float* Cb = C ? (C + z * sC) : nullptr;
    __nv_bfloat16* CThb = CTh ? (CTh + z * sCT) : nullptr;
    __nv_bfloat16* CTlb = CTl ? (CTl + z * sCT) : nullptr;
    bool scoreMode = (SP != nullptr);

    int tid = threadIdx.x;
    int warp = tid >> 5, lane = tid & 31;
    int gid = lane >> 2, tig = lane & 3;
    int wm = warp >> 1, wn = warp & 1;
    int m0 = wm * 32, n0 = wn * 64;
    int row0 = blockIdx.y * 128, col0 = blockIdx.x * 128;

    uint32_t aoff = (uint32_t)((m0 + (lane & 15)) * ST + (lane >> 4) * 8) * 2;
    uint32_t boff = (uint32_t)((n0 + (lane >> 4) * 8 + (lane & 7)) * ST
                               + ((lane >> 3) & 1) * 8) * 2;

    float acc[2][8][4];
#pragma unroll
    for (int mt = 0; mt < 2; mt++)
#pragma unroll
        for (int nt = 0; nt < 8; nt++)
#pragma unroll
            for (int i = 0; i < 4; i++) acc[mt][nt][i] = 0.f;

    auto copy_chunk = [&](int bufc, int kc) {
        uint32_t baseB = smem_base + (uint32_t)bufc * 4 * SZB * 2;
        uint32_t baseA = smem_base + 8 * SZB * 2 + (uint32_t)bufc * 16384;
#pragma unroll
        for (int it = 0; it < 4; it++) {
            int idx = it * 256 + tid;            // 0..1023
            int row = idx >> 3, c4 = (idx & 7) << 2;
            cp16(baseA + (uint32_t)(row * 32 + c4) * 4,
                 Ab + (long long)(row0 + row) * K + kc + c4);
        }
#pragma unroll
        for (int it = 0; it < 2; it++) {
            int idx = it * 256 + tid;            // 0..511
            int row = idx >> 2, c8 = (idx & 3) << 3;
            uint32_t so = (uint32_t)(row * ST + c8) * 2;
            long long gb = (long long)(col0 + row) * K + kc + c8;
            cp16(baseB + 2 * SZB * 2 + so, Bhb + gb);
            cp16(baseB + 3 * SZB * 2 + so, Blb + gb);
        }
        asm volatile("cp.async.commit_group;" ::: "memory");
    };

    copy_chunk(0, 0);
    int buf = 0;
    for (int kc = 0; kc < K; kc += 32) {
        asm volatile("cp.async.wait_group 0;" ::: "memory");
        __syncthreads();
        if (kc + 32 < K) copy_chunk(buf ^ 1, kc + 32);

        // convert fp32 A staging -> split bf16 tiles
        {
            const float* stg = (const float*)(dyn + 8 * SZB) + buf * 4096;
            __nv_bfloat16* cAh = dyn + (size_t)buf * 4 * SZB;
            __nv_bfloat16* cAl = cAh + SZB;
            int crow = tid >> 1, cc0 = (tid & 1) << 4;
            const float4* sp = (const float4*)(stg + crow * 32 + cc0);
            float4 q0 = sp[0], q1 = sp[1], q2 = sp[2], q3 = sp[3];
            float ff[16] = {q0.x, q0.y, q0.z, q0.w, q1.x, q1.y, q1.z, q1.w,
                            q2.x, q2.y, q2.z, q2.w, q3.x, q3.y, q3.z, q3.w};
            __nv_bfloat16 hh[16], ll[16];
#pragma unroll
            for (int j = 0; j < 16; j++) {
                hh[j] = __float2bfloat16(ff[j]);
                ll[j] = __float2bfloat16(ff[j] - __bfloat162float(hh[j]));
            }
            *(uint4*)&cAh[crow * ST + cc0] = *(uint4*)&hh[0];
            *(uint4*)&cAh[crow * ST + cc0 + 8] = *(uint4*)&hh[8];
            *(uint4*)&cAl[crow * ST + cc0] = *(uint4*)&ll[0];
            *(uint4*)&cAl[crow * ST + cc0 + 8] = *(uint4*)&ll[8];
        }
        __syncthreads();

        uint32_t bufb = smem_base + (uint32_t)buf * 4 * SZB * 2;
        uint32_t aH = bufb + aoff;
        uint32_t aL = bufb + SZB * 2 + aoff;
        uint32_t bH = bufb + 2 * SZB * 2 + boff;
        uint32_t bL = bufb + 3 * SZB * 2 + boff;

#pragma unroll
        for (int ks = 0; ks < 2; ks++) {
            uint32_t kbb = (uint32_t)ks * 32;
            uint32_t ah[2][4], al[2][4];
            ldsm4(ah[0], aH + kbb);
            ldsm4(ah[1], aH + 16 * ST * 2 + kbb);
            ldsm4(al[0], aL + kbb);
            ldsm4(al[1], aL + 16 * ST * 2 + kbb);
#pragma unroll
            for (int p = 0; p < 4; p++) {
                uint32_t bh[4], bl[4];
                ldsm4(bh, bH + (uint32_t)p * 16 * ST * 2 + kbb);
                ldsm4(bl, bL + (uint32_t)p * 16 * ST * 2 + kbb);
#pragma unroll
                for (int mt = 0; mt < 2; mt++) {
                    mma_bf16(acc[mt][2 * p], ah[mt], bh[0], bh[1]);
                    mma_bf16(acc[mt][2 * p], ah[mt], bl[0], bl[1]);
                    mma_bf16(acc[mt][2 * p], al[mt], bh[0], bh[1]);
                    mma_bf16(acc[mt][2 * p + 1], ah[mt], bh[2], bh[3]);
                    mma_bf16(acc[mt][2 * p + 1], ah[mt], bl[2], bl[3]);
                    mma_bf16(acc[mt][2 * p + 1], al[mt], bh[2], bh[3]);
                }
            }
        }
        buf ^= 1;
    }

    // epilogue (smem buffers are dead after this barrier)
    __syncthreads();
    __nv_bfloat16* sTh = dyn;                 // [128][TPAD] (normal mode)
    __nv_bfloat16* sTl = dyn + 128 * TPAD;
    float* srow = (float*)dyn;                // [128][9] (score mode)

    float rs[2][2] = {{0.f, 0.f}, {0.f, 0.f}};

#pragma unroll
    for (int mt = 0; mt < 2; mt++) {
        int rl = m0 + mt * 16 + gid;
        long long r = row0 + rl;
#pragma unroll
        for (int nt = 0; nt < 8; nt++) {
            int cl = n0 + nt * 8 + tig * 2;
            int c = col0 + cl;
            float v0 = acc[mt][nt][0], v1 = acc[mt][nt][1];
            float v2 = acc[mt][nt][2], v3 = acc[mt][nt][3];
            if (scoreMode) {
                float2 d0 = *(const float2*)(Db + r * N + c);
                float2 d1 = *(const float2*)(Db + (r + 8) * N + c);
                v0 *= scale; v1 *= scale; v2 *= scale; v3 *= scale;
                rs[mt][0] += fabsf(d0.x - v0) + fabsf(d0.y - v1);
                rs[mt][1] += fabsf(d1.x - v2) + fabsf(d1.y - v3);
                continue;
            }
            if (Db) {
                float2 d0 = *(const float2*)(Db + r * N + c);
                float2 d1 = *(const float2*)(Db + (r + 8) * N + c);
                v0 += d0.x; v1 += d0.y; v2 += d1.x; v3 += d1.y;
            }
            v0 *= scale; v1 *= scale; v2 *= scale; v3 *= scale;
            if (bias) {
                float2 bb = *(const float2*)(bias + c);
                v0 += bb.x; v1 += bb.y; v2 += bb.x; v3 += bb.y;
            }
            if (doRelu) {
                v0 = fmaxf(v0, 0.f); v1 = fmaxf(v1, 0.f);
                v2 = fmaxf(v2, 0.f); v3 = fmaxf(v3, 0.f);
            }
            *(float2*)(Cb + r * N + c) = make_float2(v0, v1);
            *(float2*)(Cb + (r + 8) * N + c) = make_float2(v2, v3);
            if (CThb) {
                __nv_bfloat16 h0 = __float2bfloat16(v0);
                __nv_bfloat16 h1 = __float2bfloat16(v1);
                __nv_bfloat16 h2_ = __float2bfloat16(v2);
                __nv_bfloat16 h3_ = __float2bfloat16(v3);
                sTh[cl * TPAD + rl] = h0;
                sTh[cl * TPAD + rl + 8] = h2_;
                sTh[(cl + 1) * TPAD + rl] = h1;
                sTh[(cl + 1) * TPAD + rl + 8] = h3_;
                sTl[cl * TPAD + rl] = __float2bfloat16(v0 - __bfloat162float(h0));
                sTl[cl * TPAD + rl + 8] = __float2bfloat16(v2 - __bfloat162float(h2_));
                sTl[(cl + 1) * TPAD + rl] = __float2bfloat16(v1 - __bfloat162float(h1));
                sTl[(cl + 1) * TPAD + rl + 8] = __float2bfloat16(v3 - __bfloat162float(h3_));
            }
        }
    }
    if (scoreMode) {
        int slot = wn * 4 + tig;
#pragma unroll
        for (int mt = 0; mt < 2; mt++) {
            int rl = m0 + mt * 16 + gid;
            srow[rl * 9 + slot] = rs[mt][0];
            srow[(rl + 8) * 9 + slot] = rs[mt][1];
        }
        __syncthreads();
        if (tid < 128) {
            float s = 0.f;
#pragma unroll
            for (int k = 0; k < 8; k++) s += srow[tid * 9 + k];
            SP[((long long)blockIdx.x * BGR + z) * (long long)M + row0 + tid] = s;
        }
        return;
    }
    if (CThb) {
        __syncthreads();
#pragma unroll
        for (int it = 0; it < 8; it++) {
            int i = it * 256 + tid;
            int cl = i >> 4, v8 = (i & 15) << 3;
            uint4 vh = *(const uint4*)&sTh[cl * TPAD + v8];
            uint4 vl = *(const uint4*)&sTl[cl * TPAD + v8];
            long long go = (long long)(col0 + cl) * M + row0 + v8;
            *(uint4*)(CThb + go) = vh;
            *(uint4*)(CTlb + go) = vl;
        }
    }
}

// ---------------------------------------------------------------------------
// weight prep kernels
// ---------------------------------------------------------------------------
__global__ void split_w1t(const float* __restrict__ W, __nv_bfloat16* __restrict__ hi,
                          __nv_bfloat16* __restrict__ lo)
{
    int n = blockIdx.x;
    int k = threadIdx.x;
    float v = W[k * HD + n];
    __nv_bfloat16 h = __float2bfloat16(v);
    hi[n * FD + k] = h;
    lo[n * FD + k] = __float2bfloat16(v - __bfloat162float(h));
}

__global__ void foldW2(const float* __restrict__ W2, const float* __restrict__ gam,
                       const float* __restrict__ bet, const float* __restrict__ mean,
                       const float* __restrict__ var,
                       __nv_bfloat16* __restrict__ Wth, __nv_bfloat16* __restrict__ Wtl,
                       float* __restrict__ c2)
{
    int n = blockIdx.x;
    int k = threadIdx.x;
    float sc_ = gam[k] * rsqrtf(var[k] + 1e-5f);
    float sh = bet[k] - mean[k] * sc_;
    float w0 = W2[k * HD + n];
    float w = w0 * sc_;
    __nv_bfloat16 h = __float2bfloat16(w);
    Wth[n * HD + k] = h;
    Wtl[n * HD + k] = __float2bfloat16(w - __bfloat162float(h));
    __shared__ float red[256];
    red[k] = sh * w0;
    __syncthreads();
    for (int s = 128; s > 0; s >>= 1) {
        if (k < s) red[k] += red[k + s];
        __syncthreads();
    }
    if (k == 0) c2[n] = red[0];
}

__global__ void split_w3t(const float* __restrict__ W, __nv_bfloat16* __restrict__ hi,
                          __nv_bfloat16* __restrict__ lo)
{
    int n = blockIdx.x;
    int k = threadIdx.x;
    float v = W[k * HD + n];
    __nv_bfloat16 h = __float2bfloat16(v);
    hi[n * HD + k] = h;
    lo[n * HD + k] = __float2bfloat16(v - __bfloat162float(h));
}

// ---------------------------------------------------------------------------
// Graph-structure kernels
// ---------------------------------------------------------------------------
__global__ void init_misc(int* cnt, int* rank)
{
    int i = blockIdx.x * 256 + threadIdx.x;
    if (i < NBN) { cnt[i] = 0; rank[i] = -1; }
}

__global__ void count_edges(const int* __restrict__ dst, int* cnt, int E)
{
    int e = blockIdx.x * 256 + threadIdx.x;
    if (e < E) atomicAdd(&cnt[dst[e]], 1);
}

__global__ void scan_a(const int* __restrict__ cnt, int* off, int* bsum)
{
    __shared__ int sh[256];
    int b = blockIdx.x, t = threadIdx.x;
    int v = cnt[b * 256 + t];
    sh[t] = v;
    __syncthreads();
    for (int d = 1; d < 256; d <<= 1) {
        int u = (t >= d) ? sh[t - d] : 0;
        __syncthreads();
        sh[t] += u;
        __syncthreads();
    }
    off[b * 256 + t] = sh[t] - v;
    if (t == 255) bsum[b] = sh[255];
}

__global__ void scan_c(int* off, int* pos, const int* __restrict__ bsum,
                       const int* __restrict__ cnt, float* dinv, int E)
{
    __shared__ int sh[256];
    int b = blockIdx.x, t = threadIdx.x;
    int v = bsum[t];
    sh[t] = v;
    __syncthreads();
    for (int d = 1; d < 256; d <<= 1) {
        int u = (t >= d) ? sh[t - d] : 0;
        __syncthreads();
        sh[t] += u;
        __syncthreads();
    }
    int bofs = (b == 0) ? 0 : sh[b - 1];
    __syncthreads();
    int i = b * 256 + t;
    int o = off[i] + bofs;
    off[i] = o;
    pos[i] = o;
    dinv[i] = rsqrtf((float)(cnt[i] + 1));
    if (i == NBN - 1) off[NBN] = E;
}

__global__ void scatter_edges(const int* __restrict__ src, const int* __restrict__ dst,
                              int* pos, int* csr, int E)
{
    int e = blockIdx.x * 256 + threadIdx.x;
    if (e < E) {
        int p = atomicAdd(&pos[dst[e]], 1);
        csr[p] = src[e];
    }
}

__global__ void sort_buckets(int* csr, const int* __restrict__ off)
{
    int i = blockIdx.x * 256 + threadIdx.x;
    if (i >= NBN) return;
    int a = off[i], b = off[i + 1];
    for (int p = a + 1; p < b; p++) {
        int v = csr[p];
        int q = p - 1;
        while (q >= a && csr[q] > v) { csr[q + 1] = csr[q]; q--; }
        csr[q + 1] = v;
    }
}

__global__ __launch_bounds__(256)
void gcn_agg(const float4* __restrict__ xw4, const int* __restrict__ off,
             const int* __restrict__ csr, const float* __restrict__ dinv,
             const float4* __restrict__ b1_4, float4* __restrict__ h4)
{
    int g = threadIdx.x >> 6;
    int t = threadIdx.x & 63;
    int i = blockIdx.x * 4 + g;
    float di = dinv[i];
    float4 a = xw4[(long long)i * 64 + t];
    float w0 = di * di;
    float4 acc = make_float4(a.x * w0, a.y * w0, a.z * w0, a.w * w0);
    float4 acc2 = make_float4(0.f, 0.f, 0.f, 0.f);
    int e0 = off[i], e1 = off[i + 1];
    int e = e0;
    for (; e + 1 < e1; e += 2) {
        int s0 = csr[e], s1 = csr[e + 1];
        float wa = dinv[s0] * di, wb = dinv[s1] * di;
        float4 v0 = xw4[(long long)s0 * 64 + t];
        float4 v1 = xw4[(long long)s1 * 64 + t];
        acc.x += v0.x * wa; acc.y += v0.y * wa; acc.z += v0.z * wa; acc.w += v0.w * wa;
        acc2.x += v1.x * wb; acc2.y += v1.y * wb; acc2.z += v1.z * wb; acc2.w += v1.w * wb;
    }
    if (e < e1) {
        int s0 = csr[e];
        float wa = dinv[s0] * di;
        float4 v0 = xw4[(long long)s0 * 64 + t];
        acc.x += v0.x * wa; acc.y += v0.y * wa; acc.z += v0.z * wa; acc.w += v0.w * wa;
    }
    acc.x += acc2.x; acc.y += acc2.y; acc.z += acc2.z; acc.w += acc2.w;
    float4 bb = b1_4[t];
    acc.x = fmaxf(acc.x + bb.x, 0.f);
    acc.y = fmaxf(acc.y + bb.y, 0.f);
    acc.z = fmaxf(acc.z + bb.z, 0.f);
    acc.w = fmaxf(acc.w + bb.w, 0.f);
    h4[(long long)i * 64 + t] = acc;
}

__global__ __launch_bounds__(256)
void pool_score(const float4* __restrict__ h4, const int* __restrict__ off,
                const int* __restrict__ csr, const int* __restrict__ cnt,
                float* __restrict__ score)
{
    __shared__ float red[4][2];
    int g = threadIdx.x >> 6;
    int t = threadIdx.x & 63;
    int i = blockIdx.x * 4 + g;
    float4 acc = make_float4(0.f, 0.f, 0.f, 0.f);
    float4 acc2 = make_float4(0.f, 0.f, 0.f, 0.f);
    int e0 = off[i], e1 = off[i + 1];
    int e = e0;
    for (; e + 1 < e1; e += 2) {
        int s0 = csr[e], s1 = csr[e + 1];
        float4 v0 = h4[(long long)s0 * 64 + t];
        float4 v1 = h4[(long long)s1 * 64 + t];
        acc.x += v0.x; acc.y += v0.y; acc.z += v0.z; acc.w += v0.w;
        acc2.x += v1.x; acc2.y += v1.y; acc2.z += v1.z; acc2.w += v1.w;
    }
    if (e < e1) {
        int s0 = csr[e];
        float4 v0 = h4[(long long)s0 * 64 + t];
        acc.x += v0.x; acc.y += v0.y; acc.z += v0.z; acc.w += v0.w;
    }
    acc.x += acc2.x; acc.y += acc2.y; acc.z += acc2.z; acc.w += acc2.w;
    float degp = fmaxf((float)cnt[i], 1.f);
    float4 hh = h4[(long long)i * 64 + t];
    float s = fabsf(hh.x - acc.x / degp) + fabsf(hh.y - acc.y / degp)
            + fabsf(hh.z - acc.z / degp) + fabsf(hh.w - acc.w / degp);
#pragma unroll
    for (int o = 16; o > 0; o >>= 1)
        s += __shfl_down_sync(0xffffffff, s, o);
    if ((t & 31) == 0) red[g][t >> 5] = s;
    __syncthreads();
    if (t == 0) score[i] = red[g][0] + red[g][1];
}

__global__ void topk_kernel(const float* __restrict__ score,
                            const float* __restrict__ scoreB, int n, int kout,
                            int* outidx, int* rank)
{
    int g = blockIdx.x;
    int t = threadIdx.x;
    __shared__ float s[512];
    __shared__ int id[512];
    float v = score[g * n + t];
    if (scoreB) v += scoreB[g * n + t];
    s[t] = v;
    id[t] = t;
    __syncthreads();
    for (int k = 2; k <= n; k <<= 1)
        for (int j = k >> 1; j > 0; j >>= 1) {
            int p = t ^ j;
            if (p > t) {
                float s1 = s[t], s2 = s[p];
                int i1 = id[t], i2 = id[p];
                bool lt12 = (s1 > s2) || (s1 == s2 && i1 < i2);
                bool up = ((t & k) == 0);
                if (up ? !lt12 : lt12) { s[t] = s2; s[p] = s1; id[t] = i2; id[p] = i1; }
            }
            __syncthreads();
        }
    if (t < kout) {
        if (rank) {
            int node = g * n + id[t];
            outidx[g * kout + t] = node;
            rank[node] = t;
        } else {
            outidx[g * kout + t] = id[t];
        }
    }
}

__global__ void gather_rows_ef(const float* __restrict__ h, const int* __restrict__ perm,
                               const float* __restrict__ att,
                               float* __restrict__ h1, float* __restrict__ ef)
{
    long long n = blockIdx.x;
    int c = threadIdx.x;
    float v = h[(long long)perm[n] * HD + c];
    h1[n * HD + c] = v;
    __shared__ float re[256], rf[256];
    re[c] = v * att[2 * c];
    rf[c] = v * att[2 * c + 1];
    __syncthreads();
    for (int s = 128; s > 0; s >>= 1) {
        if (c < s) { re[c] += re[c + s]; rf[c] += rf[c + s]; }
        __syncthreads();
    }
    if (c == 0) { ef[2 * n] = re[0]; ef[2 * n + 1] = rf[0]; }
}

__global__ void zero_c(uint8_t* p, long long n16)
{
    long long i = (long long)blockIdx.x * 256 + threadIdx.x;
    if (i < n16) ((uint4*)p)[i] = make_uint4(0, 0, 0, 0);
}

__global__ void buildA1(const int* __restrict__ src, const int* __restrict__ dst,
                        const int* __restrict__ rank, uint8_t* __restrict__ A1c, int E)
{
    int e = blockIdx.x * 256 + threadIdx.x;
    if (e >= E) return;
    int s = src[e], d = dst[e];
    int ns = rank[s], nd = rank[d];
    if (ns >= 0 && nd >= 0) {
        int g = s >> 9;
        A1c[(((long long)g * KP1 + ns) * KP1) + nd] = 1;
    }
}

__global__ void struct_softmax1(const uint8_t* __restrict__ Ac,
                                const float* __restrict__ ef,
                                float* __restrict__ Aout)
{
    int row = blockIdx.x;
    int j = threadIdx.x;
    int b = row >> 8;
    long long base = (long long)row * KP1;
    float logit = ef[2 * row] + ef[2 * ((b << 8) + j) + 1] + (float)Ac[base + j];
    __shared__ float red[256];
    red[j] = logit;
    __syncthreads();
    for (int s = 128; s > 0; s >>= 1) {
        if (j < s) red[j] = fmaxf(red[j], red[j + s]);
        __syncthreads();
    }
    float m = red[0];
    __syncthreads();
    float e = expf(logit - m);
    red[j] = e;
    __syncthreads();
    for (int s = 128; s > 0; s >>= 1) {
        if (j < s) red[j] += red[j + s];
        __syncthreads();
    }
    Aout[base + j] = e / red[0];
}

__global__ void struct_softmax2(const float* __restrict__ adj1,
                                const int* __restrict__ idx2,
                                const float* __restrict__ ef,
                                float* __restrict__ A2out)
{
    int row = blockIdx.x;
    int j = threadIdx.x;
    int b = row >> 7;
    int ri = idx2[row];
    int rj = idx2[(b << 7) + j];
    float aind = adj1[((long long)b * KP1 + ri) * KP1 + rj];
    float logit = ef[2 * row] + ef[2 * ((b << 7) + j) + 1] + aind;
    __shared__ float red[128];
    red[j] = logit;
    __syncthreads();
    for (int s = 64; s > 0; s >>= 1) {
        if (j < s) red[j] = fmaxf(red[j], red[j + s]);
        __syncthreads();
    }
    float m = red[0];
    __syncthreads();
    float e = expf(logit - m);
    red[j] = e;
    __syncthreads();
    for (int s = 64; s > 0; s >>= 1) {
        if (j < s) red[j] += red[j + s];
        __syncthreads();
    }
    A2out[(long long)row * KP2 + j] = e / red[0];
}

__global__ void readout_k(const float* __restrict__ X, float* __restrict__ out, int Kd)
{
    __shared__ float smx[4][256], ssm[4][256];
    int b = blockIdx.x;
    int part = threadIdx.x >> 8;
    int c = threadIdx.x & 255;
    int kq = Kd >> 2;
    int k0 = part * kq, k1 = k0 + kq;
    float mx = -3.4e38f, sm = 0.f;
    for (int k = k0; k < k1; k++) {
        float v = X[((long long)b * Kd + k) * HD + c];
        mx = fmaxf(mx, v);
        sm += v;
    }
    smx[part][c] = mx;
    ssm[part][c] = sm;
    __syncthreads();
    if (part == 0) {
        float m = fmaxf(fmaxf(smx[0][c], smx[1][c]), fmaxf(smx[2][c], smx[3][c]));
        float s = ssm[0][c] + ssm[1][c] + ssm[2][c] + ssm[3][c];
        out[b * 2 * HD + c] = m;
        out[b * 2 * HD + HD + c] = s / (float)Kd;
    }
}

__global__ void gather_h2sel_ef(const float* __restrict__ h2, const int* __restrict__ idx2,
                                const float* __restrict__ att,
                                float* __restrict__ h2sel, float* __restrict__ ef)
{
    int n = blockIdx.x;
    int c = threadIdx.x;
    int b = n >> 7;
    int row = idx2[n];
    float v = h2[((long long)b * KP1 + row) * HD + c];
    h2sel[(long long)n * HD + c] = v;
    __shared__ float re[256], rf[256];
    re[c] = v * att[2 * c];
    rf[c] = v * att[2 * c + 1];
    __syncthreads();
    for (int s = 128; s > 0; s >>= 1) {
        if (c < s) { re[c] += re[c + s]; rf[c] += rf[c + s]; }
        __syncthreads();
    }
    if (c == 0) { ef[2 * n] = re[0]; ef[2 * n + 1] = rf[0]; }
}

__global__ void head(const float* __restrict__ x1, const float* __restrict__ x2,
                     const float* __restrict__ x3,
                     const float* __restrict__ l1w, const float* __restrict__ l1b,
                     const float* __restrict__ l2w, const float* __restrict__ l2b,
                     const float* __restrict__ l3w, const float* __restrict__ l3b,
                     float* __restrict__ out_x, float* __restrict__ out_lp)
{
    int b = blockIdx.x;
    int t = threadIdx.x;
    __shared__ float g[512], g1[256], g2[128], lg[10];
    for (int i = t; i < 512; i += 256) {
        g[i] = fmaxf(x1[b * 512 + i], 0.f) + fmaxf(x2[b * 512 + i], 0.f) +
               fmaxf(x3[b * 512 + i], 0.f);
    }
    __syncthreads();
    {
        float a = 0.f;
        for (int c = 0; c < 512; c++) a += g[c] * l1w[c * 256 + t];
        g1[t] = fmaxf(a + l1b[t], 0.f);
    }
    __syncthreads();
    if (t < 128) {
        float a = 0.f;
        for (int c = 0; c < 256; c++) a += g1[c] * l2w[c * 128 + t];
        float v = fmaxf(a + l2b[t], 0.f);
        g2[t] = v;
        out_x[b * 128 + t] = v;
    }
    __syncthreads();
    if (t < 10) {
        float a = 0.f;
        for (int c = 0; c < 128; c++) a += g2[c] * l3w[c * 10 + t];
        lg[t] = a + l3b[t];
    }
    __syncthreads();
    if (t == 0) {
        float m = -3.4e38f;
        for (int i = 0; i < 10; i++) m = fmaxf(m, lg[i]);
        float s = 0.f;
        for (int i = 0; i < 10; i++) s += expf(lg[i] - m);
        float lse = m + logf(s);
        for (int i = 0; i < 10; i++) out_lp[b * 10 + i] = lg[i] - lse;
    }
}

// ---------------------------------------------------------------------------
// Launch (two-stream fork/join)
// ---------------------------------------------------------------------------
extern "C" void kernel_launch(void* const* d_in, const int* in_sizes, int n_in,
                              void* d_out, int out_size)
{
    static cudaStream_t s2 = nullptr;
    static cudaEvent_t evF, evCSR, evW, evG1, evA1, evG2, evA2;
    if (!s2) {
        cudaStreamCreateWithFlags(&s2, cudaStreamNonBlocking);
        cudaEventCreateWithFlags(&evF, cudaEventDisableTiming);
        cudaEventCreateWithFlags(&evCSR, cudaEventDisableTiming);
        cudaEventCreateWithFlags(&evW, cudaEventDisableTiming);
        cudaEventCreateWithFlags(&evG1, cudaEventDisableTiming);
        cudaEventCreateWithFlags(&evA1, cudaEventDisableTiming);
        cudaEventCreateWithFlags(&evG2, cudaEventDisableTiming);
        cudaEventCreateWithFlags(&evA2, cudaEventDisableTiming);
    }

    void* sp = nullptr;
    cudaGetSymbolAddress(&sp, S);
    Scratch* sc = (Scratch*)sp;

    const float* x    = (const float*)d_in[0];
    const int*   ei   = (const int*)d_in[1];
    const float* W1   = (const float*)d_in[3];
    const float* b1   = (const float*)d_in[4];
    const float* W2   = (const float*)d_in[5];
    const float* b2   = (const float*)d_in[6];
    const float* W3   = (const float*)d_in[7];
    const float* b3   = (const float*)d_in[8];
    const float* att1 = (const float*)d_in[9];
    const float* att2 = (const float*)d_in[10];
    const float* bng  = (const float*)d_in[11];
    const float* bnb  = (const float*)d_in[12];
    const float* bnm  = (const float*)d_in[13];
    const float* bnv  = (const float*)d_in[14];
    const float* l1w  = (const float*)d_in[15];
    const float* l1b  = (const float*)d_in[16];
    const float* l2w  = (const float*)d_in[17];
    const float* l2b  = (const float*)d_in[18];
    const float* l3w  = (const float*)d_in[19];
    const float* l3b  = (const float*)d_in[20];

    int E = in_sizes[1] / 2;
    const int* src = ei;
    const int* dst = ei + E;

    float* out    = (float*)d_out;
    float* out_x  = out;                        // [128,128]
    float* out_lp = out + BGR * 128;            // [128,10]
    float* h      = out + BGR * 128 + BGR * 10; // x__ = [65536,256]

    cudaFuncSetAttribute(bmma, cudaFuncAttributeMaxDynamicSharedMemorySize,
                         BMMA_SMEM);

    // ---- fork: CSR build + A1c zero + weight prep on s2, big GEMM on s0 ----
    cudaEventRecord(evF, 0);
    cudaStreamWaitEvent(s2, evF, 0);

    zero_c<<<(int)(((long long)BGR * KP1 * KP1 / 16 + 255) / 256), 256, 0, s2>>>(
        sc->A1c, (long long)BGR * KP1 * KP1 / 16);
    init_misc<<<NBN / 256, 256, 0, s2>>>(sc->cnt, sc->rank);
    count_edges<<<(E + 255) / 256, 256, 0, s2>>>(dst, sc->cnt, E);
    scan_a<<<256, 256, 0, s2>>>(sc->cnt, sc->off, sc->bsum);
    scan_c<<<256, 256, 0, s2>>>(sc->off, sc->pos, sc->bsum, sc->cnt, sc->dinv, E);
    scatter_edges<<<(E + 255) / 256, 256, 0, s2>>>(src, dst, sc->pos, sc->csr, E);
    sort_buckets<<<NBN / 256, 256, 0, s2>>>(sc->csr, sc->off);
    cudaEventRecord(evCSR, s2);
    foldW2<<<HD, HD, 0, s2>>>(W2, bng, bnb, bnm, bnv, sc->w2fth, sc->w2ftl, sc->c2);
    split_w3t<<<HD, HD, 0, s2>>>(W3, sc->w3th, sc->w3tl);
    cudaEventRecord(evW, s2);

    split_w1t<<<HD, FD>>>(W1, sc->w1th, sc->w1tl);
    bmma<<<dim3(HD / 128, NBN / 128, 1), 256, BMMA_SMEM>>>(
        x, sc->w1th, sc->w1tl, nullptr, sc->xw, nullptr, nullptr,
        NBN, HD, FD, 0, 0, 0, 0, 0, nullptr, 1.0f, 0, nullptr);

    // ---- join: need csr/off/dinv + xw ----
    cudaStreamWaitEvent(0, evCSR, 0);
    gcn_agg<<<NBN / 4, 256>>>((const float4*)sc->xw, sc->off, sc->csr, sc->dinv,
                              (const float4*)b1, (float4*)h);
    pool_score<<<NBN / 4, 256>>>((const float4*)h, sc->off, sc->csr, sc->cnt,
                                 sc->score);
    topk_kernel<<<BGR, NN>>>(sc->score, nullptr, NN, KP1, sc->perm, sc->rank);
    gather_rows_ef<<<BGR * KP1, 256>>>(h, sc->perm, att1, sc->h1, sc->ef1);

    // ---- fork: A1 build+softmax on s2, xw2 GEMM + readout on s0 ----
    cudaEventRecord(evG1, 0);
    cudaStreamWaitEvent(s2, evG1, 0);
    buildA1<<<(E + 255) / 256, 256, 0, s2>>>(src, dst, sc->rank, sc->A1c, E);
    struct_softmax1<<<BGR * KP1, KP1, 0, s2>>>(sc->A1c, sc->ef1, sc->A1);
    cudaEventRecord(evA1, s2);

    cudaStreamWaitEvent(0, evW, 0);
    bmma<<<dim3(2, 2, BGR), 256, BMMA_SMEM>>>(
        sc->h1, sc->w2fth, sc->w2ftl, nullptr, sc->xw2,
        sc->xw2th, sc->xw2tl,
        KP1, HD, HD, (long long)KP1 * HD, 0, 0, (long long)KP1 * HD,
        (long long)KP1 * HD, sc->c2, 1.0f, 0, nullptr);
    readout_k<<<BGR, 1024>>>(sc->h1, sc->x1, KP1);

    // ---- join: need adj1 ----
    cudaStreamWaitEvent(0, evA1, 0);
    bmma<<<dim3(2, 2, BGR), 256, BMMA_SMEM>>>(
        sc->A1, sc->xw2th, sc->xw2tl, sc->xw2, sc->h2,
        sc->h2th, sc->h2tl,
        KP1, HD, KP1, (long long)KP1 * KP1, (long long)KP1 * HD,
        (long long)KP1 * HD, (long long)KP1 * HD, (long long)KP1 * HD,
        b2, 0.5f, 1, nullptr);
    // prop+score fused: no stores, |h2 - adj1@h2| row partials -> spart
    bmma<<<dim3(2, 2, BGR), 256, BMMA_SMEM>>>(
        sc->A1, sc->h2th, sc->h2tl, sc->h2, nullptr, nullptr, nullptr,
        KP1, HD, KP1, (long long)KP1 * KP1, (long long)KP1 * HD,
        (long long)KP1 * HD, 0, 0, nullptr, 1.0f, 0, sc->spart);
    topk_kernel<<<BGR, KP1>>>(sc->spart, sc->spart + (long long)BGR * KP1,
                              KP1, KP2, sc->idx2, nullptr);
    gather_h2sel_ef<<<BGR * KP2, 256>>>(sc->h2, sc->idx2, att2, sc->h2sel,
                                        sc->ef2);

    // ---- fork: softmax2 on s2, xw3 GEMM + readout on s0 ----
    cudaEventRecord(evG2, 0);
    cudaStreamWaitEvent(s2, evG2, 0);
    struct_softmax2<<<BGR * KP2, KP2, 0, s2>>>(sc->A1, sc->idx2, sc->ef2,
                                               sc->A2);
    cudaEventRecord(evA2, s2);

    bmma<<<dim3(2, 1, BGR), 256, BMMA_SMEM>>>(
        sc->h2sel, sc->w3th, sc->w3tl, nullptr, sc->xw3,
        sc->xw3th, sc->xw3tl,
        KP2, HD, HD, (long long)KP2 * HD, 0, 0, (long long)KP2 * HD,
        (long long)KP2 * HD, nullptr, 1.0f, 0, nullptr);
    readout_k<<<BGR, 1024>>>(sc->h2sel, sc->x2, KP2);

    // ---- join: need adj2 ----
    cudaStreamWaitEvent(0, evA2, 0);
    bmma<<<dim3(2, 1, BGR), 256, BMMA_SMEM>>>(
        sc->A2, sc->xw3th, sc->xw3tl, sc->xw3, sc->h3, nullptr, nullptr,
        KP2, HD, KP2, (long long)KP2 * KP2, (long long)KP2 * HD,
        (long long)KP2 * HD, (long long)KP2 * HD, 0, b3, 0.5f, 1, nullptr);
    readout_k<<<BGR, 1024>>>(sc->h3, sc->x3, KP2);

    // ---- head ----
    head<<<BGR, 256>>>(sc->x1, sc->x2, sc->x3, l1w, l1b, l2w, l2b, l3w, l3b,
                       out_x, out_lp);
}